// round 10
// baseline (speedup 1.0000x reference)
#include <cuda_runtime.h>
#include <cuda_fp16.h>
#include <cstdint>
#include <math.h>

#define BATCH 4
#define TLEN 1024
#define CDIM 1024
#define NHEAD 16
#define HDIM 64
#define NLAYER 8
#define VOCAB 32000
#define NTOK (BATCH * TLEN)
#define FF (4 * CDIM)

// ---------------- device scratch ----------------
__device__ float g_x[NTOK * CDIM];
__device__ unsigned short g_qkvb_h[NTOK * 3 * CDIM], g_qkvb_l[NTOK * CDIM];  // lo only for Q
__device__ unsigned short g_hb[NTOK * CDIM];
__device__ unsigned short g_ob[NTOK * CDIM];
__device__ unsigned short g_ffb[(size_t)NTOK * FF];
__device__ unsigned short g_wqkv_h[(size_t)NLAYER * 3 * CDIM * CDIM], g_wqkv_l[(size_t)NLAYER * 3 * CDIM * CDIM];
__device__ unsigned short g_wproj_h[(size_t)NLAYER * CDIM * CDIM], g_wproj_l[(size_t)NLAYER * CDIM * CDIM];
__device__ unsigned short g_w1_h[(size_t)NLAYER * FF * CDIM], g_w1_l[(size_t)NLAYER * FF * CDIM];
__device__ unsigned short g_w2_h[(size_t)NLAYER * CDIM * FF], g_w2_l[(size_t)NLAYER * CDIM * FF];
__device__ unsigned short g_wlm_h[(size_t)VOCAB * CDIM], g_wlm_l[(size_t)VOCAB * CDIM];

// ---------------- helpers ----------------
__device__ __forceinline__ uint32_t cvta_s(const void* p) {
    uint32_t a;
    asm("{ .reg .u64 t; cvta.to.shared.u64 t, %1; cvt.u32.u64 %0, t; }" : "=r"(a) : "l"(p));
    return a;
}
#define CP_ASYNC16(dst, src) \
    asm volatile("cp.async.cg.shared.global [%0], [%1], 16;" :: "r"(dst), "l"(src))
#define CP_COMMIT() asm volatile("cp.async.commit_group;" ::: "memory")
#define CP_WAIT(n)  asm volatile("cp.async.wait_group %0;" :: "n"(n) : "memory")

__device__ __forceinline__ void ldm_x4(uint32_t* r, uint32_t addr) {
    asm volatile("ldmatrix.sync.aligned.m8n8.x4.shared.b16 {%0,%1,%2,%3}, [%4];"
                 : "=r"(r[0]), "=r"(r[1]), "=r"(r[2]), "=r"(r[3]) : "r"(addr));
}
__device__ __forceinline__ void ldm_x2(uint32_t* r, uint32_t addr) {
    asm volatile("ldmatrix.sync.aligned.m8n8.x2.shared.b16 {%0,%1}, [%2];"
                 : "=r"(r[0]), "=r"(r[1]) : "r"(addr));
}
__device__ __forceinline__ void ldm_x2t(uint32_t* r, uint32_t addr) {
    asm volatile("ldmatrix.sync.aligned.m8n8.x2.trans.shared.b16 {%0,%1}, [%2];"
                 : "=r"(r[0]), "=r"(r[1]) : "r"(addr));
}
__device__ __forceinline__ void mma_f16(float* d, const uint32_t* a, const uint32_t* b) {
    asm volatile(
        "mma.sync.aligned.m16n8k16.row.col.f32.f16.f16.f32 "
        "{%0,%1,%2,%3}, {%4,%5,%6,%7}, {%8,%9}, {%0,%1,%2,%3};"
        : "+f"(d[0]), "+f"(d[1]), "+f"(d[2]), "+f"(d[3])
        : "r"(a[0]), "r"(a[1]), "r"(a[2]), "r"(a[3]), "r"(b[0]), "r"(b[1]));
}
__device__ __forceinline__ void hsplit(float v, unsigned short& h, unsigned short& l) {
    __half hb = __float2half_rn(v);
    __half lb = __float2half_rn(v - __half2float(hb));
    h = __half_as_ushort(hb);
    l = __half_as_ushort(lb);
}
__device__ __forceinline__ unsigned short h1(float v) {
    return __half_as_ushort(__float2half_rn(v));
}
__device__ __forceinline__ void pack2h(float a, float b, uint32_t& hi, uint32_t& lo) {
    unsigned short h0, l0, hh1, l1;
    hsplit(a, h0, l0);
    hsplit(b, hh1, l1);
    hi = (uint32_t)h0 | ((uint32_t)hh1 << 16);
    lo = (uint32_t)l0 | ((uint32_t)l1 << 16);
}

// ---------------- weight prep (transpose + fp16 hi/lo split) ----------------
__global__ void tsplit_qkv_kernel(const float* __restrict__ wq, const float* __restrict__ wk,
                                  const float* __restrict__ wv,
                                  unsigned short* __restrict__ dh, unsigned short* __restrict__ dl) {
    __shared__ float t[32][33];
    int n0 = blockIdx.x * 32, k0 = blockIdx.y * 32, l = blockIdx.z;
    int sel = n0 >> 10;
    const float* src = sel == 0 ? wq : (sel == 1 ? wk : wv);
    int within = n0 & 1023;
    int h = within >> 6, d0 = within & 63;
    const float* sp = src + ((size_t)(l * 16 + h) * 1024 + k0) * 64 + d0;
    int tx = threadIdx.x, ty = threadIdx.y;
    #pragma unroll
    for (int i = 0; i < 4; i++) t[ty + i * 8][tx] = sp[(size_t)(ty + i * 8) * 64 + tx];
    __syncthreads();
    size_t ob = (size_t)l * 3072 * 1024;
    #pragma unroll
    for (int i = 0; i < 4; i++) {
        int n = n0 + ty + i * 8, k = k0 + tx;
        unsigned short hh, ll;
        hsplit(t[tx][ty + i * 8], hh, ll);
        dh[ob + (size_t)n * 1024 + k] = hh;
        dl[ob + (size_t)n * 1024 + k] = ll;
    }
}
__global__ void tsplit_mat_kernel(const float* __restrict__ src,
                                  unsigned short* __restrict__ dh, unsigned short* __restrict__ dl,
                                  int K, int N) {
    __shared__ float t[32][33];
    int n0 = blockIdx.x * 32, k0 = blockIdx.y * 32;
    size_t l = blockIdx.z;
    const float* sp = src + l * (size_t)K * N;
    int tx = threadIdx.x, ty = threadIdx.y;
    #pragma unroll
    for (int i = 0; i < 4; i++) t[ty + i * 8][tx] = sp[(size_t)(k0 + ty + i * 8) * N + n0 + tx];
    __syncthreads();
    size_t ob = l * (size_t)K * N;
    #pragma unroll
    for (int i = 0; i < 4; i++) {
        int n = n0 + ty + i * 8, k = k0 + tx;
        unsigned short hh, ll;
        hsplit(t[tx][ty + i * 8], hh, ll);
        dh[ob + (size_t)n * K + k] = hh;
        dl[ob + (size_t)n * K + k] = ll;
    }
}

// ---------------- embed ----------------
__global__ void embed_kernel(const int* __restrict__ idx, const float* __restrict__ tok,
                             const float* __restrict__ pos, float* __restrict__ x) {
    int row = blockIdx.x;
    int t = row & (TLEN - 1);
    int token = idx[row];
    const float4* te = (const float4*)(tok + (size_t)token * CDIM);
    const float4* pe = (const float4*)(pos + (size_t)t * CDIM);
    float4* xo = (float4*)(x + (size_t)row * CDIM);
    int i = threadIdx.x;
    float4 a = te[i], b = pe[i];
    a.x += b.x; a.y += b.y; a.z += b.z; a.w += b.w;
    xo[i] = a;
}

// ---------------- LayerNorm -> single fp16 ----------------
__global__ void ln_kernel(const float* __restrict__ x, const float* __restrict__ g,
                          const float* __restrict__ b, unsigned short* __restrict__ oh) {
    int row = blockIdx.x;
    int tid = threadIdx.x;
    float4 v = ((const float4*)(x + (size_t)row * CDIM))[tid];
    float s = v.x + v.y + v.z + v.w;
    float ss = v.x * v.x + v.y * v.y + v.z * v.z + v.w * v.w;
    #pragma unroll
    for (int o = 16; o > 0; o >>= 1) {
        s += __shfl_xor_sync(0xffffffffu, s, o);
        ss += __shfl_xor_sync(0xffffffffu, ss, o);
    }
    __shared__ float sm[8], sm2[8];
    int w = tid >> 5, lane = tid & 31;
    if (lane == 0) { sm[w] = s; sm2[w] = ss; }
    __syncthreads();
    s = 0.f; ss = 0.f;
    #pragma unroll
    for (int i = 0; i < 8; i++) { s += sm[i]; ss += sm2[i]; }
    float mean = s * (1.0f / CDIM);
    float var = ss * (1.0f / CDIM) - mean * mean;
    float rstd = rsqrtf(var + 1e-5f);
    float4 gv = ((const float4*)g)[tid];
    float4 bv = ((const float4*)b)[tid];
    ushort4 hv;
    hv.x = h1((v.x - mean) * rstd * gv.x + bv.x);
    hv.y = h1((v.y - mean) * rstd * gv.y + bv.y);
    hv.z = h1((v.z - mean) * rstd * gv.z + bv.z);
    hv.w = h1((v.w - mean) * rstd * gv.w + bv.w);
    *(ushort4*)(oh + (size_t)row * CDIM + tid * 4) = hv;
}

// ---------------- HMMA GEMM: D[M,N] = A[M,K] * (Wh+Wl)[N,K]^T ----------------
// A single fp16, W split fp16. 128x128 tile, BK=32, 8 warps, warp tile 64x32.
// 2-stage cp.async pipeline (R5-proven schedule), 2 CTAs/SM.
#define RS 80
#define ARR_BYTES (128 * RS)
#define STAGE_BYTES (3 * ARR_BYTES)       // 30720 (A, Bh, Bl)
#define SMEM_GEMM (2 * STAGE_BYTES)       // 61440

__device__ __forceinline__ void gemm_load_stage(
    const unsigned short* __restrict__ A,
    const unsigned short* __restrict__ Bh, const unsigned short* __restrict__ Bl,
    int K, int m0, int n0, int k0, uint32_t smbase, int buf, int tid) {
    uint32_t sb = smbase + buf * STAGE_BYTES;
    #pragma unroll
    for (int it = 0; it < 6; it++) {
        int e = tid + it * 256;
        int arr = e >> 9;                 // 0=A 1=Bh 2=Bl
        int idx = e & 511;
        int row = idx >> 2;
        int ch = idx & 3;
        const unsigned short* src = arr == 0 ? A : arr == 1 ? Bh : Bl;
        int r0 = (arr == 0) ? m0 : n0;
        const unsigned short* g = src + (size_t)(r0 + row) * K + k0 + ch * 8;
        CP_ASYNC16(sb + arr * ARR_BYTES + row * RS + ch * 16, g);
    }
}

__global__ __launch_bounds__(256)
void tgemm_kernel(const unsigned short* __restrict__ A,
                  const unsigned short* __restrict__ Bh, const unsigned short* __restrict__ Bl,
                  int K,
                  float* __restrict__ Cf, unsigned short* __restrict__ Ch,
                  unsigned short* __restrict__ Cl, int locols, int ldlo,
                  const float* __restrict__ bias, const float* __restrict__ res,
                  int relu, int ldc) {
    extern __shared__ char smem[];
    uint32_t smbase = cvta_s(smem);
    int tid = threadIdx.x;
    int m0 = blockIdx.x * 128, n0 = blockIdx.y * 128;
    int warp = tid >> 5, lane = tid & 31;
    int wm = (warp >> 2) * 64;
    int wn = (warp & 3) * 32;
    int arow = lane & 15;
    uint32_t asel = (uint32_t)(lane >> 4) << 4;
    int ln16 = lane & 15;
    int brow = ln16 & 7;
    uint32_t bsel = (uint32_t)((ln16 >> 3) & 1) << 4;

    float acc[4][4][4];
    #pragma unroll
    for (int i = 0; i < 4; i++)
        #pragma unroll
        for (int j = 0; j < 4; j++)
            #pragma unroll
            for (int q = 0; q < 4; q++) acc[i][j][q] = 0.f;

    int NS = K >> 5;
    gemm_load_stage(A, Bh, Bl, K, m0, n0, 0, smbase, 0, tid);
    CP_COMMIT();
    if (NS > 1) {
        gemm_load_stage(A, Bh, Bl, K, m0, n0, 32, smbase, 1, tid);
        CP_COMMIT();
    }

    for (int s = 0; s < NS; s++) {
        if (s + 1 < NS) { CP_WAIT(1); } else { CP_WAIT(0); }
        __syncthreads();
        int buf = s & 1;
        uint32_t sb = smbase + (uint32_t)buf * STAGE_BYTES;
        uint32_t sA = sb, sBh = sb + ARR_BYTES;
        #pragma unroll
        for (int kk = 0; kk < 2; kk++) {
            uint32_t kb = kk * 32;
            uint32_t af[4][4], bhf[4][2], blf[4][2];
            #pragma unroll
            for (int i = 0; i < 4; i++) {
                uint32_t ra = sA + (uint32_t)(wm + i * 16 + arow) * RS + kb + asel;
                ldm_x4(af[i], ra);
            }
            #pragma unroll
            for (int j = 0; j < 4; j++) {
                uint32_t rb = sBh + (uint32_t)(wn + j * 8 + brow) * RS + kb + bsel;
                ldm_x2(bhf[j], rb);
                ldm_x2(blf[j], rb + ARR_BYTES);
            }
            #pragma unroll
            for (int i = 0; i < 4; i++)
                #pragma unroll
                for (int j = 0; j < 4; j++) {
                    mma_f16(acc[i][j], af[i], bhf[j]);
                    mma_f16(acc[i][j], af[i], blf[j]);
                }
        }
        __syncthreads();
        if (s + 2 < NS) {
            gemm_load_stage(A, Bh, Bl, K, m0, n0, (s + 2) << 5, smbase, buf, tid);
            CP_COMMIT();
        }
    }

    int qr = lane >> 2;
    int qc = (lane & 3) * 2;
    #pragma unroll
    for (int i = 0; i < 4; i++) {
        #pragma unroll
        for (int j = 0; j < 4; j++) {
            int col = n0 + wn + j * 8 + qc;
            #pragma unroll
            for (int half = 0; half < 2; half++) {
                int row = m0 + wm + i * 16 + qr + half * 8;
                float v0 = acc[i][j][half * 2 + 0];
                float v1 = acc[i][j][half * 2 + 1];
                if (bias) {
                    float2 bv = *(const float2*)(bias + col);
                    v0 += bv.x; v1 += bv.y;
                }
                size_t base = (size_t)row * ldc + col;
                if (res) {
                    float2 e = *(const float2*)(res + base);
                    v0 += e.x; v1 += e.y;
                }
                if (relu) { v0 = fmaxf(v0, 0.f); v1 = fmaxf(v1, 0.f); }
                if (Cf) { float2 o = {v0, v1}; *(float2*)(Cf + base) = o; }
                if (Ch) {
                    __half hv0 = __float2half_rn(v0);
                    __half hv1 = __float2half_rn(v1);
                    ushort2 hv;
                    hv.x = __half_as_ushort(hv0);
                    hv.y = __half_as_ushort(hv1);
                    *(ushort2*)(Ch + base) = hv;
                    if (Cl && col < locols) {
                        ushort2 lv;
                        lv.x = h1(v0 - __half2float(hv0));
                        lv.y = h1(v1 - __half2float(hv1));
                        *(ushort2*)(Cl + (size_t)row * ldlo + col) = lv;
                    }
                }
            }
        }
    }
}

// ---------------- fused flash attention ----------------
// Q split fp16 (Qh,Ql), K single, V single, P split fp16 in-register.
// One CTA = one (bh, 128-row t-tile). 256 threads (8 warps, 16 rows each).
#define FRS 144
#define FARR (64 * FRS)                    // 9216
#define QARR (128 * FRS)                   // 18432
#define FKV_STAGE (2 * FARR)               // 18432 (K, V single)
#define SMEM_FLASH (2 * QARR + 2 * FKV_STAGE)  // 73728 -> 2 CTAs/SM

__device__ __forceinline__ void flash_load_q(
    const unsigned short* __restrict__ qh, const unsigned short* __restrict__ ql,
    int rowbase, int colbase, uint32_t smbase, int tid) {
    #pragma unroll
    for (int it = 0; it < 8; it++) {
        int e = tid + it * 256;            // 0..2047
        int arr = e >> 10;                 // 0=Qh 1=Ql
        int idx = e & 1023;
        int row = idx >> 3, ch = idx & 7;
        const unsigned short* g;
        if (arr == 0)
            g = qh + (size_t)(rowbase + row) * (3 * CDIM) + colbase + ch * 8;
        else
            g = ql + (size_t)(rowbase + row) * CDIM + colbase + ch * 8;  // lo is Q-only, ld=CDIM
        CP_ASYNC16(smbase + arr * QARR + row * FRS + ch * 16, g);
    }
}
__device__ __forceinline__ void flash_load_kv(
    const unsigned short* __restrict__ qh,
    int rowbase, int kcol, int vcol, uint32_t sb, int tid) {
    #pragma unroll
    for (int it = 0; it < 4; it++) {
        int e = tid + it * 256;            // 0..1023
        int arr = e >> 9;                  // 0=K 1=V
        int idx = e & 511;
        int row = idx >> 3, ch = idx & 7;
        int col = (arr == 0) ? kcol : vcol;
        const unsigned short* g = qh + (size_t)(rowbase + row) * (3 * CDIM) + col + ch * 8;
        CP_ASYNC16(sb + arr * FARR + row * FRS + ch * 16, g);
    }
}

__global__ __launch_bounds__(256)
void flash_kernel(const unsigned short* __restrict__ qh, const unsigned short* __restrict__ ql,
                  unsigned short* __restrict__ ob) {
    extern __shared__ char smem[];
    uint32_t smbase = cvta_s(smem);
    int tid = threadIdx.x;
    int tt = (int)gridDim.x - 1 - (int)blockIdx.x;   // heaviest tiles first
    int bh = blockIdx.y;
    int b = bh >> 4, h = bh & 15;
    int t0 = tt * 128;
    int qrowbase = b * TLEN + t0;
    int qcol = h * HDIM;
    int kcol = CDIM + h * HDIM;
    int vcol = 2 * CDIM + h * HDIM;

    int warp = tid >> 5, lane = tid & 31;
    int wm = warp * 16;
    int arow = lane & 15;
    uint32_t asel = (uint32_t)(lane >> 4) << 4;
    int ln16 = lane & 15;
    int brow = ln16 & 7;
    uint32_t bsel = (uint32_t)((ln16 >> 3) & 1) << 4;
    int qr = lane >> 2;
    int qc = (lane & 3) * 2;

    float O[8][4];
    #pragma unroll
    for (int j = 0; j < 8; j++)
        #pragma unroll
        for (int q = 0; q < 4; q++) O[j][q] = 0.f;
    float m0r = -1e30f, m1r = -1e30f, l0 = 0.f, l1 = 0.f;

    int NS = 2 * (tt + 1);
    uint32_t kvbase = smbase + 2 * QARR;

    flash_load_q(qh, ql, qrowbase, qcol, smbase, tid);
    flash_load_kv(qh, b * TLEN, kcol, vcol, kvbase, tid);
    CP_COMMIT();
    flash_load_kv(qh, b * TLEN + 64, kcol, vcol, kvbase + FKV_STAGE, tid);
    CP_COMMIT();

    for (int st = 0; st < NS; st++) {
        if (st + 1 < NS) { CP_WAIT(1); } else { CP_WAIT(0); }
        __syncthreads();
        int k0 = st * 64;
        uint32_t sKV = kvbase + (st & 1) * FKV_STAGE;
        uint32_t sK = sKV, sV = sKV + FARR;

        // ---- S = (Qh + Ql) K^T ----
        float S[8][4];
        #pragma unroll
        for (int j = 0; j < 8; j++)
            #pragma unroll
            for (int q = 0; q < 4; q++) S[j][q] = 0.f;
        #pragma unroll
        for (int d = 0; d < 4; d++) {
            uint32_t kb = d * 32;
            uint32_t ah[4], al[4];
            uint32_t ra = smbase + (uint32_t)(wm + arow) * FRS + kb + asel;
            ldm_x4(ah, ra);
            ldm_x4(al, ra + QARR);
            #pragma unroll
            for (int j = 0; j < 8; j++) {
                uint32_t bf[2];
                uint32_t rb = sK + (uint32_t)(j * 8 + brow) * FRS + kb + bsel;
                ldm_x2(bf, rb);
                mma_f16(S[j], ah, bf);
                mma_f16(S[j], al, bf);
            }
        }
        int rwb = t0 + wm;
        if (k0 + 63 >= rwb) {
            int r0g = rwb + qr, r1g = r0g + 8;
            #pragma unroll
            for (int j = 0; j < 8; j++) {
                int c0 = k0 + j * 8 + qc;
                S[j][0] = (c0     > r0g) ? -1e30f : S[j][0] * 0.125f;
                S[j][1] = (c0 + 1 > r0g) ? -1e30f : S[j][1] * 0.125f;
                S[j][2] = (c0     > r1g) ? -1e30f : S[j][2] * 0.125f;
                S[j][3] = (c0 + 1 > r1g) ? -1e30f : S[j][3] * 0.125f;
            }
        } else {
            #pragma unroll
            for (int j = 0; j < 8; j++)
                #pragma unroll
                for (int q = 0; q < 4; q++) S[j][q] *= 0.125f;
        }
        float mx0 = -1e30f, mx1 = -1e30f;
        #pragma unroll
        for (int j = 0; j < 8; j++) {
            mx0 = fmaxf(mx0, fmaxf(S[j][0], S[j][1]));
            mx1 = fmaxf(mx1, fmaxf(S[j][2], S[j][3]));
        }
        mx0 = fmaxf(mx0, __shfl_xor_sync(0xffffffffu, mx0, 1));
        mx0 = fmaxf(mx0, __shfl_xor_sync(0xffffffffu, mx0, 2));
        mx1 = fmaxf(mx1, __shfl_xor_sync(0xffffffffu, mx1, 1));
        mx1 = fmaxf(mx1, __shfl_xor_sync(0xffffffffu, mx1, 2));
        float mn0 = fmaxf(m0r, mx0), mn1 = fmaxf(m1r, mx1);
        float c0 = __expf(m0r - mn0), c1 = __expf(m1r - mn1);
        float rs0 = 0.f, rs1 = 0.f;
        #pragma unroll
        for (int j = 0; j < 8; j++) {
            S[j][0] = __expf(S[j][0] - mn0);
            S[j][1] = __expf(S[j][1] - mn0);
            S[j][2] = __expf(S[j][2] - mn1);
            S[j][3] = __expf(S[j][3] - mn1);
            rs0 += S[j][0] + S[j][1];
            rs1 += S[j][2] + S[j][3];
        }
        rs0 += __shfl_xor_sync(0xffffffffu, rs0, 1);
        rs0 += __shfl_xor_sync(0xffffffffu, rs0, 2);
        rs1 += __shfl_xor_sync(0xffffffffu, rs1, 1);
        rs1 += __shfl_xor_sync(0xffffffffu, rs1, 2);
        l0 = l0 * c0 + rs0;
        l1 = l1 * c1 + rs1;
        m0r = mn0; m1r = mn1;
        #pragma unroll
        for (int j = 0; j < 8; j++) {
            O[j][0] *= c0; O[j][1] *= c0;
            O[j][2] *= c1; O[j][3] *= c1;
        }
        // ---- O += (Ph + Pl) V ----
        #pragma unroll
        for (int kk = 0; kk < 4; kk++) {
            int j0 = 2 * kk, j1 = 2 * kk + 1;
            uint32_t pah[4], pal[4];
            pack2h(S[j0][0], S[j0][1], pah[0], pal[0]);
            pack2h(S[j0][2], S[j0][3], pah[1], pal[1]);
            pack2h(S[j1][0], S[j1][1], pah[2], pal[2]);
            pack2h(S[j1][2], S[j1][3], pah[3], pal[3]);
            uint32_t vrow = (uint32_t)(kk * 16 + (ln16 & 7) + ((ln16 >> 3) & 1) * 8);
            #pragma unroll
            for (int jd = 0; jd < 8; jd++) {
                uint32_t vf[2];
                uint32_t rv = sV + vrow * FRS + jd * 16;
                ldm_x2t(vf, rv);
                mma_f16(O[jd], pah, vf);
                mma_f16(O[jd], pal, vf);
            }
        }
        __syncthreads();
        if (st + 2 < NS) {
            flash_load_kv(qh, b * TLEN + (st + 2) * 64, kcol, vcol,
                          kvbase + (st & 1) * FKV_STAGE, tid);
            CP_COMMIT();
        }
    }

    float inv0 = 1.f / l0, inv1 = 1.f / l1;
    int row0 = b * TLEN + t0 + wm + qr;
    #pragma unroll
    for (int jd = 0; jd < 8; jd++) {
        int col = qcol + jd * 8 + qc;
        ushort2 hv;
        hv.x = h1(O[jd][0] * inv0);
        hv.y = h1(O[jd][1] * inv0);
        *(ushort2*)(ob + (size_t)row0 * CDIM + col) = hv;
        hv.x = h1(O[jd][2] * inv1);
        hv.y = h1(O[jd][3] * inv1);
        *(ushort2*)(ob + (size_t)(row0 + 8) * CDIM + col) = hv;
    }
}

// ---------------- host ----------------
extern "C" void kernel_launch(void* const* d_in, const int* in_sizes, int n_in,
                              void* d_out, int out_size) {
    const int* idx = (const int*)d_in[0];
    const float* tok = (const float*)d_in[1];
    const float* pos = (const float*)d_in[2];
    const float* wq = (const float*)d_in[3];
    const float* wk = (const float*)d_in[4];
    const float* wv = (const float*)d_in[5];
    const float* wproj = (const float*)d_in[6];
    const float* bproj = (const float*)d_in[7];
    const float* ln1g = (const float*)d_in[8];
    const float* ln1b = (const float*)d_in[9];
    const float* ln2g = (const float*)d_in[10];
    const float* ln2b = (const float*)d_in[11];
    const float* w1 = (const float*)d_in[12];
    const float* b1 = (const float*)d_in[13];
    const float* w2 = (const float*)d_in[14];
    const float* b2 = (const float*)d_in[15];
    const float* lnfg = (const float*)d_in[16];
    const float* lnfb = (const float*)d_in[17];
    const float* wlm = (const float*)d_in[18];
    const float* blm = (const float*)d_in[19];
    float* out = (float*)d_out;

    float* px;
    unsigned short *pqkvb_h, *pqkvb_l, *phb, *pob, *pffb;
    unsigned short *pwqkv_h, *pwqkv_l, *pwproj_h, *pwproj_l;
    unsigned short *pw1_h, *pw1_l, *pw2_h, *pw2_l, *pwlm_h, *pwlm_l;
    cudaGetSymbolAddress((void**)&px, g_x);
    cudaGetSymbolAddress((void**)&pqkvb_h, g_qkvb_h);
    cudaGetSymbolAddress((void**)&pqkvb_l, g_qkvb_l);
    cudaGetSymbolAddress((void**)&phb, g_hb);
    cudaGetSymbolAddress((void**)&pob, g_ob);
    cudaGetSymbolAddress((void**)&pffb, g_ffb);
    cudaGetSymbolAddress((void**)&pwqkv_h, g_wqkv_h);
    cudaGetSymbolAddress((void**)&pwqkv_l, g_wqkv_l);
    cudaGetSymbolAddress((void**)&pwproj_h, g_wproj_h);
    cudaGetSymbolAddress((void**)&pwproj_l, g_wproj_l);
    cudaGetSymbolAddress((void**)&pw1_h, g_w1_h);
    cudaGetSymbolAddress((void**)&pw1_l, g_w1_l);
    cudaGetSymbolAddress((void**)&pw2_h, g_w2_h);
    cudaGetSymbolAddress((void**)&pw2_l, g_w2_l);
    cudaGetSymbolAddress((void**)&pwlm_h, g_wlm_h);
    cudaGetSymbolAddress((void**)&pwlm_l, g_wlm_l);

    cudaFuncSetAttribute(tgemm_kernel, cudaFuncAttributeMaxDynamicSharedMemorySize, SMEM_GEMM);
    cudaFuncSetAttribute(flash_kernel, cudaFuncAttributeMaxDynamicSharedMemorySize, SMEM_FLASH);

    dim3 tb(32, 8);
    tsplit_qkv_kernel<<<dim3(96, 32, 8), tb>>>(wq, wk, wv, pwqkv_h, pwqkv_l);
    tsplit_mat_kernel<<<dim3(32, 32, 8), tb>>>(wproj, pwproj_h, pwproj_l, CDIM, CDIM);
    tsplit_mat_kernel<<<dim3(128, 32, 8), tb>>>(w1, pw1_h, pw1_l, CDIM, FF);
    tsplit_mat_kernel<<<dim3(32, 128, 8), tb>>>(w2, pw2_h, pw2_l, FF, CDIM);
    tsplit_mat_kernel<<<dim3(1000, 32, 1), tb>>>(wlm, pwlm_h, pwlm_l, CDIM, VOCAB);

    embed_kernel<<<NTOK, 256>>>(idx, tok, pos, px);

    for (int l = 0; l < NLAYER; l++) {
        ln_kernel<<<NTOK, 256>>>(px, ln1g + (size_t)l * CDIM, ln1b + (size_t)l * CDIM, phb);
        // QKV: hi for all 3072 cols; lo only for Q cols (<1024), stored at ld=CDIM
        tgemm_kernel<<<dim3(32, 24), 256, SMEM_GEMM>>>(
            phb, pwqkv_h + (size_t)l * 3072 * 1024, pwqkv_l + (size_t)l * 3072 * 1024,
            CDIM, nullptr, pqkvb_h, pqkvb_l, CDIM, CDIM, nullptr, nullptr, 0, 3 * CDIM);
        flash_kernel<<<dim3(8, BATCH * NHEAD), 256, SMEM_FLASH>>>(pqkvb_h, pqkvb_l, pob);
        tgemm_kernel<<<dim3(32, 8), 256, SMEM_GEMM>>>(
            pob, pwproj_h + (size_t)l * CDIM * CDIM, pwproj_l + (size_t)l * CDIM * CDIM,
            CDIM, px, nullptr, nullptr, 0, 0, bproj + (size_t)l * CDIM, px, 0, CDIM);
        ln_kernel<<<NTOK, 256>>>(px, ln2g + (size_t)l * CDIM, ln2b + (size_t)l * CDIM, phb);
        tgemm_kernel<<<dim3(32, 32), 256, SMEM_GEMM>>>(
            phb, pw1_h + (size_t)l * FF * CDIM, pw1_l + (size_t)l * FF * CDIM,
            CDIM, nullptr, pffb, nullptr, 0, 0, b1 + (size_t)l * FF, nullptr, 1, FF);
        tgemm_kernel<<<dim3(32, 8), 256, SMEM_GEMM>>>(
            pffb, pw2_h + (size_t)l * CDIM * FF, pw2_l + (size_t)l * CDIM * FF,
            FF, px, nullptr, nullptr, 0, 0, b2 + (size_t)l * CDIM, px, 0, CDIM);
    }
    ln_kernel<<<NTOK, 256>>>(px, lnfg, lnfb, phb);
    tgemm_kernel<<<dim3(32, 250), 256, SMEM_GEMM>>>(
        phb, pwlm_h, pwlm_l, CDIM, out, nullptr, nullptr, 0, 0, blm, nullptr, 0, VOCAB);
}

// round 11
// speedup vs baseline: 1.0333x; 1.0333x over previous
#include <cuda_runtime.h>
#include <cuda_fp16.h>
#include <cstdint>
#include <math.h>

#define BATCH 4
#define TLEN 1024
#define CDIM 1024
#define NHEAD 16
#define HDIM 64
#define NLAYER 8
#define VOCAB 32000
#define NTOK (BATCH * TLEN)
#define FF (4 * CDIM)

// ---------------- device scratch ----------------
__device__ float g_x[NTOK * CDIM];
__device__ unsigned short g_qkvb_h[NTOK * 3 * CDIM], g_qkvb_l[NTOK * CDIM];  // lo only for Q
__device__ unsigned short g_hb[NTOK * CDIM];
__device__ unsigned short g_ob[NTOK * CDIM];
__device__ unsigned short g_ffb[(size_t)NTOK * FF];
__device__ unsigned short g_wqkv_h[(size_t)NLAYER * 3 * CDIM * CDIM], g_wqkv_l[(size_t)NLAYER * 3 * CDIM * CDIM];
__device__ unsigned short g_wproj_h[(size_t)NLAYER * CDIM * CDIM], g_wproj_l[(size_t)NLAYER * CDIM * CDIM];
__device__ unsigned short g_w1_h[(size_t)NLAYER * FF * CDIM], g_w1_l[(size_t)NLAYER * FF * CDIM];
__device__ unsigned short g_w2_h[(size_t)NLAYER * CDIM * FF], g_w2_l[(size_t)NLAYER * CDIM * FF];
__device__ unsigned short g_wlm_h[(size_t)VOCAB * CDIM], g_wlm_l[(size_t)VOCAB * CDIM];

// ---------------- helpers ----------------
__device__ __forceinline__ uint32_t cvta_s(const void* p) {
    uint32_t a;
    asm("{ .reg .u64 t; cvta.to.shared.u64 t, %1; cvt.u32.u64 %0, t; }" : "=r"(a) : "l"(p));
    return a;
}
#define CP_ASYNC16(dst, src) \
    asm volatile("cp.async.cg.shared.global [%0], [%1], 16;" :: "r"(dst), "l"(src))
#define CP_COMMIT() asm volatile("cp.async.commit_group;" ::: "memory")
#define CP_WAIT(n)  asm volatile("cp.async.wait_group %0;" :: "n"(n) : "memory")

__device__ __forceinline__ void ldm_x4(uint32_t* r, uint32_t addr) {
    asm volatile("ldmatrix.sync.aligned.m8n8.x4.shared.b16 {%0,%1,%2,%3}, [%4];"
                 : "=r"(r[0]), "=r"(r[1]), "=r"(r[2]), "=r"(r[3]) : "r"(addr));
}
__device__ __forceinline__ void ldm_x2(uint32_t* r, uint32_t addr) {
    asm volatile("ldmatrix.sync.aligned.m8n8.x2.shared.b16 {%0,%1}, [%2];"
                 : "=r"(r[0]), "=r"(r[1]) : "r"(addr));
}
__device__ __forceinline__ void ldm_x2t(uint32_t* r, uint32_t addr) {
    asm volatile("ldmatrix.sync.aligned.m8n8.x2.trans.shared.b16 {%0,%1}, [%2];"
                 : "=r"(r[0]), "=r"(r[1]) : "r"(addr));
}
__device__ __forceinline__ void mma_f16(float* d, const uint32_t* a, const uint32_t* b) {
    asm volatile(
        "mma.sync.aligned.m16n8k16.row.col.f32.f16.f16.f32 "
        "{%0,%1,%2,%3}, {%4,%5,%6,%7}, {%8,%9}, {%0,%1,%2,%3};"
        : "+f"(d[0]), "+f"(d[1]), "+f"(d[2]), "+f"(d[3])
        : "r"(a[0]), "r"(a[1]), "r"(a[2]), "r"(a[3]), "r"(b[0]), "r"(b[1]));
}
__device__ __forceinline__ void hsplit(float v, unsigned short& h, unsigned short& l) {
    __half hb = __float2half_rn(v);
    __half lb = __float2half_rn(v - __half2float(hb));
    h = __half_as_ushort(hb);
    l = __half_as_ushort(lb);
}
__device__ __forceinline__ unsigned short h1(float v) {
    return __half_as_ushort(__float2half_rn(v));
}
__device__ __forceinline__ void pack2h(float a, float b, uint32_t& hi, uint32_t& lo) {
    unsigned short h0, l0, hh1, l1;
    hsplit(a, h0, l0);
    hsplit(b, hh1, l1);
    hi = (uint32_t)h0 | ((uint32_t)hh1 << 16);
    lo = (uint32_t)l0 | ((uint32_t)l1 << 16);
}

// ---------------- weight prep (transpose + fp16 hi/lo split) ----------------
__global__ void tsplit_qkv_kernel(const float* __restrict__ wq, const float* __restrict__ wk,
                                  const float* __restrict__ wv,
                                  unsigned short* __restrict__ dh, unsigned short* __restrict__ dl) {
    __shared__ float t[32][33];
    int n0 = blockIdx.x * 32, k0 = blockIdx.y * 32, l = blockIdx.z;
    int sel = n0 >> 10;
    const float* src = sel == 0 ? wq : (sel == 1 ? wk : wv);
    int within = n0 & 1023;
    int h = within >> 6, d0 = within & 63;
    const float* sp = src + ((size_t)(l * 16 + h) * 1024 + k0) * 64 + d0;
    int tx = threadIdx.x, ty = threadIdx.y;
    #pragma unroll
    for (int i = 0; i < 4; i++) t[ty + i * 8][tx] = sp[(size_t)(ty + i * 8) * 64 + tx];
    __syncthreads();
    size_t ob = (size_t)l * 3072 * 1024;
    #pragma unroll
    for (int i = 0; i < 4; i++) {
        int n = n0 + ty + i * 8, k = k0 + tx;
        unsigned short hh, ll;
        hsplit(t[tx][ty + i * 8], hh, ll);
        dh[ob + (size_t)n * 1024 + k] = hh;
        dl[ob + (size_t)n * 1024 + k] = ll;
    }
}
__global__ void tsplit_mat_kernel(const float* __restrict__ src,
                                  unsigned short* __restrict__ dh, unsigned short* __restrict__ dl,
                                  int K, int N) {
    __shared__ float t[32][33];
    int n0 = blockIdx.x * 32, k0 = blockIdx.y * 32;
    size_t l = blockIdx.z;
    const float* sp = src + l * (size_t)K * N;
    int tx = threadIdx.x, ty = threadIdx.y;
    #pragma unroll
    for (int i = 0; i < 4; i++) t[ty + i * 8][tx] = sp[(size_t)(k0 + ty + i * 8) * N + n0 + tx];
    __syncthreads();
    size_t ob = l * (size_t)K * N;
    #pragma unroll
    for (int i = 0; i < 4; i++) {
        int n = n0 + ty + i * 8, k = k0 + tx;
        unsigned short hh, ll;
        hsplit(t[tx][ty + i * 8], hh, ll);
        dh[ob + (size_t)n * K + k] = hh;
        dl[ob + (size_t)n * K + k] = ll;
    }
}

// ---------------- embed ----------------
__global__ void embed_kernel(const int* __restrict__ idx, const float* __restrict__ tok,
                             const float* __restrict__ pos, float* __restrict__ x) {
    int row = blockIdx.x;
    int t = row & (TLEN - 1);
    int token = idx[row];
    const float4* te = (const float4*)(tok + (size_t)token * CDIM);
    const float4* pe = (const float4*)(pos + (size_t)t * CDIM);
    float4* xo = (float4*)(x + (size_t)row * CDIM);
    int i = threadIdx.x;
    float4 a = te[i], b = pe[i];
    a.x += b.x; a.y += b.y; a.z += b.z; a.w += b.w;
    xo[i] = a;
}

// ---------------- LayerNorm -> single fp16 ----------------
__global__ void ln_kernel(const float* __restrict__ x, const float* __restrict__ g,
                          const float* __restrict__ b, unsigned short* __restrict__ oh) {
    int row = blockIdx.x;
    int tid = threadIdx.x;
    float4 v = ((const float4*)(x + (size_t)row * CDIM))[tid];
    float s = v.x + v.y + v.z + v.w;
    float ss = v.x * v.x + v.y * v.y + v.z * v.z + v.w * v.w;
    #pragma unroll
    for (int o = 16; o > 0; o >>= 1) {
        s += __shfl_xor_sync(0xffffffffu, s, o);
        ss += __shfl_xor_sync(0xffffffffu, ss, o);
    }
    __shared__ float sm[8], sm2[8];
    int w = tid >> 5, lane = tid & 31;
    if (lane == 0) { sm[w] = s; sm2[w] = ss; }
    __syncthreads();
    s = 0.f; ss = 0.f;
    #pragma unroll
    for (int i = 0; i < 8; i++) { s += sm[i]; ss += sm2[i]; }
    float mean = s * (1.0f / CDIM);
    float var = ss * (1.0f / CDIM) - mean * mean;
    float rstd = rsqrtf(var + 1e-5f);
    float4 gv = ((const float4*)g)[tid];
    float4 bv = ((const float4*)b)[tid];
    ushort4 hv;
    hv.x = h1((v.x - mean) * rstd * gv.x + bv.x);
    hv.y = h1((v.y - mean) * rstd * gv.y + bv.y);
    hv.z = h1((v.z - mean) * rstd * gv.z + bv.z);
    hv.w = h1((v.w - mean) * rstd * gv.w + bv.w);
    *(ushort4*)(oh + (size_t)row * CDIM + tid * 4) = hv;
}

// ---------------- HMMA GEMM: D[M,N] = A[M,K] * (Wh[+Wl])[N,K]^T ----------------
// A single fp16. Wl applied only for output cols < nlo (uniform per block).
// 128x128 tile, BK=32, 8 warps, warp tile 64x32, 2-stage cp.async, 2 CTAs/SM.
#define RS 80
#define ARR_BYTES (128 * RS)
#define STAGE_BYTES (3 * ARR_BYTES)       // 30720 (A, Bh, Bl)
#define SMEM_GEMM (2 * STAGE_BYTES)       // 61440

__device__ __forceinline__ void gemm_load_stage(
    const unsigned short* __restrict__ A,
    const unsigned short* __restrict__ Bh, const unsigned short* __restrict__ Bl,
    int K, int m0, int n0, int k0, uint32_t smbase, int buf, int tid, int use_lo) {
    uint32_t sb = smbase + buf * STAGE_BYTES;
    #pragma unroll
    for (int it = 0; it < 6; it++) {
        int e = tid + it * 256;
        int arr = e >> 9;                 // 0=A 1=Bh 2=Bl
        if (arr == 2 && !use_lo) continue;
        int idx = e & 511;
        int row = idx >> 2;
        int ch = idx & 3;
        const unsigned short* src = arr == 0 ? A : arr == 1 ? Bh : Bl;
        int r0 = (arr == 0) ? m0 : n0;
        const unsigned short* g = src + (size_t)(r0 + row) * K + k0 + ch * 8;
        CP_ASYNC16(sb + arr * ARR_BYTES + row * RS + ch * 16, g);
    }
}

__global__ __launch_bounds__(256)
void tgemm_kernel(const unsigned short* __restrict__ A,
                  const unsigned short* __restrict__ Bh, const unsigned short* __restrict__ Bl,
                  int K, int nlo,
                  float* __restrict__ Cf, unsigned short* __restrict__ Ch,
                  unsigned short* __restrict__ Cl, int locols, int ldlo,
                  const float* __restrict__ bias, const float* __restrict__ res,
                  int relu, int ldc) {
    extern __shared__ char smem[];
    uint32_t smbase = cvta_s(smem);
    int tid = threadIdx.x;
    int m0 = blockIdx.x * 128, n0 = blockIdx.y * 128;
    int use_lo = (n0 < nlo);
    int warp = tid >> 5, lane = tid & 31;
    int wm = (warp >> 2) * 64;
    int wn = (warp & 3) * 32;
    int arow = lane & 15;
    uint32_t asel = (uint32_t)(lane >> 4) << 4;
    int ln16 = lane & 15;
    int brow = ln16 & 7;
    uint32_t bsel = (uint32_t)((ln16 >> 3) & 1) << 4;

    float acc[4][4][4];
    #pragma unroll
    for (int i = 0; i < 4; i++)
        #pragma unroll
        for (int j = 0; j < 4; j++)
            #pragma unroll
            for (int q = 0; q < 4; q++) acc[i][j][q] = 0.f;

    int NS = K >> 5;
    gemm_load_stage(A, Bh, Bl, K, m0, n0, 0, smbase, 0, tid, use_lo);
    CP_COMMIT();
    if (NS > 1) {
        gemm_load_stage(A, Bh, Bl, K, m0, n0, 32, smbase, 1, tid, use_lo);
        CP_COMMIT();
    }

    for (int s = 0; s < NS; s++) {
        if (s + 1 < NS) { CP_WAIT(1); } else { CP_WAIT(0); }
        __syncthreads();
        int buf = s & 1;
        uint32_t sb = smbase + (uint32_t)buf * STAGE_BYTES;
        uint32_t sA = sb, sBh = sb + ARR_BYTES;
        #pragma unroll
        for (int kk = 0; kk < 2; kk++) {
            uint32_t kb = kk * 32;
            uint32_t af[4][4], bhf[4][2], blf[4][2];
            #pragma unroll
            for (int i = 0; i < 4; i++) {
                uint32_t ra = sA + (uint32_t)(wm + i * 16 + arow) * RS + kb + asel;
                ldm_x4(af[i], ra);
            }
            #pragma unroll
            for (int j = 0; j < 4; j++) {
                uint32_t rb = sBh + (uint32_t)(wn + j * 8 + brow) * RS + kb + bsel;
                ldm_x2(bhf[j], rb);
                if (use_lo) ldm_x2(blf[j], rb + ARR_BYTES);
            }
            #pragma unroll
            for (int i = 0; i < 4; i++)
                #pragma unroll
                for (int j = 0; j < 4; j++) {
                    mma_f16(acc[i][j], af[i], bhf[j]);
                    if (use_lo) mma_f16(acc[i][j], af[i], blf[j]);
                }
        }
        __syncthreads();
        if (s + 2 < NS) {
            gemm_load_stage(A, Bh, Bl, K, m0, n0, (s + 2) << 5, smbase, buf, tid, use_lo);
            CP_COMMIT();
        }
    }

    int qr = lane >> 2;
    int qc = (lane & 3) * 2;
    #pragma unroll
    for (int i = 0; i < 4; i++) {
        #pragma unroll
        for (int j = 0; j < 4; j++) {
            int col = n0 + wn + j * 8 + qc;
            #pragma unroll
            for (int half = 0; half < 2; half++) {
                int row = m0 + wm + i * 16 + qr + half * 8;
                float v0 = acc[i][j][half * 2 + 0];
                float v1 = acc[i][j][half * 2 + 1];
                if (bias) {
                    float2 bv = *(const float2*)(bias + col);
                    v0 += bv.x; v1 += bv.y;
                }
                size_t base = (size_t)row * ldc + col;
                if (res) {
                    float2 e = *(const float2*)(res + base);
                    v0 += e.x; v1 += e.y;
                }
                if (relu) { v0 = fmaxf(v0, 0.f); v1 = fmaxf(v1, 0.f); }
                if (Cf) { float2 o = {v0, v1}; *(float2*)(Cf + base) = o; }
                if (Ch) {
                    __half hv0 = __float2half_rn(v0);
                    __half hv1 = __float2half_rn(v1);
                    ushort2 hv;
                    hv.x = __half_as_ushort(hv0);
                    hv.y = __half_as_ushort(hv1);
                    *(ushort2*)(Ch + base) = hv;
                    if (Cl && col < locols) {
                        ushort2 lv;
                        lv.x = h1(v0 - __half2float(hv0));
                        lv.y = h1(v1 - __half2float(hv1));
                        *(ushort2*)(Cl + (size_t)row * ldlo + col) = lv;
                    }
                }
            }
        }
    }
}

// ---------------- fused flash attention (R9 geometry: 64-row tiles, 128 thr) ----
// Q split fp16 (Qh,Ql), K single, V single, P split fp16 in-register.
#define FRS 144
#define FARR (64 * FRS)                   // 9216
#define FKV_STAGE (2 * FARR)              // 18432 (K, V single)
#define SMEM_FLASH (2 * FARR + 2 * FKV_STAGE)  // 55296

__device__ __forceinline__ void flash_load_q(
    const unsigned short* __restrict__ qh, const unsigned short* __restrict__ ql,
    int rowbase, int colbase, uint32_t smbase, int tid) {
    #pragma unroll
    for (int it = 0; it < 8; it++) {
        int e = tid + it * 128;
        int arr = e >> 9;                 // 0=Qh 1=Ql
        int idx = e & 511;
        int row = idx >> 3, ch = idx & 7;
        const unsigned short* g;
        if (arr == 0)
            g = qh + (size_t)(rowbase + row) * (3 * CDIM) + colbase + ch * 8;
        else
            g = ql + (size_t)(rowbase + row) * CDIM + colbase + ch * 8;  // lo: Q-only, ld=CDIM
        CP_ASYNC16(smbase + arr * FARR + row * FRS + ch * 16, g);
    }
}
__device__ __forceinline__ void flash_load_kv(
    const unsigned short* __restrict__ qh,
    int rowbase, int kcol, int vcol, uint32_t sb, int tid) {
    #pragma unroll
    for (int it = 0; it < 8; it++) {
        int e = tid + it * 128;
        int arr = e >> 9;                 // 0=K 1=V
        int idx = e & 511;
        int row = idx >> 3, ch = idx & 7;
        int col = (arr == 0) ? kcol : vcol;
        const unsigned short* g = qh + (size_t)(rowbase + row) * (3 * CDIM) + col + ch * 8;
        CP_ASYNC16(sb + arr * FARR + row * FRS + ch * 16, g);
    }
}

__global__ __launch_bounds__(128)
void flash_kernel(const unsigned short* __restrict__ qh, const unsigned short* __restrict__ ql,
                  unsigned short* __restrict__ ob) {
    extern __shared__ char smem[];
    uint32_t smbase = cvta_s(smem);
    int tid = threadIdx.x;
    int tt = (int)gridDim.x - 1 - (int)blockIdx.x;
    int bh = blockIdx.y;
    int b = bh >> 4, h = bh & 15;
    int t0 = tt * 64;
    int qrowbase = b * TLEN + t0;
    int qcol = h * HDIM;
    int kcol = CDIM + h * HDIM;
    int vcol = 2 * CDIM + h * HDIM;

    int warp = tid >> 5, lane = tid & 31;
    int wm = warp * 16;
    int arow = lane & 15;
    uint32_t asel = (uint32_t)(lane >> 4) << 4;
    int ln16 = lane & 15;
    int brow = ln16 & 7;
    uint32_t bsel = (uint32_t)((ln16 >> 3) & 1) << 4;
    int qr = lane >> 2;
    int qc = (lane & 3) * 2;

    float O[8][4];
    #pragma unroll
    for (int j = 0; j < 8; j++)
        #pragma unroll
        for (int q = 0; q < 4; q++) O[j][q] = 0.f;
    float m0r = -1e30f, m1r = -1e30f, l0 = 0.f, l1 = 0.f;

    int NS = tt + 1;
    uint32_t kvbase = smbase + 2 * FARR;

    flash_load_q(qh, ql, qrowbase, qcol, smbase, tid);
    flash_load_kv(qh, b * TLEN, kcol, vcol, kvbase, tid);
    CP_COMMIT();
    if (NS > 1) {
        flash_load_kv(qh, b * TLEN + 64, kcol, vcol, kvbase + FKV_STAGE, tid);
        CP_COMMIT();
    }

    for (int st = 0; st < NS; st++) {
        if (st + 1 < NS) { CP_WAIT(1); } else { CP_WAIT(0); }
        __syncthreads();
        uint32_t sKV = kvbase + (st & 1) * FKV_STAGE;
        uint32_t sK = sKV, sV = sKV + FARR;

        float S[8][4];
        #pragma unroll
        for (int j = 0; j < 8; j++)
            #pragma unroll
            for (int q = 0; q < 4; q++) S[j][q] = 0.f;
        #pragma unroll
        for (int d = 0; d < 4; d++) {
            uint32_t kb = d * 32;
            uint32_t ah[4], al[4];
            uint32_t ra = smbase + (uint32_t)(wm + arow) * FRS + kb + asel;
            ldm_x4(ah, ra);
            ldm_x4(al, ra + FARR);
            #pragma unroll
            for (int j = 0; j < 8; j++) {
                uint32_t bf[2];
                uint32_t rb = sK + (uint32_t)(j * 8 + brow) * FRS + kb + bsel;
                ldm_x2(bf, rb);
                mma_f16(S[j], ah, bf);
                mma_f16(S[j], al, bf);
            }
        }
        if (st == tt) {
            int r0 = wm + qr, r1 = wm + qr + 8;
            #pragma unroll
            for (int j = 0; j < 8; j++) {
                int c0 = j * 8 + qc;
                S[j][0] = (c0     > r0) ? -1e30f : S[j][0] * 0.125f;
                S[j][1] = (c0 + 1 > r0) ? -1e30f : S[j][1] * 0.125f;
                S[j][2] = (c0     > r1) ? -1e30f : S[j][2] * 0.125f;
                S[j][3] = (c0 + 1 > r1) ? -1e30f : S[j][3] * 0.125f;
            }
        } else {
            #pragma unroll
            for (int j = 0; j < 8; j++)
                #pragma unroll
                for (int q = 0; q < 4; q++) S[j][q] *= 0.125f;
        }
        float mx0 = -1e30f, mx1 = -1e30f;
        #pragma unroll
        for (int j = 0; j < 8; j++) {
            mx0 = fmaxf(mx0, fmaxf(S[j][0], S[j][1]));
            mx1 = fmaxf(mx1, fmaxf(S[j][2], S[j][3]));
        }
        mx0 = fmaxf(mx0, __shfl_xor_sync(0xffffffffu, mx0, 1));
        mx0 = fmaxf(mx0, __shfl_xor_sync(0xffffffffu, mx0, 2));
        mx1 = fmaxf(mx1, __shfl_xor_sync(0xffffffffu, mx1, 1));
        mx1 = fmaxf(mx1, __shfl_xor_sync(0xffffffffu, mx1, 2));
        float mn0 = fmaxf(m0r, mx0), mn1 = fmaxf(m1r, mx1);
        float c0 = __expf(m0r - mn0), c1 = __expf(m1r - mn1);
        float rs0 = 0.f, rs1 = 0.f;
        #pragma unroll
        for (int j = 0; j < 8; j++) {
            S[j][0] = __expf(S[j][0] - mn0);
            S[j][1] = __expf(S[j][1] - mn0);
            S[j][2] = __expf(S[j][2] - mn1);
            S[j][3] = __expf(S[j][3] - mn1);
            rs0 += S[j][0] + S[j][1];
            rs1 += S[j][2] + S[j][3];
        }
        rs0 += __shfl_xor_sync(0xffffffffu, rs0, 1);
        rs0 += __shfl_xor_sync(0xffffffffu, rs0, 2);
        rs1 += __shfl_xor_sync(0xffffffffu, rs1, 1);
        rs1 += __shfl_xor_sync(0xffffffffu, rs1, 2);
        l0 = l0 * c0 + rs0;
        l1 = l1 * c1 + rs1;
        m0r = mn0; m1r = mn1;
        #pragma unroll
        for (int j = 0; j < 8; j++) {
            O[j][0] *= c0; O[j][1] *= c0;
            O[j][2] *= c1; O[j][3] *= c1;
        }
        #pragma unroll
        for (int kk = 0; kk < 4; kk++) {
            int j0 = 2 * kk, j1 = 2 * kk + 1;
            uint32_t pah[4], pal[4];
            pack2h(S[j0][0], S[j0][1], pah[0], pal[0]);
            pack2h(S[j0][2], S[j0][3], pah[1], pal[1]);
            pack2h(S[j1][0], S[j1][1], pah[2], pal[2]);
            pack2h(S[j1][2], S[j1][3], pah[3], pal[3]);
            uint32_t vrow = (uint32_t)(kk * 16 + (ln16 & 7) + ((ln16 >> 3) & 1) * 8);
            #pragma unroll
            for (int jd = 0; jd < 8; jd++) {
                uint32_t vf[2];
                uint32_t rv = sV + vrow * FRS + jd * 16;
                ldm_x2t(vf, rv);
                mma_f16(O[jd], pah, vf);
                mma_f16(O[jd], pal, vf);
            }
        }
        __syncthreads();
        if (st + 2 < NS) {
            flash_load_kv(qh, b * TLEN + (st + 2) * 64, kcol, vcol,
                          kvbase + (st & 1) * FKV_STAGE, tid);
            CP_COMMIT();
        }
    }

    float inv0 = 1.f / l0, inv1 = 1.f / l1;
    int row0 = b * TLEN + t0 + wm + qr;
    #pragma unroll
    for (int jd = 0; jd < 8; jd++) {
        int col = qcol + jd * 8 + qc;
        ushort2 hv;
        hv.x = h1(O[jd][0] * inv0);
        hv.y = h1(O[jd][1] * inv0);
        *(ushort2*)(ob + (size_t)row0 * CDIM + col) = hv;
        hv.x = h1(O[jd][2] * inv1);
        hv.y = h1(O[jd][3] * inv1);
        *(ushort2*)(ob + (size_t)(row0 + 8) * CDIM + col) = hv;
    }
}

// ---------------- host ----------------
extern "C" void kernel_launch(void* const* d_in, const int* in_sizes, int n_in,
                              void* d_out, int out_size) {
    const int* idx = (const int*)d_in[0];
    const float* tok = (const float*)d_in[1];
    const float* pos = (const float*)d_in[2];
    const float* wq = (const float*)d_in[3];
    const float* wk = (const float*)d_in[4];
    const float* wv = (const float*)d_in[5];
    const float* wproj = (const float*)d_in[6];
    const float* bproj = (const float*)d_in[7];
    const float* ln1g = (const float*)d_in[8];
    const float* ln1b = (const float*)d_in[9];
    const float* ln2g = (const float*)d_in[10];
    const float* ln2b = (const float*)d_in[11];
    const float* w1 = (const float*)d_in[12];
    const float* b1 = (const float*)d_in[13];
    const float* w2 = (const float*)d_in[14];
    const float* b2 = (const float*)d_in[15];
    const float* lnfg = (const float*)d_in[16];
    const float* lnfb = (const float*)d_in[17];
    const float* wlm = (const float*)d_in[18];
    const float* blm = (const float*)d_in[19];
    float* out = (float*)d_out;

    float* px;
    unsigned short *pqkvb_h, *pqkvb_l, *phb, *pob, *pffb;
    unsigned short *pwqkv_h, *pwqkv_l, *pwproj_h, *pwproj_l;
    unsigned short *pw1_h, *pw1_l, *pw2_h, *pw2_l, *pwlm_h, *pwlm_l;
    cudaGetSymbolAddress((void**)&px, g_x);
    cudaGetSymbolAddress((void**)&pqkvb_h, g_qkvb_h);
    cudaGetSymbolAddress((void**)&pqkvb_l, g_qkvb_l);
    cudaGetSymbolAddress((void**)&phb, g_hb);
    cudaGetSymbolAddress((void**)&pob, g_ob);
    cudaGetSymbolAddress((void**)&pffb, g_ffb);
    cudaGetSymbolAddress((void**)&pwqkv_h, g_wqkv_h);
    cudaGetSymbolAddress((void**)&pwqkv_l, g_wqkv_l);
    cudaGetSymbolAddress((void**)&pwproj_h, g_wproj_h);
    cudaGetSymbolAddress((void**)&pwproj_l, g_wproj_l);
    cudaGetSymbolAddress((void**)&pw1_h, g_w1_h);
    cudaGetSymbolAddress((void**)&pw1_l, g_w1_l);
    cudaGetSymbolAddress((void**)&pw2_h, g_w2_h);
    cudaGetSymbolAddress((void**)&pw2_l, g_w2_l);
    cudaGetSymbolAddress((void**)&pwlm_h, g_wlm_h);
    cudaGetSymbolAddress((void**)&pwlm_l, g_wlm_l);

    cudaFuncSetAttribute(tgemm_kernel, cudaFuncAttributeMaxDynamicSharedMemorySize, SMEM_GEMM);
    cudaFuncSetAttribute(flash_kernel, cudaFuncAttributeMaxDynamicSharedMemorySize, SMEM_FLASH);

    dim3 tb(32, 8);
    tsplit_qkv_kernel<<<dim3(96, 32, 8), tb>>>(wq, wk, wv, pwqkv_h, pwqkv_l);
    tsplit_mat_kernel<<<dim3(32, 32, 8), tb>>>(wproj, pwproj_h, pwproj_l, CDIM, CDIM);
    tsplit_mat_kernel<<<dim3(128, 32, 8), tb>>>(w1, pw1_h, pw1_l, CDIM, FF);
    tsplit_mat_kernel<<<dim3(32, 128, 8), tb>>>(w2, pw2_h, pw2_l, FF, CDIM);
    tsplit_mat_kernel<<<dim3(1000, 32, 1), tb>>>(wlm, pwlm_h, pwlm_l, CDIM, VOCAB);

    embed_kernel<<<NTOK, 256>>>(idx, tok, pos, px);

    for (int l = 0; l < NLAYER; l++) {
        ln_kernel<<<NTOK, 256>>>(px, ln1g + (size_t)l * CDIM, ln1b + (size_t)l * CDIM, phb);
        // QKV: weight-lo MMAs only for Q cols (<1024); output lo stored for Q only
        tgemm_kernel<<<dim3(32, 24), 256, SMEM_GEMM>>>(
            phb, pwqkv_h + (size_t)l * 3072 * 1024, pwqkv_l + (size_t)l * 3072 * 1024,
            CDIM, CDIM, nullptr, pqkvb_h, pqkvb_l, CDIM, CDIM, nullptr, nullptr, 0, 3 * CDIM);
        flash_kernel<<<dim3(16, BATCH * NHEAD), 128, SMEM_FLASH>>>(pqkvb_h, pqkvb_l, pob);
        tgemm_kernel<<<dim3(32, 8), 256, SMEM_GEMM>>>(
            pob, pwproj_h + (size_t)l * CDIM * CDIM, pwproj_l + (size_t)l * CDIM * CDIM,
            CDIM, CDIM, px, nullptr, nullptr, 0, 0, bproj + (size_t)l * CDIM, px, 0, CDIM);
        ln_kernel<<<NTOK, 256>>>(px, ln2g + (size_t)l * CDIM, ln2b + (size_t)l * CDIM, phb);
        // MLP up: single-weight (no Wl) — output is fp16-quantized anyway
        tgemm_kernel<<<dim3(32, 32), 256, SMEM_GEMM>>>(
            phb, pw1_h + (size_t)l * FF * CDIM, pw1_l + (size_t)l * FF * CDIM,
            CDIM, 0, nullptr, pffb, nullptr, 0, 0, b1 + (size_t)l * FF, nullptr, 1, FF);
        tgemm_kernel<<<dim3(32, 8), 256, SMEM_GEMM>>>(
            pffb, pw2_h + (size_t)l * CDIM * FF, pw2_l + (size_t)l * CDIM * FF,
            FF, CDIM, px, nullptr, nullptr, 0, 0, b2 + (size_t)l * CDIM, px, 0, CDIM);
    }
    ln_kernel<<<NTOK, 256>>>(px, lnfg, lnfb, phb);
    tgemm_kernel<<<dim3(32, 250), 256, SMEM_GEMM>>>(
        phb, pwlm_h, pwlm_l, CDIM, VOCAB, out, nullptr, nullptr, 0, 0, blm, nullptr, 0, VOCAB);
}

// round 12
// speedup vs baseline: 1.1098x; 1.0740x over previous
#include <cuda_runtime.h>
#include <cuda_fp16.h>
#include <cstdint>
#include <math.h>

#define BATCH 4
#define TLEN 1024
#define CDIM 1024
#define NHEAD 16
#define HDIM 64
#define NLAYER 8
#define VOCAB 32000
#define NTOK (BATCH * TLEN)
#define FF (4 * CDIM)

// ---------------- device scratch ----------------
__device__ float g_x[NTOK * CDIM];
__device__ unsigned short g_qkvb_h[NTOK * 3 * CDIM], g_qkvb_l[NTOK * CDIM];  // lo only for Q
__device__ unsigned short g_hb[NTOK * CDIM];
__device__ unsigned short g_ob[NTOK * CDIM];
__device__ unsigned short g_ffb[(size_t)NTOK * FF];
__device__ unsigned short g_wqkv_h[(size_t)NLAYER * 3 * CDIM * CDIM], g_wqkv_l[(size_t)NLAYER * 3 * CDIM * CDIM];
__device__ unsigned short g_wproj_h[(size_t)NLAYER * CDIM * CDIM], g_wproj_l[(size_t)NLAYER * CDIM * CDIM];
__device__ unsigned short g_w1_h[(size_t)NLAYER * FF * CDIM], g_w1_l[(size_t)NLAYER * FF * CDIM];
__device__ unsigned short g_w2_h[(size_t)NLAYER * CDIM * FF], g_w2_l[(size_t)NLAYER * CDIM * FF];
__device__ unsigned short g_wlm_h[(size_t)VOCAB * CDIM], g_wlm_l[(size_t)VOCAB * CDIM];

// ---------------- helpers ----------------
__device__ __forceinline__ uint32_t cvta_s(const void* p) {
    uint32_t a;
    asm("{ .reg .u64 t; cvta.to.shared.u64 t, %1; cvt.u32.u64 %0, t; }" : "=r"(a) : "l"(p));
    return a;
}
#define CP_ASYNC16(dst, src) \
    asm volatile("cp.async.cg.shared.global [%0], [%1], 16;" :: "r"(dst), "l"(src))
#define CP_COMMIT() asm volatile("cp.async.commit_group;" ::: "memory")
#define CP_WAIT(n)  asm volatile("cp.async.wait_group %0;" :: "n"(n) : "memory")

__device__ __forceinline__ void ldm_x4(uint32_t* r, uint32_t addr) {
    asm volatile("ldmatrix.sync.aligned.m8n8.x4.shared.b16 {%0,%1,%2,%3}, [%4];"
                 : "=r"(r[0]), "=r"(r[1]), "=r"(r[2]), "=r"(r[3]) : "r"(addr));
}
__device__ __forceinline__ void ldm_x2(uint32_t* r, uint32_t addr) {
    asm volatile("ldmatrix.sync.aligned.m8n8.x2.shared.b16 {%0,%1}, [%2];"
                 : "=r"(r[0]), "=r"(r[1]) : "r"(addr));
}
__device__ __forceinline__ void ldm_x2t(uint32_t* r, uint32_t addr) {
    asm volatile("ldmatrix.sync.aligned.m8n8.x2.trans.shared.b16 {%0,%1}, [%2];"
                 : "=r"(r[0]), "=r"(r[1]) : "r"(addr));
}
__device__ __forceinline__ void mma_f16(float* d, const uint32_t* a, const uint32_t* b) {
    asm volatile(
        "mma.sync.aligned.m16n8k16.row.col.f32.f16.f16.f32 "
        "{%0,%1,%2,%3}, {%4,%5,%6,%7}, {%8,%9}, {%0,%1,%2,%3};"
        : "+f"(d[0]), "+f"(d[1]), "+f"(d[2]), "+f"(d[3])
        : "r"(a[0]), "r"(a[1]), "r"(a[2]), "r"(a[3]), "r"(b[0]), "r"(b[1]));
}
__device__ __forceinline__ void hsplit(float v, unsigned short& h, unsigned short& l) {
    __half hb = __float2half_rn(v);
    __half lb = __float2half_rn(v - __half2float(hb));
    h = __half_as_ushort(hb);
    l = __half_as_ushort(lb);
}
__device__ __forceinline__ unsigned short h1(float v) {
    return __half_as_ushort(__float2half_rn(v));
}
__device__ __forceinline__ void pack2h(float a, float b, uint32_t& hi, uint32_t& lo) {
    unsigned short h0, l0, hh1, l1;
    hsplit(a, h0, l0);
    hsplit(b, hh1, l1);
    hi = (uint32_t)h0 | ((uint32_t)hh1 << 16);
    lo = (uint32_t)l0 | ((uint32_t)l1 << 16);
}

// ---------------- weight prep (transpose + fp16 hi/lo split) ----------------
__global__ void tsplit_qkv_kernel(const float* __restrict__ wq, const float* __restrict__ wk,
                                  const float* __restrict__ wv,
                                  unsigned short* __restrict__ dh, unsigned short* __restrict__ dl) {
    __shared__ float t[32][33];
    int n0 = blockIdx.x * 32, k0 = blockIdx.y * 32, l = blockIdx.z;
    int sel = n0 >> 10;
    const float* src = sel == 0 ? wq : (sel == 1 ? wk : wv);
    int within = n0 & 1023;
    int h = within >> 6, d0 = within & 63;
    const float* sp = src + ((size_t)(l * 16 + h) * 1024 + k0) * 64 + d0;
    int tx = threadIdx.x, ty = threadIdx.y;
    #pragma unroll
    for (int i = 0; i < 4; i++) t[ty + i * 8][tx] = sp[(size_t)(ty + i * 8) * 64 + tx];
    __syncthreads();
    size_t ob = (size_t)l * 3072 * 1024;
    #pragma unroll
    for (int i = 0; i < 4; i++) {
        int n = n0 + ty + i * 8, k = k0 + tx;
        unsigned short hh, ll;
        hsplit(t[tx][ty + i * 8], hh, ll);
        dh[ob + (size_t)n * 1024 + k] = hh;
        dl[ob + (size_t)n * 1024 + k] = ll;
    }
}
__global__ void tsplit_mat_kernel(const float* __restrict__ src,
                                  unsigned short* __restrict__ dh, unsigned short* __restrict__ dl,
                                  int K, int N) {
    __shared__ float t[32][33];
    int n0 = blockIdx.x * 32, k0 = blockIdx.y * 32;
    size_t l = blockIdx.z;
    const float* sp = src + l * (size_t)K * N;
    int tx = threadIdx.x, ty = threadIdx.y;
    #pragma unroll
    for (int i = 0; i < 4; i++) t[ty + i * 8][tx] = sp[(size_t)(k0 + ty + i * 8) * N + n0 + tx];
    __syncthreads();
    size_t ob = l * (size_t)K * N;
    #pragma unroll
    for (int i = 0; i < 4; i++) {
        int n = n0 + ty + i * 8, k = k0 + tx;
        unsigned short hh, ll;
        hsplit(t[tx][ty + i * 8], hh, ll);
        dh[ob + (size_t)n * K + k] = hh;
        dl[ob + (size_t)n * K + k] = ll;
    }
}

// ---------------- embed ----------------
__global__ void embed_kernel(const int* __restrict__ idx, const float* __restrict__ tok,
                             const float* __restrict__ pos, float* __restrict__ x) {
    int row = blockIdx.x;
    int t = row & (TLEN - 1);
    int token = idx[row];
    const float4* te = (const float4*)(tok + (size_t)token * CDIM);
    const float4* pe = (const float4*)(pos + (size_t)t * CDIM);
    float4* xo = (float4*)(x + (size_t)row * CDIM);
    int i = threadIdx.x;
    float4 a = te[i], b = pe[i];
    a.x += b.x; a.y += b.y; a.z += b.z; a.w += b.w;
    xo[i] = a;
}

// ---------------- LayerNorm -> single fp16 ----------------
__global__ void ln_kernel(const float* __restrict__ x, const float* __restrict__ g,
                          const float* __restrict__ b, unsigned short* __restrict__ oh) {
    int row = blockIdx.x;
    int tid = threadIdx.x;
    float4 v = ((const float4*)(x + (size_t)row * CDIM))[tid];
    float s = v.x + v.y + v.z + v.w;
    float ss = v.x * v.x + v.y * v.y + v.z * v.z + v.w * v.w;
    #pragma unroll
    for (int o = 16; o > 0; o >>= 1) {
        s += __shfl_xor_sync(0xffffffffu, s, o);
        ss += __shfl_xor_sync(0xffffffffu, ss, o);
    }
    __shared__ float sm[8], sm2[8];
    int w = tid >> 5, lane = tid & 31;
    if (lane == 0) { sm[w] = s; sm2[w] = ss; }
    __syncthreads();
    s = 0.f; ss = 0.f;
    #pragma unroll
    for (int i = 0; i < 8; i++) { s += sm[i]; ss += sm2[i]; }
    float mean = s * (1.0f / CDIM);
    float var = ss * (1.0f / CDIM) - mean * mean;
    float rstd = rsqrtf(var + 1e-5f);
    float4 gv = ((const float4*)g)[tid];
    float4 bv = ((const float4*)b)[tid];
    ushort4 hv;
    hv.x = h1((v.x - mean) * rstd * gv.x + bv.x);
    hv.y = h1((v.y - mean) * rstd * gv.y + bv.y);
    hv.z = h1((v.z - mean) * rstd * gv.z + bv.z);
    hv.w = h1((v.w - mean) * rstd * gv.w + bv.w);
    *(ushort4*)(oh + (size_t)row * CDIM + tid * 4) = hv;
}

// ---------------- HMMA GEMM: D[M,N] = A[M,K] * (Wh[+Wl])[N,K]^T ----------------
// A single fp16. Wl applied only for output cols < nlo (uniform per block).
// 128x128 tile, BK=32, 8 warps, warp tile 64x32, 2-stage cp.async, 2 CTAs/SM.
// B loads x4-folded: one ldmatrix.x4 covers 16 N-rows (two n-subtiles).
#define RS 80
#define ARR_BYTES (128 * RS)
#define STAGE_BYTES (3 * ARR_BYTES)       // 30720 (A, Bh, Bl)
#define SMEM_GEMM (2 * STAGE_BYTES)       // 61440

__device__ __forceinline__ void gemm_load_stage(
    const unsigned short* __restrict__ A,
    const unsigned short* __restrict__ Bh, const unsigned short* __restrict__ Bl,
    int K, int m0, int n0, int k0, uint32_t smbase, int buf, int tid, int use_lo) {
    uint32_t sb = smbase + buf * STAGE_BYTES;
    #pragma unroll
    for (int it = 0; it < 6; it++) {
        int e = tid + it * 256;
        int arr = e >> 9;                 // 0=A 1=Bh 2=Bl
        if (arr == 2 && !use_lo) continue;
        int idx = e & 511;
        int row = idx >> 2;
        int ch = idx & 3;
        const unsigned short* src = arr == 0 ? A : arr == 1 ? Bh : Bl;
        int r0 = (arr == 0) ? m0 : n0;
        const unsigned short* g = src + (size_t)(r0 + row) * K + k0 + ch * 8;
        CP_ASYNC16(sb + arr * ARR_BYTES + row * RS + ch * 16, g);
    }
}

__global__ __launch_bounds__(256)
void tgemm_kernel(const unsigned short* __restrict__ A,
                  const unsigned short* __restrict__ Bh, const unsigned short* __restrict__ Bl,
                  int K, int nlo,
                  float* __restrict__ Cf, unsigned short* __restrict__ Ch,
                  unsigned short* __restrict__ Cl, int locols, int ldlo,
                  const float* __restrict__ bias, const float* __restrict__ res,
                  int relu, int ldc) {
    extern __shared__ char smem[];
    uint32_t smbase = cvta_s(smem);
    int tid = threadIdx.x;
    int m0 = blockIdx.x * 128, n0 = blockIdx.y * 128;
    int use_lo = (n0 < nlo);
    int warp = tid >> 5, lane = tid & 31;
    int wm = (warp >> 2) * 64;
    int wn = (warp & 3) * 32;
    int arow = lane & 15;
    uint32_t asel = (uint32_t)(lane >> 4) << 4;
    // x4-folded B: row within 16-row group, k-half by bit3
    int bnoff = ((lane >> 4) & 1) * 8 + (lane & 7);
    uint32_t bkoff = (uint32_t)((lane >> 3) & 1) << 4;

    float acc[4][4][4];
    #pragma unroll
    for (int i = 0; i < 4; i++)
        #pragma unroll
        for (int j = 0; j < 4; j++)
            #pragma unroll
            for (int q = 0; q < 4; q++) acc[i][j][q] = 0.f;

    int NS = K >> 5;
    gemm_load_stage(A, Bh, Bl, K, m0, n0, 0, smbase, 0, tid, use_lo);
    CP_COMMIT();
    if (NS > 1) {
        gemm_load_stage(A, Bh, Bl, K, m0, n0, 32, smbase, 1, tid, use_lo);
        CP_COMMIT();
    }

    for (int s = 0; s < NS; s++) {
        if (s + 1 < NS) { CP_WAIT(1); } else { CP_WAIT(0); }
        __syncthreads();
        int buf = s & 1;
        uint32_t sb = smbase + (uint32_t)buf * STAGE_BYTES;
        uint32_t sA = sb, sBh = sb + ARR_BYTES;
        #pragma unroll
        for (int kk = 0; kk < 2; kk++) {
            uint32_t kb = kk * 32;
            uint32_t af[4][4];
            #pragma unroll
            for (int i = 0; i < 4; i++) {
                uint32_t ra = sA + (uint32_t)(wm + i * 16 + arow) * RS + kb + asel;
                ldm_x4(af[i], ra);
            }
            #pragma unroll
            for (int j2 = 0; j2 < 2; j2++) {
                uint32_t bh4[4], bl4[4];
                uint32_t rb = sBh + (uint32_t)(wn + j2 * 16 + bnoff) * RS + kb + bkoff;
                ldm_x4(bh4, rb);
                if (use_lo) ldm_x4(bl4, rb + ARR_BYTES);
                #pragma unroll
                for (int i = 0; i < 4; i++) {
                    mma_f16(acc[i][2 * j2],     af[i], bh4);
                    mma_f16(acc[i][2 * j2 + 1], af[i], bh4 + 2);
                    if (use_lo) {
                        mma_f16(acc[i][2 * j2],     af[i], bl4);
                        mma_f16(acc[i][2 * j2 + 1], af[i], bl4 + 2);
                    }
                }
            }
        }
        __syncthreads();
        if (s + 2 < NS) {
            gemm_load_stage(A, Bh, Bl, K, m0, n0, (s + 2) << 5, smbase, buf, tid, use_lo);
            CP_COMMIT();
        }
    }

    int qr = lane >> 2;
    int qc = (lane & 3) * 2;
    #pragma unroll
    for (int i = 0; i < 4; i++) {
        #pragma unroll
        for (int j = 0; j < 4; j++) {
            int col = n0 + wn + j * 8 + qc;
            #pragma unroll
            for (int half = 0; half < 2; half++) {
                int row = m0 + wm + i * 16 + qr + half * 8;
                float v0 = acc[i][j][half * 2 + 0];
                float v1 = acc[i][j][half * 2 + 1];
                if (bias) {
                    float2 bv = *(const float2*)(bias + col);
                    v0 += bv.x; v1 += bv.y;
                }
                size_t base = (size_t)row * ldc + col;
                if (res) {
                    float2 e = *(const float2*)(res + base);
                    v0 += e.x; v1 += e.y;
                }
                if (relu) { v0 = fmaxf(v0, 0.f); v1 = fmaxf(v1, 0.f); }
                if (Cf) { float2 o = {v0, v1}; *(float2*)(Cf + base) = o; }
                if (Ch) {
                    __half hv0 = __float2half_rn(v0);
                    __half hv1 = __float2half_rn(v1);
                    ushort2 hv;
                    hv.x = __half_as_ushort(hv0);
                    hv.y = __half_as_ushort(hv1);
                    *(ushort2*)(Ch + base) = hv;
                    if (Cl && col < locols) {
                        ushort2 lv;
                        lv.x = h1(v0 - __half2float(hv0));
                        lv.y = h1(v1 - __half2float(hv1));
                        *(ushort2*)(Cl + (size_t)row * ldlo + col) = lv;
                    }
                }
            }
        }
    }
}

// ---------------- fused flash attention (64-row tiles, 128 thr) ----------------
// Q split fp16 (Qh,Ql), K single (x4-folded loads), V single, P split fp16.
#define FRS 144
#define FARR (64 * FRS)                   // 9216
#define FKV_STAGE (2 * FARR)              // 18432 (K, V single)
#define SMEM_FLASH (2 * FARR + 2 * FKV_STAGE)  // 55296

__device__ __forceinline__ void flash_load_q(
    const unsigned short* __restrict__ qh, const unsigned short* __restrict__ ql,
    int rowbase, int colbase, uint32_t smbase, int tid) {
    #pragma unroll
    for (int it = 0; it < 8; it++) {
        int e = tid + it * 128;
        int arr = e >> 9;                 // 0=Qh 1=Ql
        int idx = e & 511;
        int row = idx >> 3, ch = idx & 7;
        const unsigned short* g;
        if (arr == 0)
            g = qh + (size_t)(rowbase + row) * (3 * CDIM) + colbase + ch * 8;
        else
            g = ql + (size_t)(rowbase + row) * CDIM + colbase + ch * 8;  // lo: Q-only, ld=CDIM
        CP_ASYNC16(smbase + arr * FARR + row * FRS + ch * 16, g);
    }
}
__device__ __forceinline__ void flash_load_kv(
    const unsigned short* __restrict__ qh,
    int rowbase, int kcol, int vcol, uint32_t sb, int tid) {
    #pragma unroll
    for (int it = 0; it < 8; it++) {
        int e = tid + it * 128;
        int arr = e >> 9;                 // 0=K 1=V
        int idx = e & 511;
        int row = idx >> 3, ch = idx & 7;
        int col = (arr == 0) ? kcol : vcol;
        const unsigned short* g = qh + (size_t)(rowbase + row) * (3 * CDIM) + col + ch * 8;
        CP_ASYNC16(sb + arr * FARR + row * FRS + ch * 16, g);
    }
}

__global__ __launch_bounds__(128)
void flash_kernel(const unsigned short* __restrict__ qh, const unsigned short* __restrict__ ql,
                  unsigned short* __restrict__ ob) {
    extern __shared__ char smem[];
    uint32_t smbase = cvta_s(smem);
    int tid = threadIdx.x;
    int tt = (int)gridDim.x - 1 - (int)blockIdx.x;
    int bh = blockIdx.y;
    int b = bh >> 4, h = bh & 15;
    int t0 = tt * 64;
    int qrowbase = b * TLEN + t0;
    int qcol = h * HDIM;
    int kcol = CDIM + h * HDIM;
    int vcol = 2 * CDIM + h * HDIM;

    int warp = tid >> 5, lane = tid & 31;
    int wm = warp * 16;
    int arow = lane & 15;
    uint32_t asel = (uint32_t)(lane >> 4) << 4;
    int ln16 = lane & 15;
    // x4-folded K loads
    int bnoff = ((lane >> 4) & 1) * 8 + (lane & 7);
    uint32_t bkoff = (uint32_t)((lane >> 3) & 1) << 4;
    int qr = lane >> 2;
    int qc = (lane & 3) * 2;

    float O[8][4];
    #pragma unroll
    for (int j = 0; j < 8; j++)
        #pragma unroll
        for (int q = 0; q < 4; q++) O[j][q] = 0.f;
    float m0r = -1e30f, m1r = -1e30f, l0 = 0.f, l1 = 0.f;

    int NS = tt + 1;
    uint32_t kvbase = smbase + 2 * FARR;

    flash_load_q(qh, ql, qrowbase, qcol, smbase, tid);
    flash_load_kv(qh, b * TLEN, kcol, vcol, kvbase, tid);
    CP_COMMIT();
    if (NS > 1) {
        flash_load_kv(qh, b * TLEN + 64, kcol, vcol, kvbase + FKV_STAGE, tid);
        CP_COMMIT();
    }

    for (int st = 0; st < NS; st++) {
        if (st + 1 < NS) { CP_WAIT(1); } else { CP_WAIT(0); }
        __syncthreads();
        uint32_t sKV = kvbase + (st & 1) * FKV_STAGE;
        uint32_t sK = sKV, sV = sKV + FARR;

        float S[8][4];
        #pragma unroll
        for (int j = 0; j < 8; j++)
            #pragma unroll
            for (int q = 0; q < 4; q++) S[j][q] = 0.f;
        #pragma unroll
        for (int d = 0; d < 4; d++) {
            uint32_t kb = d * 32;
            uint32_t ah[4], al[4];
            uint32_t ra = smbase + (uint32_t)(wm + arow) * FRS + kb + asel;
            ldm_x4(ah, ra);
            ldm_x4(al, ra + FARR);
            #pragma unroll
            for (int j2 = 0; j2 < 4; j2++) {
                uint32_t bf4[4];
                uint32_t rb = sK + (uint32_t)(j2 * 16 + bnoff) * FRS + kb + bkoff;
                ldm_x4(bf4, rb);
                mma_f16(S[2 * j2],     ah, bf4);
                mma_f16(S[2 * j2],     al, bf4);
                mma_f16(S[2 * j2 + 1], ah, bf4 + 2);
                mma_f16(S[2 * j2 + 1], al, bf4 + 2);
            }
        }
        if (st == tt) {
            int r0 = wm + qr, r1 = wm + qr + 8;
            #pragma unroll
            for (int j = 0; j < 8; j++) {
                int c0 = j * 8 + qc;
                S[j][0] = (c0     > r0) ? -1e30f : S[j][0] * 0.125f;
                S[j][1] = (c0 + 1 > r0) ? -1e30f : S[j][1] * 0.125f;
                S[j][2] = (c0     > r1) ? -1e30f : S[j][2] * 0.125f;
                S[j][3] = (c0 + 1 > r1) ? -1e30f : S[j][3] * 0.125f;
            }
        } else {
            #pragma unroll
            for (int j = 0; j < 8; j++)
                #pragma unroll
                for (int q = 0; q < 4; q++) S[j][q] *= 0.125f;
        }
        float mx0 = -1e30f, mx1 = -1e30f;
        #pragma unroll
        for (int j = 0; j < 8; j++) {
            mx0 = fmaxf(mx0, fmaxf(S[j][0], S[j][1]));
            mx1 = fmaxf(mx1, fmaxf(S[j][2], S[j][3]));
        }
        mx0 = fmaxf(mx0, __shfl_xor_sync(0xffffffffu, mx0, 1));
        mx0 = fmaxf(mx0, __shfl_xor_sync(0xffffffffu, mx0, 2));
        mx1 = fmaxf(mx1, __shfl_xor_sync(0xffffffffu, mx1, 1));
        mx1 = fmaxf(mx1, __shfl_xor_sync(0xffffffffu, mx1, 2));
        float mn0 = fmaxf(m0r, mx0), mn1 = fmaxf(m1r, mx1);
        float c0 = __expf(m0r - mn0), c1 = __expf(m1r - mn1);
        float rs0 = 0.f, rs1 = 0.f;
        #pragma unroll
        for (int j = 0; j < 8; j++) {
            S[j][0] = __expf(S[j][0] - mn0);
            S[j][1] = __expf(S[j][1] - mn0);
            S[j][2] = __expf(S[j][2] - mn1);
            S[j][3] = __expf(S[j][3] - mn1);
            rs0 += S[j][0] + S[j][1];
            rs1 += S[j][2] + S[j][3];
        }
        rs0 += __shfl_xor_sync(0xffffffffu, rs0, 1);
        rs0 += __shfl_xor_sync(0xffffffffu, rs0, 2);
        rs1 += __shfl_xor_sync(0xffffffffu, rs1, 1);
        rs1 += __shfl_xor_sync(0xffffffffu, rs1, 2);
        l0 = l0 * c0 + rs0;
        l1 = l1 * c1 + rs1;
        m0r = mn0; m1r = mn1;
        #pragma unroll
        for (int j = 0; j < 8; j++) {
            O[j][0] *= c0; O[j][1] *= c0;
            O[j][2] *= c1; O[j][3] *= c1;
        }
        #pragma unroll
        for (int kk = 0; kk < 4; kk++) {
            int j0 = 2 * kk, j1 = 2 * kk + 1;
            uint32_t pah[4], pal[4];
            pack2h(S[j0][0], S[j0][1], pah[0], pal[0]);
            pack2h(S[j0][2], S[j0][3], pah[1], pal[1]);
            pack2h(S[j1][0], S[j1][1], pah[2], pal[2]);
            pack2h(S[j1][2], S[j1][3], pah[3], pal[3]);
            uint32_t vrow = (uint32_t)(kk * 16 + (ln16 & 7) + ((ln16 >> 3) & 1) * 8);
            #pragma unroll
            for (int jd = 0; jd < 8; jd++) {
                uint32_t vf[2];
                uint32_t rv = sV + vrow * FRS + jd * 16;
                ldm_x2t(vf, rv);
                mma_f16(O[jd], pah, vf);
                mma_f16(O[jd], pal, vf);
            }
        }
        __syncthreads();
        if (st + 2 < NS) {
            flash_load_kv(qh, b * TLEN + (st + 2) * 64, kcol, vcol,
                          kvbase + (st & 1) * FKV_STAGE, tid);
            CP_COMMIT();
        }
    }

    float inv0 = 1.f / l0, inv1 = 1.f / l1;
    int row0 = b * TLEN + t0 + wm + qr;
    #pragma unroll
    for (int jd = 0; jd < 8; jd++) {
        int col = qcol + jd * 8 + qc;
        ushort2 hv;
        hv.x = h1(O[jd][0] * inv0);
        hv.y = h1(O[jd][1] * inv0);
        *(ushort2*)(ob + (size_t)row0 * CDIM + col) = hv;
        hv.x = h1(O[jd][2] * inv1);
        hv.y = h1(O[jd][3] * inv1);
        *(ushort2*)(ob + (size_t)(row0 + 8) * CDIM + col) = hv;
    }
}

// ---------------- host ----------------
extern "C" void kernel_launch(void* const* d_in, const int* in_sizes, int n_in,
                              void* d_out, int out_size) {
    const int* idx = (const int*)d_in[0];
    const float* tok = (const float*)d_in[1];
    const float* pos = (const float*)d_in[2];
    const float* wq = (const float*)d_in[3];
    const float* wk = (const float*)d_in[4];
    const float* wv = (const float*)d_in[5];
    const float* wproj = (const float*)d_in[6];
    const float* bproj = (const float*)d_in[7];
    const float* ln1g = (const float*)d_in[8];
    const float* ln1b = (const float*)d_in[9];
    const float* ln2g = (const float*)d_in[10];
    const float* ln2b = (const float*)d_in[11];
    const float* w1 = (const float*)d_in[12];
    const float* b1 = (const float*)d_in[13];
    const float* w2 = (const float*)d_in[14];
    const float* b2 = (const float*)d_in[15];
    const float* lnfg = (const float*)d_in[16];
    const float* lnfb = (const float*)d_in[17];
    const float* wlm = (const float*)d_in[18];
    const float* blm = (const float*)d_in[19];
    float* out = (float*)d_out;

    float* px;
    unsigned short *pqkvb_h, *pqkvb_l, *phb, *pob, *pffb;
    unsigned short *pwqkv_h, *pwqkv_l, *pwproj_h, *pwproj_l;
    unsigned short *pw1_h, *pw1_l, *pw2_h, *pw2_l, *pwlm_h, *pwlm_l;
    cudaGetSymbolAddress((void**)&px, g_x);
    cudaGetSymbolAddress((void**)&pqkvb_h, g_qkvb_h);
    cudaGetSymbolAddress((void**)&pqkvb_l, g_qkvb_l);
    cudaGetSymbolAddress((void**)&phb, g_hb);
    cudaGetSymbolAddress((void**)&pob, g_ob);
    cudaGetSymbolAddress((void**)&pffb, g_ffb);
    cudaGetSymbolAddress((void**)&pwqkv_h, g_wqkv_h);
    cudaGetSymbolAddress((void**)&pwqkv_l, g_wqkv_l);
    cudaGetSymbolAddress((void**)&pwproj_h, g_wproj_h);
    cudaGetSymbolAddress((void**)&pwproj_l, g_wproj_l);
    cudaGetSymbolAddress((void**)&pw1_h, g_w1_h);
    cudaGetSymbolAddress((void**)&pw1_l, g_w1_l);
    cudaGetSymbolAddress((void**)&pw2_h, g_w2_h);
    cudaGetSymbolAddress((void**)&pw2_l, g_w2_l);
    cudaGetSymbolAddress((void**)&pwlm_h, g_wlm_h);
    cudaGetSymbolAddress((void**)&pwlm_l, g_wlm_l);

    cudaFuncSetAttribute(tgemm_kernel, cudaFuncAttributeMaxDynamicSharedMemorySize, SMEM_GEMM);
    cudaFuncSetAttribute(flash_kernel, cudaFuncAttributeMaxDynamicSharedMemorySize, SMEM_FLASH);

    dim3 tb(32, 8);
    tsplit_qkv_kernel<<<dim3(96, 32, 8), tb>>>(wq, wk, wv, pwqkv_h, pwqkv_l);
    tsplit_mat_kernel<<<dim3(32, 32, 8), tb>>>(wproj, pwproj_h, pwproj_l, CDIM, CDIM);
    tsplit_mat_kernel<<<dim3(128, 32, 8), tb>>>(w1, pw1_h, pw1_l, CDIM, FF);
    tsplit_mat_kernel<<<dim3(32, 128, 8), tb>>>(w2, pw2_h, pw2_l, FF, CDIM);
    tsplit_mat_kernel<<<dim3(1000, 32, 1), tb>>>(wlm, pwlm_h, pwlm_l, CDIM, VOCAB);

    embed_kernel<<<NTOK, 256>>>(idx, tok, pos, px);

    for (int l = 0; l < NLAYER; l++) {
        ln_kernel<<<NTOK, 256>>>(px, ln1g + (size_t)l * CDIM, ln1b + (size_t)l * CDIM, phb);
        tgemm_kernel<<<dim3(32, 24), 256, SMEM_GEMM>>>(
            phb, pwqkv_h + (size_t)l * 3072 * 1024, pwqkv_l + (size_t)l * 3072 * 1024,
            CDIM, CDIM, nullptr, pqkvb_h, pqkvb_l, CDIM, CDIM, nullptr, nullptr, 0, 3 * CDIM);
        flash_kernel<<<dim3(16, BATCH * NHEAD), 128, SMEM_FLASH>>>(pqkvb_h, pqkvb_l, pob);
        tgemm_kernel<<<dim3(32, 8), 256, SMEM_GEMM>>>(
            pob, pwproj_h + (size_t)l * CDIM * CDIM, pwproj_l + (size_t)l * CDIM * CDIM,
            CDIM, CDIM, px, nullptr, nullptr, 0, 0, bproj + (size_t)l * CDIM, px, 0, CDIM);
        ln_kernel<<<NTOK, 256>>>(px, ln2g + (size_t)l * CDIM, ln2b + (size_t)l * CDIM, phb);
        tgemm_kernel<<<dim3(32, 32), 256, SMEM_GEMM>>>(
            phb, pw1_h + (size_t)l * FF * CDIM, pw1_l + (size_t)l * FF * CDIM,
            CDIM, 0, nullptr, pffb, nullptr, 0, 0, b1 + (size_t)l * FF, nullptr, 1, FF);
        tgemm_kernel<<<dim3(32, 8), 256, SMEM_GEMM>>>(
            pffb, pw2_h + (size_t)l * CDIM * FF, pw2_l + (size_t)l * CDIM * FF,
            FF, CDIM, px, nullptr, nullptr, 0, 0, b2 + (size_t)l * CDIM, px, 0, CDIM);
    }
    ln_kernel<<<NTOK, 256>>>(px, lnfg, lnfb, phb);
    tgemm_kernel<<<dim3(32, 250), 256, SMEM_GEMM>>>(
        phb, pwlm_h, pwlm_l, CDIM, VOCAB, out, nullptr, nullptr, 0, 0, blm, nullptr, 0, VOCAB);
}

// round 13
// speedup vs baseline: 1.1766x; 1.0602x over previous
#include <cuda_runtime.h>
#include <cuda_fp16.h>
#include <cstdint>
#include <math.h>

#define BATCH 4
#define TLEN 1024
#define CDIM 1024
#define NHEAD 16
#define HDIM 64
#define NLAYER 8
#define VOCAB 32000
#define NTOK (BATCH * TLEN)
#define FF (4 * CDIM)

// ---------------- device scratch ----------------
__device__ float g_x[NTOK * CDIM];
__device__ unsigned short g_qkvb_h[NTOK * 3 * CDIM], g_qkvb_l[NTOK * CDIM];  // lo only for Q
__device__ unsigned short g_hb[NTOK * CDIM];
__device__ unsigned short g_ob[NTOK * CDIM];
__device__ unsigned short g_ffb[(size_t)NTOK * FF];
__device__ unsigned short g_wqkv_h[(size_t)NLAYER * 3 * CDIM * CDIM], g_wqkv_l[(size_t)NLAYER * 3 * CDIM * CDIM];
__device__ unsigned short g_wproj_h[(size_t)NLAYER * CDIM * CDIM], g_wproj_l[(size_t)NLAYER * CDIM * CDIM];
__device__ unsigned short g_w1_h[(size_t)NLAYER * FF * CDIM], g_w1_l[(size_t)NLAYER * FF * CDIM];
__device__ unsigned short g_w2_h[(size_t)NLAYER * CDIM * FF], g_w2_l[(size_t)NLAYER * CDIM * FF];
__device__ unsigned short g_wlm_h[(size_t)VOCAB * CDIM], g_wlm_l[(size_t)VOCAB * CDIM];

// ---------------- helpers ----------------
__device__ __forceinline__ uint32_t cvta_s(const void* p) {
    uint32_t a;
    asm("{ .reg .u64 t; cvta.to.shared.u64 t, %1; cvt.u32.u64 %0, t; }" : "=r"(a) : "l"(p));
    return a;
}
#define CP_ASYNC16(dst, src) \
    asm volatile("cp.async.cg.shared.global [%0], [%1], 16;" :: "r"(dst), "l"(src))
#define CP_COMMIT() asm volatile("cp.async.commit_group;" ::: "memory")
#define CP_WAIT(n)  asm volatile("cp.async.wait_group %0;" :: "n"(n) : "memory")

__device__ __forceinline__ void ldm_x4(uint32_t* r, uint32_t addr) {
    asm volatile("ldmatrix.sync.aligned.m8n8.x4.shared.b16 {%0,%1,%2,%3}, [%4];"
                 : "=r"(r[0]), "=r"(r[1]), "=r"(r[2]), "=r"(r[3]) : "r"(addr));
}
__device__ __forceinline__ void ldm_x2(uint32_t* r, uint32_t addr) {
    asm volatile("ldmatrix.sync.aligned.m8n8.x2.shared.b16 {%0,%1}, [%2];"
                 : "=r"(r[0]), "=r"(r[1]) : "r"(addr));
}
__device__ __forceinline__ void ldm_x4t(uint32_t* r, uint32_t addr) {
    asm volatile("ldmatrix.sync.aligned.m8n8.x4.trans.shared.b16 {%0,%1,%2,%3}, [%4];"
                 : "=r"(r[0]), "=r"(r[1]), "=r"(r[2]), "=r"(r[3]) : "r"(addr));
}
__device__ __forceinline__ void mma_f16(float* d, const uint32_t* a, const uint32_t* b) {
    asm volatile(
        "mma.sync.aligned.m16n8k16.row.col.f32.f16.f16.f32 "
        "{%0,%1,%2,%3}, {%4,%5,%6,%7}, {%8,%9}, {%0,%1,%2,%3};"
        : "+f"(d[0]), "+f"(d[1]), "+f"(d[2]), "+f"(d[3])
        : "r"(a[0]), "r"(a[1]), "r"(a[2]), "r"(a[3]), "r"(b[0]), "r"(b[1]));
}
__device__ __forceinline__ void hsplit(float v, unsigned short& h, unsigned short& l) {
    __half hb = __float2half_rn(v);
    __half lb = __float2half_rn(v - __half2float(hb));
    h = __half_as_ushort(hb);
    l = __half_as_ushort(lb);
}
__device__ __forceinline__ unsigned short h1(float v) {
    return __half_as_ushort(__float2half_rn(v));
}
__device__ __forceinline__ void pack2h(float a, float b, uint32_t& hi, uint32_t& lo) {
    unsigned short h0, l0, hh1, l1;
    hsplit(a, h0, l0);
    hsplit(b, hh1, l1);
    hi = (uint32_t)h0 | ((uint32_t)hh1 << 16);
    lo = (uint32_t)l0 | ((uint32_t)l1 << 16);
}

// ---------------- weight prep (transpose + fp16 hi/lo split) ----------------
__global__ void tsplit_qkv_kernel(const float* __restrict__ wq, const float* __restrict__ wk,
                                  const float* __restrict__ wv,
                                  unsigned short* __restrict__ dh, unsigned short* __restrict__ dl) {
    __shared__ float t[32][33];
    int n0 = blockIdx.x * 32, k0 = blockIdx.y * 32, l = blockIdx.z;
    int sel = n0 >> 10;
    const float* src = sel == 0 ? wq : (sel == 1 ? wk : wv);
    int within = n0 & 1023;
    int h = within >> 6, d0 = within & 63;
    const float* sp = src + ((size_t)(l * 16 + h) * 1024 + k0) * 64 + d0;
    int tx = threadIdx.x, ty = threadIdx.y;
    #pragma unroll
    for (int i = 0; i < 4; i++) t[ty + i * 8][tx] = sp[(size_t)(ty + i * 8) * 64 + tx];
    __syncthreads();
    size_t ob = (size_t)l * 3072 * 1024;
    #pragma unroll
    for (int i = 0; i < 4; i++) {
        int n = n0 + ty + i * 8, k = k0 + tx;
        unsigned short hh, ll;
        hsplit(t[tx][ty + i * 8], hh, ll);
        dh[ob + (size_t)n * 1024 + k] = hh;
        dl[ob + (size_t)n * 1024 + k] = ll;
    }
}
__global__ void tsplit_mat_kernel(const float* __restrict__ src,
                                  unsigned short* __restrict__ dh, unsigned short* __restrict__ dl,
                                  int K, int N) {
    __shared__ float t[32][33];
    int n0 = blockIdx.x * 32, k0 = blockIdx.y * 32;
    size_t l = blockIdx.z;
    const float* sp = src + l * (size_t)K * N;
    int tx = threadIdx.x, ty = threadIdx.y;
    #pragma unroll
    for (int i = 0; i < 4; i++) t[ty + i * 8][tx] = sp[(size_t)(k0 + ty + i * 8) * N + n0 + tx];
    __syncthreads();
    size_t ob = l * (size_t)K * N;
    #pragma unroll
    for (int i = 0; i < 4; i++) {
        int n = n0 + ty + i * 8, k = k0 + tx;
        unsigned short hh, ll;
        hsplit(t[tx][ty + i * 8], hh, ll);
        dh[ob + (size_t)n * K + k] = hh;
        dl[ob + (size_t)n * K + k] = ll;
    }
}

// ---------------- embed ----------------
__global__ void embed_kernel(const int* __restrict__ idx, const float* __restrict__ tok,
                             const float* __restrict__ pos, float* __restrict__ x) {
    int row = blockIdx.x;
    int t = row & (TLEN - 1);
    int token = idx[row];
    const float4* te = (const float4*)(tok + (size_t)token * CDIM);
    const float4* pe = (const float4*)(pos + (size_t)t * CDIM);
    float4* xo = (float4*)(x + (size_t)row * CDIM);
    int i = threadIdx.x;
    float4 a = te[i], b = pe[i];
    a.x += b.x; a.y += b.y; a.z += b.z; a.w += b.w;
    xo[i] = a;
}

// ---------------- LayerNorm -> single fp16 ----------------
__global__ void ln_kernel(const float* __restrict__ x, const float* __restrict__ g,
                          const float* __restrict__ b, unsigned short* __restrict__ oh) {
    int row = blockIdx.x;
    int tid = threadIdx.x;
    float4 v = ((const float4*)(x + (size_t)row * CDIM))[tid];
    float s = v.x + v.y + v.z + v.w;
    float ss = v.x * v.x + v.y * v.y + v.z * v.z + v.w * v.w;
    #pragma unroll
    for (int o = 16; o > 0; o >>= 1) {
        s += __shfl_xor_sync(0xffffffffu, s, o);
        ss += __shfl_xor_sync(0xffffffffu, ss, o);
    }
    __shared__ float sm[8], sm2[8];
    int w = tid >> 5, lane = tid & 31;
    if (lane == 0) { sm[w] = s; sm2[w] = ss; }
    __syncthreads();
    s = 0.f; ss = 0.f;
    #pragma unroll
    for (int i = 0; i < 8; i++) { s += sm[i]; ss += sm2[i]; }
    float mean = s * (1.0f / CDIM);
    float var = ss * (1.0f / CDIM) - mean * mean;
    float rstd = rsqrtf(var + 1e-5f);
    float4 gv = ((const float4*)g)[tid];
    float4 bv = ((const float4*)b)[tid];
    ushort4 hv;
    hv.x = h1((v.x - mean) * rstd * gv.x + bv.x);
    hv.y = h1((v.y - mean) * rstd * gv.y + bv.y);
    hv.z = h1((v.z - mean) * rstd * gv.z + bv.z);
    hv.w = h1((v.w - mean) * rstd * gv.w + bv.w);
    *(ushort4*)(oh + (size_t)row * CDIM + tid * 4) = hv;
}

// ---------------- HMMA GEMM: D[M,N] = A[M,K] * (Wh[+Wl])[N,K]^T ----------------
// A single fp16. Wl only for output cols < nlo. 128x128, BK=32, warp tile 64x32.
// 3-stage cp.async pipeline, ONE __syncthreads per stage, 2 CTAs/SM (92 KB smem).
// B loads x4-folded.
#define RS 80
#define ARR_BYTES (128 * RS)
#define STAGE_BYTES (3 * ARR_BYTES)       // 30720 (A, Bh, Bl)
#define SMEM_GEMM (3 * STAGE_BYTES)       // 92160 -> still 2 CTAs/SM

__device__ __forceinline__ void gemm_load_stage(
    const unsigned short* __restrict__ A,
    const unsigned short* __restrict__ Bh, const unsigned short* __restrict__ Bl,
    int K, int m0, int n0, int k0, uint32_t smbase, int buf, int tid, int use_lo) {
    uint32_t sb = smbase + buf * STAGE_BYTES;
    #pragma unroll
    for (int it = 0; it < 6; it++) {
        int e = tid + it * 256;
        int arr = e >> 9;                 // 0=A 1=Bh 2=Bl
        if (arr == 2 && !use_lo) continue;
        int idx = e & 511;
        int row = idx >> 2;
        int ch = idx & 3;
        const unsigned short* src = arr == 0 ? A : arr == 1 ? Bh : Bl;
        int r0 = (arr == 0) ? m0 : n0;
        const unsigned short* g = src + (size_t)(r0 + row) * K + k0 + ch * 8;
        CP_ASYNC16(sb + arr * ARR_BYTES + row * RS + ch * 16, g);
    }
}

__global__ __launch_bounds__(256)
void tgemm_kernel(const unsigned short* __restrict__ A,
                  const unsigned short* __restrict__ Bh, const unsigned short* __restrict__ Bl,
                  int K, int nlo,
                  float* __restrict__ Cf, unsigned short* __restrict__ Ch,
                  unsigned short* __restrict__ Cl, int locols, int ldlo,
                  const float* __restrict__ bias, const float* __restrict__ res,
                  int relu, int ldc) {
    extern __shared__ char smem[];
    uint32_t smbase = cvta_s(smem);
    int tid = threadIdx.x;
    int m0 = blockIdx.x * 128, n0 = blockIdx.y * 128;
    int use_lo = (n0 < nlo);
    int warp = tid >> 5, lane = tid & 31;
    int wm = (warp >> 2) * 64;
    int wn = (warp & 3) * 32;
    int arow = lane & 15;
    uint32_t asel = (uint32_t)(lane >> 4) << 4;
    int bnoff = ((lane >> 4) & 1) * 8 + (lane & 7);
    uint32_t bkoff = (uint32_t)((lane >> 3) & 1) << 4;

    float acc[4][4][4];
    #pragma unroll
    for (int i = 0; i < 4; i++)
        #pragma unroll
        for (int j = 0; j < 4; j++)
            #pragma unroll
            for (int q = 0; q < 4; q++) acc[i][j][q] = 0.f;

    int NS = K >> 5;
    gemm_load_stage(A, Bh, Bl, K, m0, n0, 0, smbase, 0, tid, use_lo);
    CP_COMMIT();
    gemm_load_stage(A, Bh, Bl, K, m0, n0, 32, smbase, 1, tid, use_lo);
    CP_COMMIT();

    int buf = 0;
    for (int s = 0; s < NS; s++) {
        if (s + 1 < NS) { CP_WAIT(1); } else { CP_WAIT(0); }
        __syncthreads();
        // prefetch s+2 into the buffer consumed at s-1 (free right after the sync)
        if (s + 2 < NS) {
            int pb = buf + 2; if (pb >= 3) pb -= 3;
            gemm_load_stage(A, Bh, Bl, K, m0, n0, (s + 2) << 5, smbase, pb, tid, use_lo);
            CP_COMMIT();
        }
        uint32_t sb = smbase + (uint32_t)buf * STAGE_BYTES;
        uint32_t sA = sb, sBh = sb + ARR_BYTES;
        #pragma unroll
        for (int kk = 0; kk < 2; kk++) {
            uint32_t kb = kk * 32;
            uint32_t af[4][4];
            #pragma unroll
            for (int i = 0; i < 4; i++) {
                uint32_t ra = sA + (uint32_t)(wm + i * 16 + arow) * RS + kb + asel;
                ldm_x4(af[i], ra);
            }
            #pragma unroll
            for (int j2 = 0; j2 < 2; j2++) {
                uint32_t bh4[4], bl4[4];
                uint32_t rb = sBh + (uint32_t)(wn + j2 * 16 + bnoff) * RS + kb + bkoff;
                ldm_x4(bh4, rb);
                if (use_lo) ldm_x4(bl4, rb + ARR_BYTES);
                #pragma unroll
                for (int i = 0; i < 4; i++) {
                    mma_f16(acc[i][2 * j2],     af[i], bh4);
                    mma_f16(acc[i][2 * j2 + 1], af[i], bh4 + 2);
                    if (use_lo) {
                        mma_f16(acc[i][2 * j2],     af[i], bl4);
                        mma_f16(acc[i][2 * j2 + 1], af[i], bl4 + 2);
                    }
                }
            }
        }
        if (++buf == 3) buf = 0;
    }

    int qr = lane >> 2;
    int qc = (lane & 3) * 2;
    #pragma unroll
    for (int i = 0; i < 4; i++) {
        #pragma unroll
        for (int j = 0; j < 4; j++) {
            int col = n0 + wn + j * 8 + qc;
            #pragma unroll
            for (int half = 0; half < 2; half++) {
                int row = m0 + wm + i * 16 + qr + half * 8;
                float v0 = acc[i][j][half * 2 + 0];
                float v1 = acc[i][j][half * 2 + 1];
                if (bias) {
                    float2 bv = *(const float2*)(bias + col);
                    v0 += bv.x; v1 += bv.y;
                }
                size_t base = (size_t)row * ldc + col;
                if (res) {
                    float2 e = *(const float2*)(res + base);
                    v0 += e.x; v1 += e.y;
                }
                if (relu) { v0 = fmaxf(v0, 0.f); v1 = fmaxf(v1, 0.f); }
                if (Cf) { float2 o = {v0, v1}; *(float2*)(Cf + base) = o; }
                if (Ch) {
                    __half hv0 = __float2half_rn(v0);
                    __half hv1 = __float2half_rn(v1);
                    ushort2 hv;
                    hv.x = __half_as_ushort(hv0);
                    hv.y = __half_as_ushort(hv1);
                    *(ushort2*)(Ch + base) = hv;
                    if (Cl && col < locols) {
                        ushort2 lv;
                        lv.x = h1(v0 - __half2float(hv0));
                        lv.y = h1(v1 - __half2float(hv1));
                        *(ushort2*)(Cl + (size_t)row * ldlo + col) = lv;
                    }
                }
            }
        }
    }
}

// ---------------- fused flash attention (64-row tiles, 128 thr) ----------------
// Q split fp16 (Qh,Ql), K single (x4-folded), V single (x4t-folded), P split fp16.
#define FRS 144
#define FARR (64 * FRS)                   // 9216
#define FKV_STAGE (2 * FARR)              // 18432 (K, V single)
#define SMEM_FLASH (2 * FARR + 2 * FKV_STAGE)  // 55296

__device__ __forceinline__ void flash_load_q(
    const unsigned short* __restrict__ qh, const unsigned short* __restrict__ ql,
    int rowbase, int colbase, uint32_t smbase, int tid) {
    #pragma unroll
    for (int it = 0; it < 8; it++) {
        int e = tid + it * 128;
        int arr = e >> 9;                 // 0=Qh 1=Ql
        int idx = e & 511;
        int row = idx >> 3, ch = idx & 7;
        const unsigned short* g;
        if (arr == 0)
            g = qh + (size_t)(rowbase + row) * (3 * CDIM) + colbase + ch * 8;
        else
            g = ql + (size_t)(rowbase + row) * CDIM + colbase + ch * 8;
        CP_ASYNC16(smbase + arr * FARR + row * FRS + ch * 16, g);
    }
}
__device__ __forceinline__ void flash_load_kv(
    const unsigned short* __restrict__ qh,
    int rowbase, int kcol, int vcol, uint32_t sb, int tid) {
    #pragma unroll
    for (int it = 0; it < 8; it++) {
        int e = tid + it * 128;
        int arr = e >> 9;                 // 0=K 1=V
        int idx = e & 511;
        int row = idx >> 3, ch = idx & 7;
        int col = (arr == 0) ? kcol : vcol;
        const unsigned short* g = qh + (size_t)(rowbase + row) * (3 * CDIM) + col + ch * 8;
        CP_ASYNC16(sb + arr * FARR + row * FRS + ch * 16, g);
    }
}

__global__ __launch_bounds__(128)
void flash_kernel(const unsigned short* __restrict__ qh, const unsigned short* __restrict__ ql,
                  unsigned short* __restrict__ ob) {
    extern __shared__ char smem[];
    uint32_t smbase = cvta_s(smem);
    int tid = threadIdx.x;
    int tt = (int)gridDim.x - 1 - (int)blockIdx.x;
    int bh = blockIdx.y;
    int b = bh >> 4, h = bh & 15;
    int t0 = tt * 64;
    int qrowbase = b * TLEN + t0;
    int qcol = h * HDIM;
    int kcol = CDIM + h * HDIM;
    int vcol = 2 * CDIM + h * HDIM;

    int warp = tid >> 5, lane = tid & 31;
    int wm = warp * 16;
    int arow = lane & 15;
    uint32_t asel = (uint32_t)(lane >> 4) << 4;
    int bnoff = ((lane >> 4) & 1) * 8 + (lane & 7);
    uint32_t bkoff = (uint32_t)((lane >> 3) & 1) << 4;
    // V x4t fold: row within 16-row k-group; column pair by lane>>4
    int vrowoff = (lane & 7) + ((lane >> 3) & 1) * 8;
    int vcp = (lane >> 4) & 1;
    int qr = lane >> 2;
    int qc = (lane & 3) * 2;

    float O[8][4];
    #pragma unroll
    for (int j = 0; j < 8; j++)
        #pragma unroll
        for (int q = 0; q < 4; q++) O[j][q] = 0.f;
    float m0r = -1e30f, m1r = -1e30f, l0 = 0.f, l1 = 0.f;

    int NS = tt + 1;
    uint32_t kvbase = smbase + 2 * FARR;

    flash_load_q(qh, ql, qrowbase, qcol, smbase, tid);
    flash_load_kv(qh, b * TLEN, kcol, vcol, kvbase, tid);
    CP_COMMIT();
    if (NS > 1) {
        flash_load_kv(qh, b * TLEN + 64, kcol, vcol, kvbase + FKV_STAGE, tid);
        CP_COMMIT();
    }

    for (int st = 0; st < NS; st++) {
        if (st + 1 < NS) { CP_WAIT(1); } else { CP_WAIT(0); }
        __syncthreads();
        uint32_t sKV = kvbase + (st & 1) * FKV_STAGE;
        uint32_t sK = sKV, sV = sKV + FARR;

        float S[8][4];
        #pragma unroll
        for (int j = 0; j < 8; j++)
            #pragma unroll
            for (int q = 0; q < 4; q++) S[j][q] = 0.f;
        #pragma unroll
        for (int d = 0; d < 4; d++) {
            uint32_t kb = d * 32;
            uint32_t ah[4], al[4];
            uint32_t ra = smbase + (uint32_t)(wm + arow) * FRS + kb + asel;
            ldm_x4(ah, ra);
            ldm_x4(al, ra + FARR);
            #pragma unroll
            for (int j2 = 0; j2 < 4; j2++) {
                uint32_t bf4[4];
                uint32_t rb = sK + (uint32_t)(j2 * 16 + bnoff) * FRS + kb + bkoff;
                ldm_x4(bf4, rb);
                mma_f16(S[2 * j2],     ah, bf4);
                mma_f16(S[2 * j2],     al, bf4);
                mma_f16(S[2 * j2 + 1], ah, bf4 + 2);
                mma_f16(S[2 * j2 + 1], al, bf4 + 2);
            }
        }
        if (st == tt) {
            int r0 = wm + qr, r1 = wm + qr + 8;
            #pragma unroll
            for (int j = 0; j < 8; j++) {
                int c0 = j * 8 + qc;
                S[j][0] = (c0     > r0) ? -1e30f : S[j][0] * 0.125f;
                S[j][1] = (c0 + 1 > r0) ? -1e30f : S[j][1] * 0.125f;
                S[j][2] = (c0     > r1) ? -1e30f : S[j][2] * 0.125f;
                S[j][3] = (c0 + 1 > r1) ? -1e30f : S[j][3] * 0.125f;
            }
        } else {
            #pragma unroll
            for (int j = 0; j < 8; j++)
                #pragma unroll
                for (int q = 0; q < 4; q++) S[j][q] *= 0.125f;
        }
        float mx0 = -1e30f, mx1 = -1e30f;
        #pragma unroll
        for (int j = 0; j < 8; j++) {
            mx0 = fmaxf(mx0, fmaxf(S[j][0], S[j][1]));
            mx1 = fmaxf(mx1, fmaxf(S[j][2], S[j][3]));
        }
        mx0 = fmaxf(mx0, __shfl_xor_sync(0xffffffffu, mx0, 1));
        mx0 = fmaxf(mx0, __shfl_xor_sync(0xffffffffu, mx0, 2));
        mx1 = fmaxf(mx1, __shfl_xor_sync(0xffffffffu, mx1, 1));
        mx1 = fmaxf(mx1, __shfl_xor_sync(0xffffffffu, mx1, 2));
        float mn0 = fmaxf(m0r, mx0), mn1 = fmaxf(m1r, mx1);
        float c0 = __expf(m0r - mn0), c1 = __expf(m1r - mn1);
        float rs0 = 0.f, rs1 = 0.f;
        #pragma unroll
        for (int j = 0; j < 8; j++) {
            S[j][0] = __expf(S[j][0] - mn0);
            S[j][1] = __expf(S[j][1] - mn0);
            S[j][2] = __expf(S[j][2] - mn1);
            S[j][3] = __expf(S[j][3] - mn1);
            rs0 += S[j][0] + S[j][1];
            rs1 += S[j][2] + S[j][3];
        }
        rs0 += __shfl_xor_sync(0xffffffffu, rs0, 1);
        rs0 += __shfl_xor_sync(0xffffffffu, rs0, 2);
        rs1 += __shfl_xor_sync(0xffffffffu, rs1, 1);
        rs1 += __shfl_xor_sync(0xffffffffu, rs1, 2);
        l0 = l0 * c0 + rs0;
        l1 = l1 * c1 + rs1;
        m0r = mn0; m1r = mn1;
        #pragma unroll
        for (int j = 0; j < 8; j++) {
            O[j][0] *= c0; O[j][1] *= c0;
            O[j][2] *= c1; O[j][3] *= c1;
        }
        #pragma unroll
        for (int kk = 0; kk < 4; kk++) {
            int j0 = 2 * kk, j1 = 2 * kk + 1;
            uint32_t pah[4], pal[4];
            pack2h(S[j0][0], S[j0][1], pah[0], pal[0]);
            pack2h(S[j0][2], S[j0][3], pah[1], pal[1]);
            pack2h(S[j1][0], S[j1][1], pah[2], pal[2]);
            pack2h(S[j1][2], S[j1][3], pah[3], pal[3]);
            uint32_t vrow = (uint32_t)(kk * 16 + vrowoff);
            #pragma unroll
            for (int jd2 = 0; jd2 < 4; jd2++) {
                uint32_t vf4[4];
                uint32_t rv = sV + vrow * FRS + (uint32_t)(jd2 * 2 + vcp) * 16;
                ldm_x4t(vf4, rv);
                mma_f16(O[2 * jd2],     pah, vf4);
                mma_f16(O[2 * jd2],     pal, vf4);
                mma_f16(O[2 * jd2 + 1], pah, vf4 + 2);
                mma_f16(O[2 * jd2 + 1], pal, vf4 + 2);
            }
        }
        __syncthreads();
        if (st + 2 < NS) {
            flash_load_kv(qh, b * TLEN + (st + 2) * 64, kcol, vcol,
                          kvbase + (st & 1) * FKV_STAGE, tid);
            CP_COMMIT();
        }
    }

    float inv0 = 1.f / l0, inv1 = 1.f / l1;
    int row0 = b * TLEN + t0 + wm + qr;
    #pragma unroll
    for (int jd = 0; jd < 8; jd++) {
        int col = qcol + jd * 8 + qc;
        ushort2 hv;
        hv.x = h1(O[jd][0] * inv0);
        hv.y = h1(O[jd][1] * inv0);
        *(ushort2*)(ob + (size_t)row0 * CDIM + col) = hv;
        hv.x = h1(O[jd][2] * inv1);
        hv.y = h1(O[jd][3] * inv1);
        *(ushort2*)(ob + (size_t)(row0 + 8) * CDIM + col) = hv;
    }
}

// ---------------- host ----------------
extern "C" void kernel_launch(void* const* d_in, const int* in_sizes, int n_in,
                              void* d_out, int out_size) {
    const int* idx = (const int*)d_in[0];
    const float* tok = (const float*)d_in[1];
    const float* pos = (const float*)d_in[2];
    const float* wq = (const float*)d_in[3];
    const float* wk = (const float*)d_in[4];
    const float* wv = (const float*)d_in[5];
    const float* wproj = (const float*)d_in[6];
    const float* bproj = (const float*)d_in[7];
    const float* ln1g = (const float*)d_in[8];
    const float* ln1b = (const float*)d_in[9];
    const float* ln2g = (const float*)d_in[10];
    const float* ln2b = (const float*)d_in[11];
    const float* w1 = (const float*)d_in[12];
    const float* b1 = (const float*)d_in[13];
    const float* w2 = (const float*)d_in[14];
    const float* b2 = (const float*)d_in[15];
    const float* lnfg = (const float*)d_in[16];
    const float* lnfb = (const float*)d_in[17];
    const float* wlm = (const float*)d_in[18];
    const float* blm = (const float*)d_in[19];
    float* out = (float*)d_out;

    float* px;
    unsigned short *pqkvb_h, *pqkvb_l, *phb, *pob, *pffb;
    unsigned short *pwqkv_h, *pwqkv_l, *pwproj_h, *pwproj_l;
    unsigned short *pw1_h, *pw1_l, *pw2_h, *pw2_l, *pwlm_h, *pwlm_l;
    cudaGetSymbolAddress((void**)&px, g_x);
    cudaGetSymbolAddress((void**)&pqkvb_h, g_qkvb_h);
    cudaGetSymbolAddress((void**)&pqkvb_l, g_qkvb_l);
    cudaGetSymbolAddress((void**)&phb, g_hb);
    cudaGetSymbolAddress((void**)&pob, g_ob);
    cudaGetSymbolAddress((void**)&pffb, g_ffb);
    cudaGetSymbolAddress((void**)&pwqkv_h, g_wqkv_h);
    cudaGetSymbolAddress((void**)&pwqkv_l, g_wqkv_l);
    cudaGetSymbolAddress((void**)&pwproj_h, g_wproj_h);
    cudaGetSymbolAddress((void**)&pwproj_l, g_wproj_l);
    cudaGetSymbolAddress((void**)&pw1_h, g_w1_h);
    cudaGetSymbolAddress((void**)&pw1_l, g_w1_l);
    cudaGetSymbolAddress((void**)&pw2_h, g_w2_h);
    cudaGetSymbolAddress((void**)&pw2_l, g_w2_l);
    cudaGetSymbolAddress((void**)&pwlm_h, g_wlm_h);
    cudaGetSymbolAddress((void**)&pwlm_l, g_wlm_l);

    cudaFuncSetAttribute(tgemm_kernel, cudaFuncAttributeMaxDynamicSharedMemorySize, SMEM_GEMM);
    cudaFuncSetAttribute(flash_kernel, cudaFuncAttributeMaxDynamicSharedMemorySize, SMEM_FLASH);

    dim3 tb(32, 8);
    tsplit_qkv_kernel<<<dim3(96, 32, 8), tb>>>(wq, wk, wv, pwqkv_h, pwqkv_l);
    tsplit_mat_kernel<<<dim3(32, 32, 8), tb>>>(wproj, pwproj_h, pwproj_l, CDIM, CDIM);
    tsplit_mat_kernel<<<dim3(128, 32, 8), tb>>>(w1, pw1_h, pw1_l, CDIM, FF);
    tsplit_mat_kernel<<<dim3(32, 128, 8), tb>>>(w2, pw2_h, pw2_l, FF, CDIM);
    tsplit_mat_kernel<<<dim3(1000, 32, 1), tb>>>(wlm, pwlm_h, pwlm_l, CDIM, VOCAB);

    embed_kernel<<<NTOK, 256>>>(idx, tok, pos, px);

    for (int l = 0; l < NLAYER; l++) {
        ln_kernel<<<NTOK, 256>>>(px, ln1g + (size_t)l * CDIM, ln1b + (size_t)l * CDIM, phb);
        tgemm_kernel<<<dim3(32, 24), 256, SMEM_GEMM>>>(
            phb, pwqkv_h + (size_t)l * 3072 * 1024, pwqkv_l + (size_t)l * 3072 * 1024,
            CDIM, CDIM, nullptr, pqkvb_h, pqkvb_l, CDIM, CDIM, nullptr, nullptr, 0, 3 * CDIM);
        flash_kernel<<<dim3(16, BATCH * NHEAD), 128, SMEM_FLASH>>>(pqkvb_h, pqkvb_l, pob);
        tgemm_kernel<<<dim3(32, 8), 256, SMEM_GEMM>>>(
            pob, pwproj_h + (size_t)l * CDIM * CDIM, pwproj_l + (size_t)l * CDIM * CDIM,
            CDIM, CDIM, px, nullptr, nullptr, 0, 0, bproj + (size_t)l * CDIM, px, 0, CDIM);
        ln_kernel<<<NTOK, 256>>>(px, ln2g + (size_t)l * CDIM, ln2b + (size_t)l * CDIM, phb);
        tgemm_kernel<<<dim3(32, 32), 256, SMEM_GEMM>>>(
            phb, pw1_h + (size_t)l * FF * CDIM, pw1_l + (size_t)l * FF * CDIM,
            CDIM, 0, nullptr, pffb, nullptr, 0, 0, b1 + (size_t)l * FF, nullptr, 1, FF);
        tgemm_kernel<<<dim3(32, 8), 256, SMEM_GEMM>>>(
            pffb, pw2_h + (size_t)l * CDIM * FF, pw2_l + (size_t)l * CDIM * FF,
            FF, CDIM, px, nullptr, nullptr, 0, 0, b2 + (size_t)l * CDIM, px, 0, CDIM);
    }
    ln_kernel<<<NTOK, 256>>>(px, lnfg, lnfb, phb);
    tgemm_kernel<<<dim3(32, 250), 256, SMEM_GEMM>>>(
        phb, pwlm_h, pwlm_l, CDIM, VOCAB, out, nullptr, nullptr, 0, 0, blm, nullptr, 0, VOCAB);
}

// round 14
// speedup vs baseline: 1.1993x; 1.0193x over previous
#include <cuda_runtime.h>
#include <cuda_fp16.h>
#include <cstdint>
#include <math.h>

#define BATCH 4
#define TLEN 1024
#define CDIM 1024
#define NHEAD 16
#define HDIM 64
#define NLAYER 8
#define VOCAB 32000
#define NTOK (BATCH * TLEN)
#define FF (4 * CDIM)

// ---------------- device scratch ----------------
__device__ float g_x[NTOK * CDIM];
__device__ unsigned short g_qkvb_h[NTOK * 3 * CDIM], g_qkvb_l[NTOK * CDIM];  // lo only for Q
__device__ unsigned short g_hb[NTOK * CDIM];
__device__ unsigned short g_ob[NTOK * CDIM];
__device__ unsigned short g_ffb[(size_t)NTOK * FF];
__device__ unsigned short g_wqkv_h[(size_t)NLAYER * 3 * CDIM * CDIM], g_wqkv_l[(size_t)NLAYER * 3 * CDIM * CDIM];
__device__ unsigned short g_wproj_h[(size_t)NLAYER * CDIM * CDIM], g_wproj_l[(size_t)NLAYER * CDIM * CDIM];
__device__ unsigned short g_w1_h[(size_t)NLAYER * FF * CDIM], g_w1_l[(size_t)NLAYER * FF * CDIM];
__device__ unsigned short g_w2_h[(size_t)NLAYER * CDIM * FF], g_w2_l[(size_t)NLAYER * CDIM * FF];
__device__ unsigned short g_wlm_h[(size_t)VOCAB * CDIM], g_wlm_l[(size_t)VOCAB * CDIM];

// ---------------- helpers ----------------
__device__ __forceinline__ uint32_t cvta_s(const void* p) {
    uint32_t a;
    asm("{ .reg .u64 t; cvta.to.shared.u64 t, %1; cvt.u32.u64 %0, t; }" : "=r"(a) : "l"(p));
    return a;
}
#define CP_ASYNC16(dst, src) \
    asm volatile("cp.async.cg.shared.global [%0], [%1], 16;" :: "r"(dst), "l"(src))
#define CP_COMMIT() asm volatile("cp.async.commit_group;" ::: "memory")
#define CP_WAIT(n)  asm volatile("cp.async.wait_group %0;" :: "n"(n) : "memory")

__device__ __forceinline__ void ldm_x4(uint32_t* r, uint32_t addr) {
    asm volatile("ldmatrix.sync.aligned.m8n8.x4.shared.b16 {%0,%1,%2,%3}, [%4];"
                 : "=r"(r[0]), "=r"(r[1]), "=r"(r[2]), "=r"(r[3]) : "r"(addr));
}
__device__ __forceinline__ void ldm_x2(uint32_t* r, uint32_t addr) {
    asm volatile("ldmatrix.sync.aligned.m8n8.x2.shared.b16 {%0,%1}, [%2];"
                 : "=r"(r[0]), "=r"(r[1]) : "r"(addr));
}
__device__ __forceinline__ void ldm_x4t(uint32_t* r, uint32_t addr) {
    asm volatile("ldmatrix.sync.aligned.m8n8.x4.trans.shared.b16 {%0,%1,%2,%3}, [%4];"
                 : "=r"(r[0]), "=r"(r[1]), "=r"(r[2]), "=r"(r[3]) : "r"(addr));
}
__device__ __forceinline__ void mma_f16(float* d, const uint32_t* a, const uint32_t* b) {
    asm volatile(
        "mma.sync.aligned.m16n8k16.row.col.f32.f16.f16.f32 "
        "{%0,%1,%2,%3}, {%4,%5,%6,%7}, {%8,%9}, {%0,%1,%2,%3};"
        : "+f"(d[0]), "+f"(d[1]), "+f"(d[2]), "+f"(d[3])
        : "r"(a[0]), "r"(a[1]), "r"(a[2]), "r"(a[3]), "r"(b[0]), "r"(b[1]));
}
__device__ __forceinline__ void hsplit(float v, unsigned short& h, unsigned short& l) {
    __half hb = __float2half_rn(v);
    __half lb = __float2half_rn(v - __half2float(hb));
    h = __half_as_ushort(hb);
    l = __half_as_ushort(lb);
}
__device__ __forceinline__ unsigned short h1(float v) {
    return __half_as_ushort(__float2half_rn(v));
}
__device__ __forceinline__ void pack2h(float a, float b, uint32_t& hi, uint32_t& lo) {
    unsigned short h0, l0, hh1, l1;
    hsplit(a, h0, l0);
    hsplit(b, hh1, l1);
    hi = (uint32_t)h0 | ((uint32_t)hh1 << 16);
    lo = (uint32_t)l0 | ((uint32_t)l1 << 16);
}

// ---------------- weight prep (transpose + fp16 hi/lo split) ----------------
__global__ void tsplit_qkv_kernel(const float* __restrict__ wq, const float* __restrict__ wk,
                                  const float* __restrict__ wv,
                                  unsigned short* __restrict__ dh, unsigned short* __restrict__ dl) {
    __shared__ float t[32][33];
    int n0 = blockIdx.x * 32, k0 = blockIdx.y * 32, l = blockIdx.z;
    int sel = n0 >> 10;
    const float* src = sel == 0 ? wq : (sel == 1 ? wk : wv);
    int within = n0 & 1023;
    int h = within >> 6, d0 = within & 63;
    const float* sp = src + ((size_t)(l * 16 + h) * 1024 + k0) * 64 + d0;
    int tx = threadIdx.x, ty = threadIdx.y;
    #pragma unroll
    for (int i = 0; i < 4; i++) t[ty + i * 8][tx] = sp[(size_t)(ty + i * 8) * 64 + tx];
    __syncthreads();
    size_t ob = (size_t)l * 3072 * 1024;
    #pragma unroll
    for (int i = 0; i < 4; i++) {
        int n = n0 + ty + i * 8, k = k0 + tx;
        unsigned short hh, ll;
        hsplit(t[tx][ty + i * 8], hh, ll);
        dh[ob + (size_t)n * 1024 + k] = hh;
        dl[ob + (size_t)n * 1024 + k] = ll;
    }
}
__global__ void tsplit_mat_kernel(const float* __restrict__ src,
                                  unsigned short* __restrict__ dh, unsigned short* __restrict__ dl,
                                  int K, int N) {
    __shared__ float t[32][33];
    int n0 = blockIdx.x * 32, k0 = blockIdx.y * 32;
    size_t l = blockIdx.z;
    const float* sp = src + l * (size_t)K * N;
    int tx = threadIdx.x, ty = threadIdx.y;
    #pragma unroll
    for (int i = 0; i < 4; i++) t[ty + i * 8][tx] = sp[(size_t)(k0 + ty + i * 8) * N + n0 + tx];
    __syncthreads();
    size_t ob = l * (size_t)K * N;
    #pragma unroll
    for (int i = 0; i < 4; i++) {
        int n = n0 + ty + i * 8, k = k0 + tx;
        unsigned short hh, ll;
        hsplit(t[tx][ty + i * 8], hh, ll);
        dh[ob + (size_t)n * K + k] = hh;
        dl[ob + (size_t)n * K + k] = ll;
    }
}

// ---------------- embed ----------------
__global__ void embed_kernel(const int* __restrict__ idx, const float* __restrict__ tok,
                             const float* __restrict__ pos, float* __restrict__ x) {
    int row = blockIdx.x;
    int t = row & (TLEN - 1);
    int token = idx[row];
    const float4* te = (const float4*)(tok + (size_t)token * CDIM);
    const float4* pe = (const float4*)(pos + (size_t)t * CDIM);
    float4* xo = (float4*)(x + (size_t)row * CDIM);
    int i = threadIdx.x;
    float4 a = te[i], b = pe[i];
    a.x += b.x; a.y += b.y; a.z += b.z; a.w += b.w;
    xo[i] = a;
}

// ---------------- LayerNorm -> single fp16 ----------------
__global__ void ln_kernel(const float* __restrict__ x, const float* __restrict__ g,
                          const float* __restrict__ b, unsigned short* __restrict__ oh) {
    int row = blockIdx.x;
    int tid = threadIdx.x;
    float4 v = ((const float4*)(x + (size_t)row * CDIM))[tid];
    float s = v.x + v.y + v.z + v.w;
    float ss = v.x * v.x + v.y * v.y + v.z * v.z + v.w * v.w;
    #pragma unroll
    for (int o = 16; o > 0; o >>= 1) {
        s += __shfl_xor_sync(0xffffffffu, s, o);
        ss += __shfl_xor_sync(0xffffffffu, ss, o);
    }
    __shared__ float sm[8], sm2[8];
    int w = tid >> 5, lane = tid & 31;
    if (lane == 0) { sm[w] = s; sm2[w] = ss; }
    __syncthreads();
    s = 0.f; ss = 0.f;
    #pragma unroll
    for (int i = 0; i < 8; i++) { s += sm[i]; ss += sm2[i]; }
    float mean = s * (1.0f / CDIM);
    float var = ss * (1.0f / CDIM) - mean * mean;
    float rstd = rsqrtf(var + 1e-5f);
    float4 gv = ((const float4*)g)[tid];
    float4 bv = ((const float4*)b)[tid];
    ushort4 hv;
    hv.x = h1((v.x - mean) * rstd * gv.x + bv.x);
    hv.y = h1((v.y - mean) * rstd * gv.y + bv.y);
    hv.z = h1((v.z - mean) * rstd * gv.z + bv.z);
    hv.w = h1((v.w - mean) * rstd * gv.w + bv.w);
    *(ushort4*)(oh + (size_t)row * CDIM + tid * 4) = hv;
}

// ---------------- HMMA GEMM: D[M,N] = A[M,K] * (Wh[+Wl])[N,K]^T ----------------
// A single fp16. Wl only for output cols < nlo. 128x128, BK=32, warp tile 64x32.
// 3-stage cp.async pipeline, ONE __syncthreads per stage, 2 CTAs/SM (92 KB smem).
// B loads x4-folded.
#define RS 80
#define ARR_BYTES (128 * RS)
#define STAGE_BYTES (3 * ARR_BYTES)       // 30720 (A, Bh, Bl)
#define SMEM_GEMM (3 * STAGE_BYTES)       // 92160 -> still 2 CTAs/SM

__device__ __forceinline__ void gemm_load_stage(
    const unsigned short* __restrict__ A,
    const unsigned short* __restrict__ Bh, const unsigned short* __restrict__ Bl,
    int K, int m0, int n0, int k0, uint32_t smbase, int buf, int tid, int use_lo) {
    uint32_t sb = smbase + buf * STAGE_BYTES;
    #pragma unroll
    for (int it = 0; it < 6; it++) {
        int e = tid + it * 256;
        int arr = e >> 9;                 // 0=A 1=Bh 2=Bl
        if (arr == 2 && !use_lo) continue;
        int idx = e & 511;
        int row = idx >> 2;
        int ch = idx & 3;
        const unsigned short* src = arr == 0 ? A : arr == 1 ? Bh : Bl;
        int r0 = (arr == 0) ? m0 : n0;
        const unsigned short* g = src + (size_t)(r0 + row) * K + k0 + ch * 8;
        CP_ASYNC16(sb + arr * ARR_BYTES + row * RS + ch * 16, g);
    }
}

__global__ __launch_bounds__(256)
void tgemm_kernel(const unsigned short* __restrict__ A,
                  const unsigned short* __restrict__ Bh, const unsigned short* __restrict__ Bl,
                  int K, int nlo,
                  float* __restrict__ Cf, unsigned short* __restrict__ Ch,
                  unsigned short* __restrict__ Cl, int locols, int ldlo,
                  const float* __restrict__ bias, const float* __restrict__ res,
                  int relu, int ldc) {
    extern __shared__ char smem[];
    uint32_t smbase = cvta_s(smem);
    int tid = threadIdx.x;
    int m0 = blockIdx.x * 128, n0 = blockIdx.y * 128;
    int use_lo = (n0 < nlo);
    int warp = tid >> 5, lane = tid & 31;
    int wm = (warp >> 2) * 64;
    int wn = (warp & 3) * 32;
    int arow = lane & 15;
    uint32_t asel = (uint32_t)(lane >> 4) << 4;
    int bnoff = ((lane >> 4) & 1) * 8 + (lane & 7);
    uint32_t bkoff = (uint32_t)((lane >> 3) & 1) << 4;

    float acc[4][4][4];
    #pragma unroll
    for (int i = 0; i < 4; i++)
        #pragma unroll
        for (int j = 0; j < 4; j++)
            #pragma unroll
            for (int q = 0; q < 4; q++) acc[i][j][q] = 0.f;

    int NS = K >> 5;
    gemm_load_stage(A, Bh, Bl, K, m0, n0, 0, smbase, 0, tid, use_lo);
    CP_COMMIT();
    gemm_load_stage(A, Bh, Bl, K, m0, n0, 32, smbase, 1, tid, use_lo);
    CP_COMMIT();

    int buf = 0;
    for (int s = 0; s < NS; s++) {
        if (s + 1 < NS) { CP_WAIT(1); } else { CP_WAIT(0); }
        __syncthreads();
        // prefetch s+2 into the buffer consumed at s-1 (free right after the sync)
        if (s + 2 < NS) {
            int pb = buf + 2; if (pb >= 3) pb -= 3;
            gemm_load_stage(A, Bh, Bl, K, m0, n0, (s + 2) << 5, smbase, pb, tid, use_lo);
            CP_COMMIT();
        }
        uint32_t sb = smbase + (uint32_t)buf * STAGE_BYTES;
        uint32_t sA = sb, sBh = sb + ARR_BYTES;
        #pragma unroll
        for (int kk = 0; kk < 2; kk++) {
            uint32_t kb = kk * 32;
            uint32_t af[4][4];
            #pragma unroll
            for (int i = 0; i < 4; i++) {
                uint32_t ra = sA + (uint32_t)(wm + i * 16 + arow) * RS + kb + asel;
                ldm_x4(af[i], ra);
            }
            #pragma unroll
            for (int j2 = 0; j2 < 2; j2++) {
                uint32_t bh4[4], bl4[4];
                uint32_t rb = sBh + (uint32_t)(wn + j2 * 16 + bnoff) * RS + kb + bkoff;
                ldm_x4(bh4, rb);
                if (use_lo) ldm_x4(bl4, rb + ARR_BYTES);
                #pragma unroll
                for (int i = 0; i < 4; i++) {
                    mma_f16(acc[i][2 * j2],     af[i], bh4);
                    mma_f16(acc[i][2 * j2 + 1], af[i], bh4 + 2);
                    if (use_lo) {
                        mma_f16(acc[i][2 * j2],     af[i], bl4);
                        mma_f16(acc[i][2 * j2 + 1], af[i], bl4 + 2);
                    }
                }
            }
        }
        if (++buf == 3) buf = 0;
    }

    int qr = lane >> 2;
    int qc = (lane & 3) * 2;
    #pragma unroll
    for (int i = 0; i < 4; i++) {
        #pragma unroll
        for (int j = 0; j < 4; j++) {
            int col = n0 + wn + j * 8 + qc;
            #pragma unroll
            for (int half = 0; half < 2; half++) {
                int row = m0 + wm + i * 16 + qr + half * 8;
                float v0 = acc[i][j][half * 2 + 0];
                float v1 = acc[i][j][half * 2 + 1];
                if (bias) {
                    float2 bv = *(const float2*)(bias + col);
                    v0 += bv.x; v1 += bv.y;
                }
                size_t base = (size_t)row * ldc + col;
                if (res) {
                    float2 e = *(const float2*)(res + base);
                    v0 += e.x; v1 += e.y;
                }
                if (relu) { v0 = fmaxf(v0, 0.f); v1 = fmaxf(v1, 0.f); }
                if (Cf) { float2 o = {v0, v1}; *(float2*)(Cf + base) = o; }
                if (Ch) {
                    __half hv0 = __float2half_rn(v0);
                    __half hv1 = __float2half_rn(v1);
                    ushort2 hv;
                    hv.x = __half_as_ushort(hv0);
                    hv.y = __half_as_ushort(hv1);
                    *(ushort2*)(Ch + base) = hv;
                    if (Cl && col < locols) {
                        ushort2 lv;
                        lv.x = h1(v0 - __half2float(hv0));
                        lv.y = h1(v1 - __half2float(hv1));
                        *(ushort2*)(Cl + (size_t)row * ldlo + col) = lv;
                    }
                }
            }
        }
    }
}

// ---------------- fused flash attention (64-row tiles, 128 thr) ----------------
// Q split fp16 (Qh,Ql), K single (x4-folded), V single (x4t-folded), P split fp16.
#define FRS 144
#define FARR (64 * FRS)                   // 9216
#define FKV_STAGE (2 * FARR)              // 18432 (K, V single)
#define SMEM_FLASH (2 * FARR + 2 * FKV_STAGE)  // 55296

__device__ __forceinline__ void flash_load_q(
    const unsigned short* __restrict__ qh, const unsigned short* __restrict__ ql,
    int rowbase, int colbase, uint32_t smbase, int tid) {
    #pragma unroll
    for (int it = 0; it < 8; it++) {
        int e = tid + it * 128;
        int arr = e >> 9;                 // 0=Qh 1=Ql
        int idx = e & 511;
        int row = idx >> 3, ch = idx & 7;
        const unsigned short* g;
        if (arr == 0)
            g = qh + (size_t)(rowbase + row) * (3 * CDIM) + colbase + ch * 8;
        else
            g = ql + (size_t)(rowbase + row) * CDIM + colbase + ch * 8;
        CP_ASYNC16(smbase + arr * FARR + row * FRS + ch * 16, g);
    }
}
__device__ __forceinline__ void flash_load_kv(
    const unsigned short* __restrict__ qh,
    int rowbase, int kcol, int vcol, uint32_t sb, int tid) {
    #pragma unroll
    for (int it = 0; it < 8; it++) {
        int e = tid + it * 128;
        int arr = e >> 9;                 // 0=K 1=V
        int idx = e & 511;
        int row = idx >> 3, ch = idx & 7;
        int col = (arr == 0) ? kcol : vcol;
        const unsigned short* g = qh + (size_t)(rowbase + row) * (3 * CDIM) + col + ch * 8;
        CP_ASYNC16(sb + arr * FARR + row * FRS + ch * 16, g);
    }
}

__global__ __launch_bounds__(128)
void flash_kernel(const unsigned short* __restrict__ qh, const unsigned short* __restrict__ ql,
                  unsigned short* __restrict__ ob) {
    extern __shared__ char smem[];
    uint32_t smbase = cvta_s(smem);
    int tid = threadIdx.x;
    int tt = (int)gridDim.x - 1 - (int)blockIdx.x;
    int bh = blockIdx.y;
    int b = bh >> 4, h = bh & 15;
    int t0 = tt * 64;
    int qrowbase = b * TLEN + t0;
    int qcol = h * HDIM;
    int kcol = CDIM + h * HDIM;
    int vcol = 2 * CDIM + h * HDIM;

    int warp = tid >> 5, lane = tid & 31;
    int wm = warp * 16;
    int arow = lane & 15;
    uint32_t asel = (uint32_t)(lane >> 4) << 4;
    int bnoff = ((lane >> 4) & 1) * 8 + (lane & 7);
    uint32_t bkoff = (uint32_t)((lane >> 3) & 1) << 4;
    int vrowoff = (lane & 7) + ((lane >> 3) & 1) * 8;
    int vcp = (lane >> 4) & 1;
    int qr = lane >> 2;
    int qc = (lane & 3) * 2;

    float O[8][4];
    #pragma unroll
    for (int j = 0; j < 8; j++)
        #pragma unroll
        for (int q = 0; q < 4; q++) O[j][q] = 0.f;
    float m0r = -1e30f, m1r = -1e30f, l0 = 0.f, l1 = 0.f;

    int NS = tt + 1;
    uint32_t kvbase = smbase + 2 * FARR;

    flash_load_q(qh, ql, qrowbase, qcol, smbase, tid);
    flash_load_kv(qh, b * TLEN, kcol, vcol, kvbase, tid);
    CP_COMMIT();
    if (NS > 1) {
        flash_load_kv(qh, b * TLEN + 64, kcol, vcol, kvbase + FKV_STAGE, tid);
        CP_COMMIT();
    }

    for (int st = 0; st < NS; st++) {
        if (st + 1 < NS) { CP_WAIT(1); } else { CP_WAIT(0); }
        __syncthreads();
        uint32_t sKV = kvbase + (st & 1) * FKV_STAGE;
        uint32_t sK = sKV, sV = sKV + FARR;

        float S[8][4];
        #pragma unroll
        for (int j = 0; j < 8; j++)
            #pragma unroll
            for (int q = 0; q < 4; q++) S[j][q] = 0.f;
        #pragma unroll
        for (int d = 0; d < 4; d++) {
            uint32_t kb = d * 32;
            uint32_t ah[4], al[4];
            uint32_t ra = smbase + (uint32_t)(wm + arow) * FRS + kb + asel;
            ldm_x4(ah, ra);
            ldm_x4(al, ra + FARR);
            #pragma unroll
            for (int j2 = 0; j2 < 4; j2++) {
                uint32_t bf4[4];
                uint32_t rb = sK + (uint32_t)(j2 * 16 + bnoff) * FRS + kb + bkoff;
                ldm_x4(bf4, rb);
                mma_f16(S[2 * j2],     ah, bf4);
                mma_f16(S[2 * j2],     al, bf4);
                mma_f16(S[2 * j2 + 1], ah, bf4 + 2);
                mma_f16(S[2 * j2 + 1], al, bf4 + 2);
            }
        }
        if (st == tt) {
            int r0 = wm + qr, r1 = wm + qr + 8;
            #pragma unroll
            for (int j = 0; j < 8; j++) {
                int c0 = j * 8 + qc;
                S[j][0] = (c0     > r0) ? -1e30f : S[j][0] * 0.125f;
                S[j][1] = (c0 + 1 > r0) ? -1e30f : S[j][1] * 0.125f;
                S[j][2] = (c0     > r1) ? -1e30f : S[j][2] * 0.125f;
                S[j][3] = (c0 + 1 > r1) ? -1e30f : S[j][3] * 0.125f;
            }
        } else {
            #pragma unroll
            for (int j = 0; j < 8; j++)
                #pragma unroll
                for (int q = 0; q < 4; q++) S[j][q] *= 0.125f;
        }
        float mx0 = -1e30f, mx1 = -1e30f;
        #pragma unroll
        for (int j = 0; j < 8; j++) {
            mx0 = fmaxf(mx0, fmaxf(S[j][0], S[j][1]));
            mx1 = fmaxf(mx1, fmaxf(S[j][2], S[j][3]));
        }
        mx0 = fmaxf(mx0, __shfl_xor_sync(0xffffffffu, mx0, 1));
        mx0 = fmaxf(mx0, __shfl_xor_sync(0xffffffffu, mx0, 2));
        mx1 = fmaxf(mx1, __shfl_xor_sync(0xffffffffu, mx1, 1));
        mx1 = fmaxf(mx1, __shfl_xor_sync(0xffffffffu, mx1, 2));
        float mn0 = fmaxf(m0r, mx0), mn1 = fmaxf(m1r, mx1);
        float c0 = __expf(m0r - mn0), c1 = __expf(m1r - mn1);
        float rs0 = 0.f, rs1 = 0.f;
        #pragma unroll
        for (int j = 0; j < 8; j++) {
            S[j][0] = __expf(S[j][0] - mn0);
            S[j][1] = __expf(S[j][1] - mn0);
            S[j][2] = __expf(S[j][2] - mn1);
            S[j][3] = __expf(S[j][3] - mn1);
            rs0 += S[j][0] + S[j][1];
            rs1 += S[j][2] + S[j][3];
        }
        rs0 += __shfl_xor_sync(0xffffffffu, rs0, 1);
        rs0 += __shfl_xor_sync(0xffffffffu, rs0, 2);
        rs1 += __shfl_xor_sync(0xffffffffu, rs1, 1);
        rs1 += __shfl_xor_sync(0xffffffffu, rs1, 2);
        l0 = l0 * c0 + rs0;
        l1 = l1 * c1 + rs1;
        m0r = mn0; m1r = mn1;
        #pragma unroll
        for (int j = 0; j < 8; j++) {
            O[j][0] *= c0; O[j][1] *= c0;
            O[j][2] *= c1; O[j][3] *= c1;
        }
        #pragma unroll
        for (int kk = 0; kk < 4; kk++) {
            int j0 = 2 * kk, j1 = 2 * kk + 1;
            uint32_t pah[4], pal[4];
            pack2h(S[j0][0], S[j0][1], pah[0], pal[0]);
            pack2h(S[j0][2], S[j0][3], pah[1], pal[1]);
            pack2h(S[j1][0], S[j1][1], pah[2], pal[2]);
            pack2h(S[j1][2], S[j1][3], pah[3], pal[3]);
            uint32_t vrow = (uint32_t)(kk * 16 + vrowoff);
            #pragma unroll
            for (int jd2 = 0; jd2 < 4; jd2++) {
                uint32_t vf4[4];
                uint32_t rv = sV + vrow * FRS + (uint32_t)(jd2 * 2 + vcp) * 16;
                ldm_x4t(vf4, rv);
                mma_f16(O[2 * jd2],     pah, vf4);
                mma_f16(O[2 * jd2],     pal, vf4);
                mma_f16(O[2 * jd2 + 1], pah, vf4 + 2);
                mma_f16(O[2 * jd2 + 1], pal, vf4 + 2);
            }
        }
        __syncthreads();
        if (st + 2 < NS) {
            flash_load_kv(qh, b * TLEN + (st + 2) * 64, kcol, vcol,
                          kvbase + (st & 1) * FKV_STAGE, tid);
            CP_COMMIT();
        }
    }

    float inv0 = 1.f / l0, inv1 = 1.f / l1;
    int row0 = b * TLEN + t0 + wm + qr;
    #pragma unroll
    for (int jd = 0; jd < 8; jd++) {
        int col = qcol + jd * 8 + qc;
        ushort2 hv;
        hv.x = h1(O[jd][0] * inv0);
        hv.y = h1(O[jd][1] * inv0);
        *(ushort2*)(ob + (size_t)row0 * CDIM + col) = hv;
        hv.x = h1(O[jd][2] * inv1);
        hv.y = h1(O[jd][3] * inv1);
        *(ushort2*)(ob + (size_t)(row0 + 8) * CDIM + col) = hv;
    }
}

// ---------------- host ----------------
extern "C" void kernel_launch(void* const* d_in, const int* in_sizes, int n_in,
                              void* d_out, int out_size) {
    const int* idx = (const int*)d_in[0];
    const float* tok = (const float*)d_in[1];
    const float* pos = (const float*)d_in[2];
    const float* wq = (const float*)d_in[3];
    const float* wk = (const float*)d_in[4];
    const float* wv = (const float*)d_in[5];
    const float* wproj = (const float*)d_in[6];
    const float* bproj = (const float*)d_in[7];
    const float* ln1g = (const float*)d_in[8];
    const float* ln1b = (const float*)d_in[9];
    const float* ln2g = (const float*)d_in[10];
    const float* ln2b = (const float*)d_in[11];
    const float* w1 = (const float*)d_in[12];
    const float* b1 = (const float*)d_in[13];
    const float* w2 = (const float*)d_in[14];
    const float* b2 = (const float*)d_in[15];
    const float* lnfg = (const float*)d_in[16];
    const float* lnfb = (const float*)d_in[17];
    const float* wlm = (const float*)d_in[18];
    const float* blm = (const float*)d_in[19];
    float* out = (float*)d_out;

    float* px;
    unsigned short *pqkvb_h, *pqkvb_l, *phb, *pob, *pffb;
    unsigned short *pwqkv_h, *pwqkv_l, *pwproj_h, *pwproj_l;
    unsigned short *pw1_h, *pw1_l, *pw2_h, *pw2_l, *pwlm_h, *pwlm_l;
    cudaGetSymbolAddress((void**)&px, g_x);
    cudaGetSymbolAddress((void**)&pqkvb_h, g_qkvb_h);
    cudaGetSymbolAddress((void**)&pqkvb_l, g_qkvb_l);
    cudaGetSymbolAddress((void**)&phb, g_hb);
    cudaGetSymbolAddress((void**)&pob, g_ob);
    cudaGetSymbolAddress((void**)&pffb, g_ffb);
    cudaGetSymbolAddress((void**)&pwqkv_h, g_wqkv_h);
    cudaGetSymbolAddress((void**)&pwqkv_l, g_wqkv_l);
    cudaGetSymbolAddress((void**)&pwproj_h, g_wproj_h);
    cudaGetSymbolAddress((void**)&pwproj_l, g_wproj_l);
    cudaGetSymbolAddress((void**)&pw1_h, g_w1_h);
    cudaGetSymbolAddress((void**)&pw1_l, g_w1_l);
    cudaGetSymbolAddress((void**)&pw2_h, g_w2_h);
    cudaGetSymbolAddress((void**)&pw2_l, g_w2_l);
    cudaGetSymbolAddress((void**)&pwlm_h, g_wlm_h);
    cudaGetSymbolAddress((void**)&pwlm_l, g_wlm_l);

    cudaFuncSetAttribute(tgemm_kernel, cudaFuncAttributeMaxDynamicSharedMemorySize, SMEM_GEMM);
    cudaFuncSetAttribute(flash_kernel, cudaFuncAttributeMaxDynamicSharedMemorySize, SMEM_FLASH);

    dim3 tb(32, 8);
    tsplit_qkv_kernel<<<dim3(96, 32, 8), tb>>>(wq, wk, wv, pwqkv_h, pwqkv_l);
    tsplit_mat_kernel<<<dim3(32, 32, 8), tb>>>(wproj, pwproj_h, pwproj_l, CDIM, CDIM);
    tsplit_mat_kernel<<<dim3(128, 32, 8), tb>>>(w1, pw1_h, pw1_l, CDIM, FF);
    tsplit_mat_kernel<<<dim3(32, 128, 8), tb>>>(w2, pw2_h, pw2_l, FF, CDIM);
    tsplit_mat_kernel<<<dim3(1000, 32, 1), tb>>>(wlm, pwlm_h, pwlm_l, CDIM, VOCAB);

    embed_kernel<<<NTOK, 256>>>(idx, tok, pos, px);

    for (int l = 0; l < NLAYER; l++) {
        ln_kernel<<<NTOK, 256>>>(px, ln1g + (size_t)l * CDIM, ln1b + (size_t)l * CDIM, phb);
        tgemm_kernel<<<dim3(32, 24), 256, SMEM_GEMM>>>(
            phb, pwqkv_h + (size_t)l * 3072 * 1024, pwqkv_l + (size_t)l * 3072 * 1024,
            CDIM, CDIM, nullptr, pqkvb_h, pqkvb_l, CDIM, CDIM, nullptr, nullptr, 0, 3 * CDIM);
        flash_kernel<<<dim3(16, BATCH * NHEAD), 128, SMEM_FLASH>>>(pqkvb_h, pqkvb_l, pob);
        tgemm_kernel<<<dim3(32, 8), 256, SMEM_GEMM>>>(
            pob, pwproj_h + (size_t)l * CDIM * CDIM, pwproj_l + (size_t)l * CDIM * CDIM,
            CDIM, CDIM, px, nullptr, nullptr, 0, 0, bproj + (size_t)l * CDIM, px, 0, CDIM);
        ln_kernel<<<NTOK, 256>>>(px, ln2g + (size_t)l * CDIM, ln2b + (size_t)l * CDIM, phb);
        tgemm_kernel<<<dim3(32, 32), 256, SMEM_GEMM>>>(
            phb, pw1_h + (size_t)l * FF * CDIM, pw1_l + (size_t)l * FF * CDIM,
            CDIM, 0, nullptr, pffb, nullptr, 0, 0, b1 + (size_t)l * FF, nullptr, 1, FF);
        tgemm_kernel<<<dim3(32, 8), 256, SMEM_GEMM>>>(
            pffb, pw2_h + (size_t)l * CDIM * FF, pw2_l + (size_t)l * CDIM * FF,
            FF, CDIM, px, nullptr, nullptr, 0, 0, b2 + (size_t)l * CDIM, px, 0, CDIM);
    }
    ln_kernel<<<NTOK, 256>>>(px, lnfg, lnfb, phb);
    // LM head: hi-only (weight-lo dropped — existing residual-stream error dominates)
    tgemm_kernel<<<dim3(32, 250), 256, SMEM_GEMM>>>(
        phb, pwlm_h, pwlm_l, CDIM, 0, out, nullptr, nullptr, 0, 0, blm, nullptr, 0, VOCAB);
}

// round 15
// speedup vs baseline: 1.4080x; 1.1740x over previous
#include <cuda_runtime.h>
#include <cuda_fp16.h>
#include <cstdint>
#include <math.h>

#define BATCH 4
#define TLEN 1024
#define CDIM 1024
#define NHEAD 16
#define HDIM 64
#define NLAYER 8
#define VOCAB 32000
#define NTOK (BATCH * TLEN)
#define FF (4 * CDIM)

// ---------------- device scratch ----------------
__device__ float g_x[NTOK * CDIM];
__device__ unsigned short g_qkvb_h[NTOK * 3 * CDIM], g_qkvb_l[NTOK * CDIM];  // lo only for Q
__device__ unsigned short g_hb[NTOK * CDIM];
__device__ unsigned short g_ob[NTOK * CDIM];
__device__ unsigned short g_ffb[(size_t)NTOK * FF];
__device__ unsigned short g_wqkv_h[(size_t)NLAYER * 3 * CDIM * CDIM], g_wqkv_l[(size_t)NLAYER * 3 * CDIM * CDIM];
__device__ unsigned short g_wproj_h[(size_t)NLAYER * CDIM * CDIM], g_wproj_l[(size_t)NLAYER * CDIM * CDIM];
__device__ unsigned short g_w1_h[(size_t)NLAYER * FF * CDIM];
__device__ unsigned short g_w2_h[(size_t)NLAYER * CDIM * FF], g_w2_l[(size_t)NLAYER * CDIM * FF];
__device__ unsigned short g_wlm_h[(size_t)VOCAB * CDIM];

// ---------------- helpers ----------------
__device__ __forceinline__ uint32_t cvta_s(const void* p) {
    uint32_t a;
    asm("{ .reg .u64 t; cvta.to.shared.u64 t, %1; cvt.u32.u64 %0, t; }" : "=r"(a) : "l"(p));
    return a;
}
#define CP_ASYNC16(dst, src) \
    asm volatile("cp.async.cg.shared.global [%0], [%1], 16;" :: "r"(dst), "l"(src))
#define CP_COMMIT() asm volatile("cp.async.commit_group;" ::: "memory")
#define CP_WAIT(n)  asm volatile("cp.async.wait_group %0;" :: "n"(n) : "memory")

__device__ __forceinline__ void ldm_x4(uint32_t* r, uint32_t addr) {
    asm volatile("ldmatrix.sync.aligned.m8n8.x4.shared.b16 {%0,%1,%2,%3}, [%4];"
                 : "=r"(r[0]), "=r"(r[1]), "=r"(r[2]), "=r"(r[3]) : "r"(addr));
}
__device__ __forceinline__ void ldm_x4t(uint32_t* r, uint32_t addr) {
    asm volatile("ldmatrix.sync.aligned.m8n8.x4.trans.shared.b16 {%0,%1,%2,%3}, [%4];"
                 : "=r"(r[0]), "=r"(r[1]), "=r"(r[2]), "=r"(r[3]) : "r"(addr));
}
__device__ __forceinline__ void mma_f16(float* d, const uint32_t* a, const uint32_t* b) {
    asm volatile(
        "mma.sync.aligned.m16n8k16.row.col.f32.f16.f16.f32 "
        "{%0,%1,%2,%3}, {%4,%5,%6,%7}, {%8,%9}, {%0,%1,%2,%3};"
        : "+f"(d[0]), "+f"(d[1]), "+f"(d[2]), "+f"(d[3])
        : "r"(a[0]), "r"(a[1]), "r"(a[2]), "r"(a[3]), "r"(b[0]), "r"(b[1]));
}
__device__ __forceinline__ void hsplit(float v, unsigned short& h, unsigned short& l) {
    __half hb = __float2half_rn(v);
    __half lb = __float2half_rn(v - __half2float(hb));
    h = __half_as_ushort(hb);
    l = __half_as_ushort(lb);
}
__device__ __forceinline__ unsigned short h1(float v) {
    return __half_as_ushort(__float2half_rn(v));
}
__device__ __forceinline__ void pack2h(float a, float b, uint32_t& hi, uint32_t& lo) {
    unsigned short h0, l0, hh1, l1;
    hsplit(a, h0, l0);
    hsplit(b, hh1, l1);
    hi = (uint32_t)h0 | ((uint32_t)hh1 << 16);
    lo = (uint32_t)l0 | ((uint32_t)l1 << 16);
}

// ---------------- weight prep (transpose + fp16 hi/lo split) ----------------
__global__ void tsplit_qkv_kernel(const float* __restrict__ wq, const float* __restrict__ wk,
                                  const float* __restrict__ wv,
                                  unsigned short* __restrict__ dh, unsigned short* __restrict__ dl) {
    __shared__ float t[32][33];
    int n0 = blockIdx.x * 32, k0 = blockIdx.y * 32, l = blockIdx.z;
    int sel = n0 >> 10;
    const float* src = sel == 0 ? wq : (sel == 1 ? wk : wv);
    int within = n0 & 1023;
    int h = within >> 6, d0 = within & 63;
    const float* sp = src + ((size_t)(l * 16 + h) * 1024 + k0) * 64 + d0;
    int tx = threadIdx.x, ty = threadIdx.y;
    #pragma unroll
    for (int i = 0; i < 4; i++) t[ty + i * 8][tx] = sp[(size_t)(ty + i * 8) * 64 + tx];
    __syncthreads();
    size_t ob = (size_t)l * 3072 * 1024;
    #pragma unroll
    for (int i = 0; i < 4; i++) {
        int n = n0 + ty + i * 8, k = k0 + tx;
        unsigned short hh, ll;
        hsplit(t[tx][ty + i * 8], hh, ll);
        dh[ob + (size_t)n * 1024 + k] = hh;
        dl[ob + (size_t)n * 1024 + k] = ll;
    }
}
__global__ void tsplit_mat_kernel(const float* __restrict__ src,
                                  unsigned short* __restrict__ dh, unsigned short* __restrict__ dl,
                                  int K, int N) {
    __shared__ float t[32][33];
    int n0 = blockIdx.x * 32, k0 = blockIdx.y * 32;
    size_t l = blockIdx.z;
    const float* sp = src + l * (size_t)K * N;
    int tx = threadIdx.x, ty = threadIdx.y;
    #pragma unroll
    for (int i = 0; i < 4; i++) t[ty + i * 8][tx] = sp[(size_t)(k0 + ty + i * 8) * N + n0 + tx];
    __syncthreads();
    size_t ob = l * (size_t)K * N;
    #pragma unroll
    for (int i = 0; i < 4; i++) {
        int n = n0 + ty + i * 8, k = k0 + tx;
        unsigned short hh, ll;
        hsplit(t[tx][ty + i * 8], hh, ll);
        dh[ob + (size_t)n * K + k] = hh;
        if (dl) dl[ob + (size_t)n * K + k] = ll;
    }
}

// ---------------- embed ----------------
__global__ void embed_kernel(const int* __restrict__ idx, const float* __restrict__ tok,
                             const float* __restrict__ pos, float* __restrict__ x) {
    int row = blockIdx.x;
    int t = row & (TLEN - 1);
    int token = idx[row];
    const float4* te = (const float4*)(tok + (size_t)token * CDIM);
    const float4* pe = (const float4*)(pos + (size_t)t * CDIM);
    float4* xo = (float4*)(x + (size_t)row * CDIM);
    int i = threadIdx.x;
    float4 a = te[i], b = pe[i];
    a.x += b.x; a.y += b.y; a.z += b.z; a.w += b.w;
    xo[i] = a;
}

// ---------------- LayerNorm -> single fp16 (warp-per-row) ----------------
__global__ void ln_kernel(const float* __restrict__ x, const float* __restrict__ g,
                          const float* __restrict__ b, unsigned short* __restrict__ oh) {
    int warp = threadIdx.x >> 5, lane = threadIdx.x & 31;
    int row = blockIdx.x * 8 + warp;
    const float4* xr = (const float4*)(x + (size_t)row * CDIM);
    float4 v[8];
    float s = 0.f, ss = 0.f;
    #pragma unroll
    for (int i = 0; i < 8; i++) {
        v[i] = xr[lane + i * 32];
        s += v[i].x + v[i].y + v[i].z + v[i].w;
        ss += v[i].x * v[i].x + v[i].y * v[i].y + v[i].z * v[i].z + v[i].w * v[i].w;
    }
    #pragma unroll
    for (int o = 16; o > 0; o >>= 1) {
        s += __shfl_xor_sync(0xffffffffu, s, o);
        ss += __shfl_xor_sync(0xffffffffu, ss, o);
    }
    float mean = s * (1.0f / CDIM);
    float var = ss * (1.0f / CDIM) - mean * mean;
    float rstd = rsqrtf(var + 1e-5f);
    const float4* gp = (const float4*)g;
    const float4* bp = (const float4*)b;
    ushort4* op = (ushort4*)(oh + (size_t)row * CDIM);
    #pragma unroll
    for (int i = 0; i < 8; i++) {
        float4 gv = gp[lane + i * 32];
        float4 bv = bp[lane + i * 32];
        ushort4 hv;
        hv.x = h1((v[i].x - mean) * rstd * gv.x + bv.x);
        hv.y = h1((v[i].y - mean) * rstd * gv.y + bv.y);
        hv.z = h1((v[i].z - mean) * rstd * gv.z + bv.z);
        hv.w = h1((v[i].w - mean) * rstd * gv.w + bv.w);
        op[lane + i * 32] = hv;
    }
}

// ---------------- HMMA GEMM (hi/lo): D = A * (Wh[+Wl])^T ----------------
// 128x128, BK=32, warp tile 64x32, 3-stage, 1 sync/stage, 2 CTAs/SM.
#define RS 80
#define ARR_BYTES (128 * RS)
#define STAGE_BYTES (3 * ARR_BYTES)       // 30720 (A, Bh, Bl)
#define SMEM_GEMM (3 * STAGE_BYTES)       // 92160

__device__ __forceinline__ void gemm_load_stage(
    const unsigned short* __restrict__ A,
    const unsigned short* __restrict__ Bh, const unsigned short* __restrict__ Bl,
    int K, int m0, int n0, int k0, uint32_t smbase, int buf, int tid, int use_lo) {
    uint32_t sb = smbase + buf * STAGE_BYTES;
    #pragma unroll
    for (int it = 0; it < 6; it++) {
        int e = tid + it * 256;
        int arr = e >> 9;
        if (arr == 2 && !use_lo) continue;
        int idx = e & 511;
        int row = idx >> 2;
        int ch = idx & 3;
        const unsigned short* src = arr == 0 ? A : arr == 1 ? Bh : Bl;
        int r0 = (arr == 0) ? m0 : n0;
        const unsigned short* g = src + (size_t)(r0 + row) * K + k0 + ch * 8;
        CP_ASYNC16(sb + arr * ARR_BYTES + row * RS + ch * 16, g);
    }
}

__global__ __launch_bounds__(256)
void tgemm_kernel(const unsigned short* __restrict__ A,
                  const unsigned short* __restrict__ Bh, const unsigned short* __restrict__ Bl,
                  int K, int nlo,
                  float* __restrict__ Cf, unsigned short* __restrict__ Ch,
                  unsigned short* __restrict__ Cl, int locols, int ldlo,
                  const float* __restrict__ bias, const float* __restrict__ res,
                  int relu, int ldc) {
    extern __shared__ char smem[];
    uint32_t smbase = cvta_s(smem);
    int tid = threadIdx.x;
    int m0 = blockIdx.x * 128, n0 = blockIdx.y * 128;
    int use_lo = (n0 < nlo);
    int warp = tid >> 5, lane = tid & 31;
    int wm = (warp >> 2) * 64;
    int wn = (warp & 3) * 32;
    int arow = lane & 15;
    uint32_t asel = (uint32_t)(lane >> 4) << 4;
    int bnoff = ((lane >> 4) & 1) * 8 + (lane & 7);
    uint32_t bkoff = (uint32_t)((lane >> 3) & 1) << 4;

    float acc[4][4][4];
    #pragma unroll
    for (int i = 0; i < 4; i++)
        #pragma unroll
        for (int j = 0; j < 4; j++)
            #pragma unroll
            for (int q = 0; q < 4; q++) acc[i][j][q] = 0.f;

    int NS = K >> 5;
    gemm_load_stage(A, Bh, Bl, K, m0, n0, 0, smbase, 0, tid, use_lo);
    CP_COMMIT();
    gemm_load_stage(A, Bh, Bl, K, m0, n0, 32, smbase, 1, tid, use_lo);
    CP_COMMIT();

    int buf = 0;
    for (int s = 0; s < NS; s++) {
        if (s + 1 < NS) { CP_WAIT(1); } else { CP_WAIT(0); }
        __syncthreads();
        if (s + 2 < NS) {
            int pb = buf + 2; if (pb >= 3) pb -= 3;
            gemm_load_stage(A, Bh, Bl, K, m0, n0, (s + 2) << 5, smbase, pb, tid, use_lo);
            CP_COMMIT();
        }
        uint32_t sb = smbase + (uint32_t)buf * STAGE_BYTES;
        uint32_t sA = sb, sBh = sb + ARR_BYTES;
        #pragma unroll
        for (int kk = 0; kk < 2; kk++) {
            uint32_t kb = kk * 32;
            uint32_t af[4][4];
            #pragma unroll
            for (int i = 0; i < 4; i++) {
                uint32_t ra = sA + (uint32_t)(wm + i * 16 + arow) * RS + kb + asel;
                ldm_x4(af[i], ra);
            }
            #pragma unroll
            for (int j2 = 0; j2 < 2; j2++) {
                uint32_t bh4[4], bl4[4];
                uint32_t rb = sBh + (uint32_t)(wn + j2 * 16 + bnoff) * RS + kb + bkoff;
                ldm_x4(bh4, rb);
                if (use_lo) ldm_x4(bl4, rb + ARR_BYTES);
                #pragma unroll
                for (int i = 0; i < 4; i++) {
                    mma_f16(acc[i][2 * j2],     af[i], bh4);
                    mma_f16(acc[i][2 * j2 + 1], af[i], bh4 + 2);
                    if (use_lo) {
                        mma_f16(acc[i][2 * j2],     af[i], bl4);
                        mma_f16(acc[i][2 * j2 + 1], af[i], bl4 + 2);
                    }
                }
            }
        }
        if (++buf == 3) buf = 0;
    }

    int qr = lane >> 2;
    int qc = (lane & 3) * 2;
    #pragma unroll
    for (int i = 0; i < 4; i++) {
        #pragma unroll
        for (int j = 0; j < 4; j++) {
            int col = n0 + wn + j * 8 + qc;
            #pragma unroll
            for (int half = 0; half < 2; half++) {
                int row = m0 + wm + i * 16 + qr + half * 8;
                float v0 = acc[i][j][half * 2 + 0];
                float v1 = acc[i][j][half * 2 + 1];
                if (bias) {
                    float2 bv = *(const float2*)(bias + col);
                    v0 += bv.x; v1 += bv.y;
                }
                size_t base = (size_t)row * ldc + col;
                if (res) {
                    float2 e = *(const float2*)(res + base);
                    v0 += e.x; v1 += e.y;
                }
                if (relu) { v0 = fmaxf(v0, 0.f); v1 = fmaxf(v1, 0.f); }
                if (Cf) { float2 o = {v0, v1}; *(float2*)(Cf + base) = o; }
                if (Ch) {
                    __half hv0 = __float2half_rn(v0);
                    __half hv1 = __float2half_rn(v1);
                    ushort2 hv;
                    hv.x = __half_as_ushort(hv0);
                    hv.y = __half_as_ushort(hv1);
                    *(ushort2*)(Ch + base) = hv;
                    if (Cl && col < locols) {
                        ushort2 lv;
                        lv.x = h1(v0 - __half2float(hv0));
                        lv.y = h1(v1 - __half2float(hv1));
                        *(ushort2*)(Cl + (size_t)row * ldlo + col) = lv;
                    }
                }
            }
        }
    }
}

// ---------------- HMMA GEMM (hi-only): D = A * Wh^T ----------------
// 128x128, BK=64, warp tile 64x32, 3-stage, 1 sync/stage, 2 CTAs/SM (110.6 KB).
#define RS2 144
#define ARR2 (128 * RS2)                  // 18432
#define STAGE2 (2 * ARR2)                 // 36864 (A, Bh)
#define SMEM_GEMM2 (3 * STAGE2)           // 110592

__device__ __forceinline__ void gemm2_load_stage(
    const unsigned short* __restrict__ A, const unsigned short* __restrict__ Bh,
    int K, int m0, int n0, int k0, uint32_t smbase, int buf, int tid) {
    uint32_t sb = smbase + buf * STAGE2;
    #pragma unroll
    for (int it = 0; it < 8; it++) {
        int e = tid + it * 256;            // 0..2047
        int arr = e >> 10;                 // 0=A 1=Bh
        int idx = e & 1023;
        int row = idx >> 3;
        int ch = idx & 7;
        const unsigned short* src = arr == 0 ? A : Bh;
        int r0 = (arr == 0) ? m0 : n0;
        const unsigned short* g = src + (size_t)(r0 + row) * K + k0 + ch * 8;
        CP_ASYNC16(sb + arr * ARR2 + row * RS2 + ch * 16, g);
    }
}

__global__ __launch_bounds__(256)
void tgemm_hi_kernel(const unsigned short* __restrict__ A, const unsigned short* __restrict__ Bh,
                     int K,
                     float* __restrict__ Cf, unsigned short* __restrict__ Ch,
                     const float* __restrict__ bias, int relu, int ldc) {
    extern __shared__ char smem[];
    uint32_t smbase = cvta_s(smem);
    int tid = threadIdx.x;
    int m0 = blockIdx.x * 128, n0 = blockIdx.y * 128;
    int warp = tid >> 5, lane = tid & 31;
    int wm = (warp >> 2) * 64;
    int wn = (warp & 3) * 32;
    int arow = lane & 15;
    uint32_t asel = (uint32_t)(lane >> 4) << 4;
    int bnoff = ((lane >> 4) & 1) * 8 + (lane & 7);
    uint32_t bkoff = (uint32_t)((lane >> 3) & 1) << 4;

    float acc[4][4][4];
    #pragma unroll
    for (int i = 0; i < 4; i++)
        #pragma unroll
        for (int j = 0; j < 4; j++)
            #pragma unroll
            for (int q = 0; q < 4; q++) acc[i][j][q] = 0.f;

    int NS = K >> 6;
    gemm2_load_stage(A, Bh, K, m0, n0, 0, smbase, 0, tid);
    CP_COMMIT();
    gemm2_load_stage(A, Bh, K, m0, n0, 64, smbase, 1, tid);
    CP_COMMIT();

    int buf = 0;
    for (int s = 0; s < NS; s++) {
        if (s + 1 < NS) { CP_WAIT(1); } else { CP_WAIT(0); }
        __syncthreads();
        if (s + 2 < NS) {
            int pb = buf + 2; if (pb >= 3) pb -= 3;
            gemm2_load_stage(A, Bh, K, m0, n0, (s + 2) << 6, smbase, pb, tid);
            CP_COMMIT();
        }
        uint32_t sb = smbase + (uint32_t)buf * STAGE2;
        uint32_t sA = sb, sB = sb + ARR2;
        #pragma unroll
        for (int kk = 0; kk < 4; kk++) {
            uint32_t kb = kk * 32;
            uint32_t af[4][4];
            #pragma unroll
            for (int i = 0; i < 4; i++) {
                uint32_t ra = sA + (uint32_t)(wm + i * 16 + arow) * RS2 + kb + asel;
                ldm_x4(af[i], ra);
            }
            #pragma unroll
            for (int j2 = 0; j2 < 2; j2++) {
                uint32_t bh4[4];
                uint32_t rb = sB + (uint32_t)(wn + j2 * 16 + bnoff) * RS2 + kb + bkoff;
                ldm_x4(bh4, rb);
                #pragma unroll
                for (int i = 0; i < 4; i++) {
                    mma_f16(acc[i][2 * j2],     af[i], bh4);
                    mma_f16(acc[i][2 * j2 + 1], af[i], bh4 + 2);
                }
            }
        }
        if (++buf == 3) buf = 0;
    }

    int qr = lane >> 2;
    int qc = (lane & 3) * 2;
    #pragma unroll
    for (int i = 0; i < 4; i++) {
        #pragma unroll
        for (int j = 0; j < 4; j++) {
            int col = n0 + wn + j * 8 + qc;
            #pragma unroll
            for (int half = 0; half < 2; half++) {
                int row = m0 + wm + i * 16 + qr + half * 8;
                float v0 = acc[i][j][half * 2 + 0];
                float v1 = acc[i][j][half * 2 + 1];
                if (bias) {
                    float2 bv = *(const float2*)(bias + col);
                    v0 += bv.x; v1 += bv.y;
                }
                if (relu) { v0 = fmaxf(v0, 0.f); v1 = fmaxf(v1, 0.f); }
                size_t base = (size_t)row * ldc + col;
                if (Cf) { float2 o = {v0, v1}; *(float2*)(Cf + base) = o; }
                if (Ch) {
                    ushort2 hv;
                    hv.x = h1(v0);
                    hv.y = h1(v1);
                    *(ushort2*)(Ch + base) = hv;
                }
            }
        }
    }
}

// ---------------- fused flash attention (64-row tiles, 128 thr) ----------------
#define FRS 144
#define FARR (64 * FRS)
#define FKV_STAGE (2 * FARR)
#define SMEM_FLASH (2 * FARR + 2 * FKV_STAGE)

__device__ __forceinline__ void flash_load_q(
    const unsigned short* __restrict__ qh, const unsigned short* __restrict__ ql,
    int rowbase, int colbase, uint32_t smbase, int tid) {
    #pragma unroll
    for (int it = 0; it < 8; it++) {
        int e = tid + it * 128;
        int arr = e >> 9;
        int idx = e & 511;
        int row = idx >> 3, ch = idx & 7;
        const unsigned short* g;
        if (arr == 0)
            g = qh + (size_t)(rowbase + row) * (3 * CDIM) + colbase + ch * 8;
        else
            g = ql + (size_t)(rowbase + row) * CDIM + colbase + ch * 8;
        CP_ASYNC16(smbase + arr * FARR + row * FRS + ch * 16, g);
    }
}
__device__ __forceinline__ void flash_load_kv(
    const unsigned short* __restrict__ qh,
    int rowbase, int kcol, int vcol, uint32_t sb, int tid) {
    #pragma unroll
    for (int it = 0; it < 8; it++) {
        int e = tid + it * 128;
        int arr = e >> 9;
        int idx = e & 511;
        int row = idx >> 3, ch = idx & 7;
        int col = (arr == 0) ? kcol : vcol;
        const unsigned short* g = qh + (size_t)(rowbase + row) * (3 * CDIM) + col + ch * 8;
        CP_ASYNC16(sb + arr * FARR + row * FRS + ch * 16, g);
    }
}

__global__ __launch_bounds__(128)
void flash_kernel(const unsigned short* __restrict__ qh, const unsigned short* __restrict__ ql,
                  unsigned short* __restrict__ ob) {
    extern __shared__ char smem[];
    uint32_t smbase = cvta_s(smem);
    int tid = threadIdx.x;
    int tt = (int)gridDim.x - 1 - (int)blockIdx.x;
    int bh = blockIdx.y;
    int b = bh >> 4, h = bh & 15;
    int t0 = tt * 64;
    int qrowbase = b * TLEN + t0;
    int qcol = h * HDIM;
    int kcol = CDIM + h * HDIM;
    int vcol = 2 * CDIM + h * HDIM;

    int warp = tid >> 5, lane = tid & 31;
    int wm = warp * 16;
    int arow = lane & 15;
    uint32_t asel = (uint32_t)(lane >> 4) << 4;
    int ln16 = lane & 15;
    int bnoff = ((lane >> 4) & 1) * 8 + (lane & 7);
    uint32_t bkoff = (uint32_t)((lane >> 3) & 1) << 4;
    int vrowoff = (lane & 7) + ((lane >> 3) & 1) * 8;
    int vcp = (lane >> 4) & 1;
    int qr = lane >> 2;
    int qc = (lane & 3) * 2;

    float O[8][4];
    #pragma unroll
    for (int j = 0; j < 8; j++)
        #pragma unroll
        for (int q = 0; q < 4; q++) O[j][q] = 0.f;
    float m0r = -1e30f, m1r = -1e30f, l0 = 0.f, l1 = 0.f;

    int NS = tt + 1;
    uint32_t kvbase = smbase + 2 * FARR;

    flash_load_q(qh, ql, qrowbase, qcol, smbase, tid);
    flash_load_kv(qh, b * TLEN, kcol, vcol, kvbase, tid);
    CP_COMMIT();
    if (NS > 1) {
        flash_load_kv(qh, b * TLEN + 64, kcol, vcol, kvbase + FKV_STAGE, tid);
        CP_COMMIT();
    }

    for (int st = 0; st < NS; st++) {
        if (st + 1 < NS) { CP_WAIT(1); } else { CP_WAIT(0); }
        __syncthreads();
        uint32_t sKV = kvbase + (st & 1) * FKV_STAGE;
        uint32_t sK = sKV, sV = sKV + FARR;

        float S[8][4];
        #pragma unroll
        for (int j = 0; j < 8; j++)
            #pragma unroll
            for (int q = 0; q < 4; q++) S[j][q] = 0.f;
        #pragma unroll
        for (int d = 0; d < 4; d++) {
            uint32_t kb = d * 32;
            uint32_t ah[4], al[4];
            uint32_t ra = smbase + (uint32_t)(wm + arow) * FRS + kb + asel;
            ldm_x4(ah, ra);
            ldm_x4(al, ra + FARR);
            #pragma unroll
            for (int j2 = 0; j2 < 4; j2++) {
                uint32_t bf4[4];
                uint32_t rb = sK + (uint32_t)(j2 * 16 + bnoff) * FRS + kb + bkoff;
                ldm_x4(bf4, rb);
                mma_f16(S[2 * j2],     ah, bf4);
                mma_f16(S[2 * j2],     al, bf4);
                mma_f16(S[2 * j2 + 1], ah, bf4 + 2);
                mma_f16(S[2 * j2 + 1], al, bf4 + 2);
            }
        }
        if (st == tt) {
            int r0 = wm + qr, r1 = wm + qr + 8;
            #pragma unroll
            for (int j = 0; j < 8; j++) {
                int c0 = j * 8 + qc;
                S[j][0] = (c0     > r0) ? -1e30f : S[j][0] * 0.125f;
                S[j][1] = (c0 + 1 > r0) ? -1e30f : S[j][1] * 0.125f;
                S[j][2] = (c0     > r1) ? -1e30f : S[j][2] * 0.125f;
                S[j][3] = (c0 + 1 > r1) ? -1e30f : S[j][3] * 0.125f;
            }
        } else {
            #pragma unroll
            for (int j = 0; j < 8; j++)
                #pragma unroll
                for (int q = 0; q < 4; q++) S[j][q] *= 0.125f;
        }
        float mx0 = -1e30f, mx1 = -1e30f;
        #pragma unroll
        for (int j = 0; j < 8; j++) {
            mx0 = fmaxf(mx0, fmaxf(S[j][0], S[j][1]));
            mx1 = fmaxf(mx1, fmaxf(S[j][2], S[j][3]));
        }
        mx0 = fmaxf(mx0, __shfl_xor_sync(0xffffffffu, mx0, 1));
        mx0 = fmaxf(mx0, __shfl_xor_sync(0xffffffffu, mx0, 2));
        mx1 = fmaxf(mx1, __shfl_xor_sync(0xffffffffu, mx1, 1));
        mx1 = fmaxf(mx1, __shfl_xor_sync(0xffffffffu, mx1, 2));
        float mn0 = fmaxf(m0r, mx0), mn1 = fmaxf(m1r, mx1);
        float c0 = __expf(m0r - mn0), c1 = __expf(m1r - mn1);
        float rs0 = 0.f, rs1 = 0.f;
        #pragma unroll
        for (int j = 0; j < 8; j++) {
            S[j][0] = __expf(S[j][0] - mn0);
            S[j][1] = __expf(S[j][1] - mn0);
            S[j][2] = __expf(S[j][2] - mn1);
            S[j][3] = __expf(S[j][3] - mn1);
            rs0 += S[j][0] + S[j][1];
            rs1 += S[j][2] + S[j][3];
        }
        rs0 += __shfl_xor_sync(0xffffffffu, rs0, 1);
        rs0 += __shfl_xor_sync(0xffffffffu, rs0, 2);
        rs1 += __shfl_xor_sync(0xffffffffu, rs1, 1);
        rs1 += __shfl_xor_sync(0xffffffffu, rs1, 2);
        l0 = l0 * c0 + rs0;
        l1 = l1 * c1 + rs1;
        m0r = mn0; m1r = mn1;
        #pragma unroll
        for (int j = 0; j < 8; j++) {
            O[j][0] *= c0; O[j][1] *= c0;
            O[j][2] *= c1; O[j][3] *= c1;
        }
        #pragma unroll
        for (int kk = 0; kk < 4; kk++) {
            int j0 = 2 * kk, j1 = 2 * kk + 1;
            uint32_t pah[4], pal[4];
            pack2h(S[j0][0], S[j0][1], pah[0], pal[0]);
            pack2h(S[j0][2], S[j0][3], pah[1], pal[1]);
            pack2h(S[j1][0], S[j1][1], pah[2], pal[2]);
            pack2h(S[j1][2], S[j1][3], pah[3], pal[3]);
            uint32_t vrow = (uint32_t)(kk * 16 + vrowoff);
            #pragma unroll
            for (int jd2 = 0; jd2 < 4; jd2++) {
                uint32_t vf4[4];
                uint32_t rv = sV + vrow * FRS + (uint32_t)(jd2 * 2 + vcp) * 16;
                ldm_x4t(vf4, rv);
                mma_f16(O[2 * jd2],     pah, vf4);
                mma_f16(O[2 * jd2],     pal, vf4);
                mma_f16(O[2 * jd2 + 1], pah, vf4 + 2);
                mma_f16(O[2 * jd2 + 1], pal, vf4 + 2);
            }
        }
        __syncthreads();
        if (st + 2 < NS) {
            flash_load_kv(qh, b * TLEN + (st + 2) * 64, kcol, vcol,
                          kvbase + (st & 1) * FKV_STAGE, tid);
            CP_COMMIT();
        }
    }

    float inv0 = 1.f / l0, inv1 = 1.f / l1;
    int row0 = b * TLEN + t0 + wm + qr;
    #pragma unroll
    for (int jd = 0; jd < 8; jd++) {
        int col = qcol + jd * 8 + qc;
        ushort2 hv;
        hv.x = h1(O[jd][0] * inv0);
        hv.y = h1(O[jd][1] * inv0);
        *(ushort2*)(ob + (size_t)row0 * CDIM + col) = hv;
        hv.x = h1(O[jd][2] * inv1);
        hv.y = h1(O[jd][3] * inv1);
        *(ushort2*)(ob + (size_t)(row0 + 8) * CDIM + col) = hv;
    }
}

// ---------------- host ----------------
extern "C" void kernel_launch(void* const* d_in, const int* in_sizes, int n_in,
                              void* d_out, int out_size) {
    const int* idx = (const int*)d_in[0];
    const float* tok = (const float*)d_in[1];
    const float* pos = (const float*)d_in[2];
    const float* wq = (const float*)d_in[3];
    const float* wk = (const float*)d_in[4];
    const float* wv = (const float*)d_in[5];
    const float* wproj = (const float*)d_in[6];
    const float* bproj = (const float*)d_in[7];
    const float* ln1g = (const float*)d_in[8];
    const float* ln1b = (const float*)d_in[9];
    const float* ln2g = (const float*)d_in[10];
    const float* ln2b = (const float*)d_in[11];
    const float* w1 = (const float*)d_in[12];
    const float* b1 = (const float*)d_in[13];
    const float* w2 = (const float*)d_in[14];
    const float* b2 = (const float*)d_in[15];
    const float* lnfg = (const float*)d_in[16];
    const float* lnfb = (const float*)d_in[17];
    const float* wlm = (const float*)d_in[18];
    const float* blm = (const float*)d_in[19];
    float* out = (float*)d_out;

    float* px;
    unsigned short *pqkvb_h, *pqkvb_l, *phb, *pob, *pffb;
    unsigned short *pwqkv_h, *pwqkv_l, *pwproj_h, *pwproj_l;
    unsigned short *pw1_h, *pw2_h, *pw2_l, *pwlm_h;
    cudaGetSymbolAddress((void**)&px, g_x);
    cudaGetSymbolAddress((void**)&pqkvb_h, g_qkvb_h);
    cudaGetSymbolAddress((void**)&pqkvb_l, g_qkvb_l);
    cudaGetSymbolAddress((void**)&phb, g_hb);
    cudaGetSymbolAddress((void**)&pob, g_ob);
    cudaGetSymbolAddress((void**)&pffb, g_ffb);
    cudaGetSymbolAddress((void**)&pwqkv_h, g_wqkv_h);
    cudaGetSymbolAddress((void**)&pwqkv_l, g_wqkv_l);
    cudaGetSymbolAddress((void**)&pwproj_h, g_wproj_h);
    cudaGetSymbolAddress((void**)&pwproj_l, g_wproj_l);
    cudaGetSymbolAddress((void**)&pw1_h, g_w1_h);
    cudaGetSymbolAddress((void**)&pw2_h, g_w2_h);
    cudaGetSymbolAddress((void**)&pw2_l, g_w2_l);
    cudaGetSymbolAddress((void**)&pwlm_h, g_wlm_h);

    cudaFuncSetAttribute(tgemm_kernel, cudaFuncAttributeMaxDynamicSharedMemorySize, SMEM_GEMM);
    cudaFuncSetAttribute(tgemm_hi_kernel, cudaFuncAttributeMaxDynamicSharedMemorySize, SMEM_GEMM2);
    cudaFuncSetAttribute(flash_kernel, cudaFuncAttributeMaxDynamicSharedMemorySize, SMEM_FLASH);

    dim3 tb(32, 8);
    tsplit_qkv_kernel<<<dim3(96, 32, 8), tb>>>(wq, wk, wv, pwqkv_h, pwqkv_l);
    tsplit_mat_kernel<<<dim3(32, 32, 8), tb>>>(wproj, pwproj_h, pwproj_l, CDIM, CDIM);
    tsplit_mat_kernel<<<dim3(128, 32, 8), tb>>>(w1, pw1_h, nullptr, CDIM, FF);
    tsplit_mat_kernel<<<dim3(32, 128, 8), tb>>>(w2, pw2_h, pw2_l, FF, CDIM);
    tsplit_mat_kernel<<<dim3(1000, 32, 1), tb>>>(wlm, pwlm_h, nullptr, CDIM, VOCAB);

    embed_kernel<<<NTOK, 256>>>(idx, tok, pos, px);

    for (int l = 0; l < NLAYER; l++) {
        ln_kernel<<<NTOK / 8, 256>>>(px, ln1g + (size_t)l * CDIM, ln1b + (size_t)l * CDIM, phb);
        tgemm_kernel<<<dim3(32, 24), 256, SMEM_GEMM>>>(
            phb, pwqkv_h + (size_t)l * 3072 * 1024, pwqkv_l + (size_t)l * 3072 * 1024,
            CDIM, CDIM, nullptr, pqkvb_h, pqkvb_l, CDIM, CDIM, nullptr, nullptr, 0, 3 * CDIM);
        flash_kernel<<<dim3(16, BATCH * NHEAD), 128, SMEM_FLASH>>>(pqkvb_h, pqkvb_l, pob);
        tgemm_kernel<<<dim3(32, 8), 256, SMEM_GEMM>>>(
            pob, pwproj_h + (size_t)l * CDIM * CDIM, pwproj_l + (size_t)l * CDIM * CDIM,
            CDIM, CDIM, px, nullptr, nullptr, 0, 0, bproj + (size_t)l * CDIM, px, 0, CDIM);
        ln_kernel<<<NTOK / 8, 256>>>(px, ln2g + (size_t)l * CDIM, ln2b + (size_t)l * CDIM, phb);
        // MLP up: hi-only GEMM (BK=64, fewer syncs)
        tgemm_hi_kernel<<<dim3(32, 32), 256, SMEM_GEMM2>>>(
            phb, pw1_h + (size_t)l * FF * CDIM, CDIM,
            nullptr, pffb, b1 + (size_t)l * FF, 1, FF);
        tgemm_kernel<<<dim3(32, 8), 256, SMEM_GEMM>>>(
            pffb, pw2_h + (size_t)l * CDIM * FF, pw2_l + (size_t)l * CDIM * FF,
            FF, CDIM, px, nullptr, nullptr, 0, 0, b2 + (size_t)l * CDIM, px, 0, CDIM);
    }
    ln_kernel<<<NTOK / 8, 256>>>(px, lnfg, lnfb, phb);
    // LM head: hi-only GEMM
    tgemm_hi_kernel<<<dim3(32, 250), 256, SMEM_GEMM2>>>(
        phb, pwlm_h, CDIM, out, nullptr, blm, 0, VOCAB);
}

// round 16
// speedup vs baseline: 1.4652x; 1.0406x over previous
#include <cuda_runtime.h>
#include <cuda_fp16.h>
#include <cstdint>
#include <math.h>

#define BATCH 4
#define TLEN 1024
#define CDIM 1024
#define NHEAD 16
#define HDIM 64
#define NLAYER 8
#define VOCAB 32000
#define NTOK (BATCH * TLEN)
#define FF (4 * CDIM)

// ---------------- device scratch ----------------
__device__ float g_x[NTOK * CDIM];
__device__ unsigned short g_qkvb_h[NTOK * 3 * CDIM], g_qkvb_l[NTOK * CDIM];  // lo only for Q
__device__ unsigned short g_hb[NTOK * CDIM];
__device__ unsigned short g_ob[NTOK * CDIM];
__device__ unsigned short g_ffb[(size_t)NTOK * FF];
__device__ unsigned short g_wqkv_h[(size_t)NLAYER * 3 * CDIM * CDIM], g_wqkv_l[(size_t)NLAYER * 3 * CDIM * CDIM];
__device__ unsigned short g_wproj_h[(size_t)NLAYER * CDIM * CDIM], g_wproj_l[(size_t)NLAYER * CDIM * CDIM];
__device__ unsigned short g_w1_h[(size_t)NLAYER * FF * CDIM];
__device__ unsigned short g_w2_h[(size_t)NLAYER * CDIM * FF], g_w2_l[(size_t)NLAYER * CDIM * FF];
__device__ unsigned short g_wlm_h[(size_t)VOCAB * CDIM];

// ---------------- helpers ----------------
__device__ __forceinline__ uint32_t cvta_s(const void* p) {
    uint32_t a;
    asm("{ .reg .u64 t; cvta.to.shared.u64 t, %1; cvt.u32.u64 %0, t; }" : "=r"(a) : "l"(p));
    return a;
}
#define CP_ASYNC16(dst, src) \
    asm volatile("cp.async.cg.shared.global [%0], [%1], 16;" :: "r"(dst), "l"(src))
#define CP_COMMIT() asm volatile("cp.async.commit_group;" ::: "memory")
#define CP_WAIT(n)  asm volatile("cp.async.wait_group %0;" :: "n"(n) : "memory")

__device__ __forceinline__ void ldm_x4(uint32_t* r, uint32_t addr) {
    asm volatile("ldmatrix.sync.aligned.m8n8.x4.shared.b16 {%0,%1,%2,%3}, [%4];"
                 : "=r"(r[0]), "=r"(r[1]), "=r"(r[2]), "=r"(r[3]) : "r"(addr));
}
__device__ __forceinline__ void ldm_x4t(uint32_t* r, uint32_t addr) {
    asm volatile("ldmatrix.sync.aligned.m8n8.x4.trans.shared.b16 {%0,%1,%2,%3}, [%4];"
                 : "=r"(r[0]), "=r"(r[1]), "=r"(r[2]), "=r"(r[3]) : "r"(addr));
}
__device__ __forceinline__ void mma_f16(float* d, const uint32_t* a, const uint32_t* b) {
    asm volatile(
        "mma.sync.aligned.m16n8k16.row.col.f32.f16.f16.f32 "
        "{%0,%1,%2,%3}, {%4,%5,%6,%7}, {%8,%9}, {%0,%1,%2,%3};"
        : "+f"(d[0]), "+f"(d[1]), "+f"(d[2]), "+f"(d[3])
        : "r"(a[0]), "r"(a[1]), "r"(a[2]), "r"(a[3]), "r"(b[0]), "r"(b[1]));
}
__device__ __forceinline__ void hsplit(float v, unsigned short& h, unsigned short& l) {
    __half hb = __float2half_rn(v);
    __half lb = __float2half_rn(v - __half2float(hb));
    h = __half_as_ushort(hb);
    l = __half_as_ushort(lb);
}
__device__ __forceinline__ unsigned short h1(float v) {
    return __half_as_ushort(__float2half_rn(v));
}
__device__ __forceinline__ void pack2h(float a, float b, uint32_t& hi, uint32_t& lo) {
    unsigned short h0, l0, hh1, l1;
    hsplit(a, h0, l0);
    hsplit(b, hh1, l1);
    hi = (uint32_t)h0 | ((uint32_t)hh1 << 16);
    lo = (uint32_t)l0 | ((uint32_t)l1 << 16);
}

// ---------------- weight prep (transpose + fp16 hi/lo split) ----------------
__global__ void tsplit_qkv_kernel(const float* __restrict__ wq, const float* __restrict__ wk,
                                  const float* __restrict__ wv,
                                  unsigned short* __restrict__ dh, unsigned short* __restrict__ dl) {
    __shared__ float t[32][33];
    int n0 = blockIdx.x * 32, k0 = blockIdx.y * 32, l = blockIdx.z;
    int sel = n0 >> 10;
    const float* src = sel == 0 ? wq : (sel == 1 ? wk : wv);
    int within = n0 & 1023;
    int h = within >> 6, d0 = within & 63;
    const float* sp = src + ((size_t)(l * 16 + h) * 1024 + k0) * 64 + d0;
    int tx = threadIdx.x, ty = threadIdx.y;
    #pragma unroll
    for (int i = 0; i < 4; i++) t[ty + i * 8][tx] = sp[(size_t)(ty + i * 8) * 64 + tx];
    __syncthreads();
    size_t ob = (size_t)l * 3072 * 1024;
    #pragma unroll
    for (int i = 0; i < 4; i++) {
        int n = n0 + ty + i * 8, k = k0 + tx;
        unsigned short hh, ll;
        hsplit(t[tx][ty + i * 8], hh, ll);
        dh[ob + (size_t)n * 1024 + k] = hh;
        dl[ob + (size_t)n * 1024 + k] = ll;
    }
}
__global__ void tsplit_mat_kernel(const float* __restrict__ src,
                                  unsigned short* __restrict__ dh, unsigned short* __restrict__ dl,
                                  int K, int N) {
    __shared__ float t[32][33];
    int n0 = blockIdx.x * 32, k0 = blockIdx.y * 32;
    size_t l = blockIdx.z;
    const float* sp = src + l * (size_t)K * N;
    int tx = threadIdx.x, ty = threadIdx.y;
    #pragma unroll
    for (int i = 0; i < 4; i++) t[ty + i * 8][tx] = sp[(size_t)(k0 + ty + i * 8) * N + n0 + tx];
    __syncthreads();
    size_t ob = l * (size_t)K * N;
    #pragma unroll
    for (int i = 0; i < 4; i++) {
        int n = n0 + ty + i * 8, k = k0 + tx;
        unsigned short hh, ll;
        hsplit(t[tx][ty + i * 8], hh, ll);
        dh[ob + (size_t)n * K + k] = hh;
        if (dl) dl[ob + (size_t)n * K + k] = ll;
    }
}

// ---------------- embed ----------------
__global__ void embed_kernel(const int* __restrict__ idx, const float* __restrict__ tok,
                             const float* __restrict__ pos, float* __restrict__ x) {
    int row = blockIdx.x;
    int t = row & (TLEN - 1);
    int token = idx[row];
    const float4* te = (const float4*)(tok + (size_t)token * CDIM);
    const float4* pe = (const float4*)(pos + (size_t)t * CDIM);
    float4* xo = (float4*)(x + (size_t)row * CDIM);
    int i = threadIdx.x;
    float4 a = te[i], b = pe[i];
    a.x += b.x; a.y += b.y; a.z += b.z; a.w += b.w;
    xo[i] = a;
}

// ---------------- LayerNorm -> single fp16 (warp-per-row) ----------------
__global__ void ln_kernel(const float* __restrict__ x, const float* __restrict__ g,
                          const float* __restrict__ b, unsigned short* __restrict__ oh) {
    int warp = threadIdx.x >> 5, lane = threadIdx.x & 31;
    int row = blockIdx.x * 8 + warp;
    const float4* xr = (const float4*)(x + (size_t)row * CDIM);
    float4 v[8];
    float s = 0.f, ss = 0.f;
    #pragma unroll
    for (int i = 0; i < 8; i++) {
        v[i] = xr[lane + i * 32];
        s += v[i].x + v[i].y + v[i].z + v[i].w;
        ss += v[i].x * v[i].x + v[i].y * v[i].y + v[i].z * v[i].z + v[i].w * v[i].w;
    }
    #pragma unroll
    for (int o = 16; o > 0; o >>= 1) {
        s += __shfl_xor_sync(0xffffffffu, s, o);
        ss += __shfl_xor_sync(0xffffffffu, ss, o);
    }
    float mean = s * (1.0f / CDIM);
    float var = ss * (1.0f / CDIM) - mean * mean;
    float rstd = rsqrtf(var + 1e-5f);
    const float4* gp = (const float4*)g;
    const float4* bp = (const float4*)b;
    ushort4* op = (ushort4*)(oh + (size_t)row * CDIM);
    #pragma unroll
    for (int i = 0; i < 8; i++) {
        float4 gv = gp[lane + i * 32];
        float4 bv = bp[lane + i * 32];
        ushort4 hv;
        hv.x = h1((v[i].x - mean) * rstd * gv.x + bv.x);
        hv.y = h1((v[i].y - mean) * rstd * gv.y + bv.y);
        hv.z = h1((v[i].z - mean) * rstd * gv.z + bv.z);
        hv.w = h1((v[i].w - mean) * rstd * gv.w + bv.w);
        op[lane + i * 32] = hv;
    }
}

// ---------------- HMMA GEMM (hi/lo): D = A * (Wh[+Wl])^T ----------------
// 128x128, BK=32, warp tile 64x32, 3-stage, 1 sync/stage, 2 CTAs/SM.
#define RS 80
#define ARR_BYTES (128 * RS)
#define STAGE_BYTES (3 * ARR_BYTES)       // 30720 (A, Bh, Bl)
#define SMEM_GEMM (3 * STAGE_BYTES)       // 92160

__device__ __forceinline__ void gemm_load_stage(
    const unsigned short* __restrict__ A,
    const unsigned short* __restrict__ Bh, const unsigned short* __restrict__ Bl,
    int K, int m0, int n0, int k0, uint32_t smbase, int buf, int tid, int use_lo) {
    uint32_t sb = smbase + buf * STAGE_BYTES;
    #pragma unroll
    for (int it = 0; it < 6; it++) {
        int e = tid + it * 256;
        int arr = e >> 9;
        if (arr == 2 && !use_lo) continue;
        int idx = e & 511;
        int row = idx >> 2;
        int ch = idx & 3;
        const unsigned short* src = arr == 0 ? A : arr == 1 ? Bh : Bl;
        int r0 = (arr == 0) ? m0 : n0;
        const unsigned short* g = src + (size_t)(r0 + row) * K + k0 + ch * 8;
        CP_ASYNC16(sb + arr * ARR_BYTES + row * RS + ch * 16, g);
    }
}

__global__ __launch_bounds__(256)
void tgemm_kernel(const unsigned short* __restrict__ A,
                  const unsigned short* __restrict__ Bh, const unsigned short* __restrict__ Bl,
                  int K, int nlo,
                  float* __restrict__ Cf, unsigned short* __restrict__ Ch,
                  unsigned short* __restrict__ Cl, int locols, int ldlo,
                  const float* __restrict__ bias, const float* __restrict__ res,
                  int relu, int ldc) {
    extern __shared__ char smem[];
    uint32_t smbase = cvta_s(smem);
    int tid = threadIdx.x;
    int m0 = blockIdx.x * 128, n0 = blockIdx.y * 128;
    int use_lo = (n0 < nlo);
    int warp = tid >> 5, lane = tid & 31;
    int wm = (warp >> 2) * 64;
    int wn = (warp & 3) * 32;
    int arow = lane & 15;
    uint32_t asel = (uint32_t)(lane >> 4) << 4;
    int bnoff = ((lane >> 4) & 1) * 8 + (lane & 7);
    uint32_t bkoff = (uint32_t)((lane >> 3) & 1) << 4;

    float acc[4][4][4];
    #pragma unroll
    for (int i = 0; i < 4; i++)
        #pragma unroll
        for (int j = 0; j < 4; j++)
            #pragma unroll
            for (int q = 0; q < 4; q++) acc[i][j][q] = 0.f;

    int NS = K >> 5;
    gemm_load_stage(A, Bh, Bl, K, m0, n0, 0, smbase, 0, tid, use_lo);
    CP_COMMIT();
    gemm_load_stage(A, Bh, Bl, K, m0, n0, 32, smbase, 1, tid, use_lo);
    CP_COMMIT();

    int buf = 0;
    for (int s = 0; s < NS; s++) {
        if (s + 1 < NS) { CP_WAIT(1); } else { CP_WAIT(0); }
        __syncthreads();
        if (s + 2 < NS) {
            int pb = buf + 2; if (pb >= 3) pb -= 3;
            gemm_load_stage(A, Bh, Bl, K, m0, n0, (s + 2) << 5, smbase, pb, tid, use_lo);
            CP_COMMIT();
        }
        uint32_t sb = smbase + (uint32_t)buf * STAGE_BYTES;
        uint32_t sA = sb, sBh = sb + ARR_BYTES;
        #pragma unroll
        for (int kk = 0; kk < 2; kk++) {
            uint32_t kb = kk * 32;
            uint32_t af[4][4];
            #pragma unroll
            for (int i = 0; i < 4; i++) {
                uint32_t ra = sA + (uint32_t)(wm + i * 16 + arow) * RS + kb + asel;
                ldm_x4(af[i], ra);
            }
            #pragma unroll
            for (int j2 = 0; j2 < 2; j2++) {
                uint32_t bh4[4], bl4[4];
                uint32_t rb = sBh + (uint32_t)(wn + j2 * 16 + bnoff) * RS + kb + bkoff;
                ldm_x4(bh4, rb);
                if (use_lo) ldm_x4(bl4, rb + ARR_BYTES);
                #pragma unroll
                for (int i = 0; i < 4; i++) {
                    mma_f16(acc[i][2 * j2],     af[i], bh4);
                    mma_f16(acc[i][2 * j2 + 1], af[i], bh4 + 2);
                    if (use_lo) {
                        mma_f16(acc[i][2 * j2],     af[i], bl4);
                        mma_f16(acc[i][2 * j2 + 1], af[i], bl4 + 2);
                    }
                }
            }
        }
        if (++buf == 3) buf = 0;
    }

    int qr = lane >> 2;
    int qc = (lane & 3) * 2;
    #pragma unroll
    for (int i = 0; i < 4; i++) {
        #pragma unroll
        for (int j = 0; j < 4; j++) {
            int col = n0 + wn + j * 8 + qc;
            #pragma unroll
            for (int half = 0; half < 2; half++) {
                int row = m0 + wm + i * 16 + qr + half * 8;
                float v0 = acc[i][j][half * 2 + 0];
                float v1 = acc[i][j][half * 2 + 1];
                if (bias) {
                    float2 bv = *(const float2*)(bias + col);
                    v0 += bv.x; v1 += bv.y;
                }
                size_t base = (size_t)row * ldc + col;
                if (res) {
                    float2 e = *(const float2*)(res + base);
                    v0 += e.x; v1 += e.y;
                }
                if (relu) { v0 = fmaxf(v0, 0.f); v1 = fmaxf(v1, 0.f); }
                if (Cf) { float2 o = {v0, v1}; *(float2*)(Cf + base) = o; }
                if (Ch) {
                    __half hv0 = __float2half_rn(v0);
                    __half hv1 = __float2half_rn(v1);
                    ushort2 hv;
                    hv.x = __half_as_ushort(hv0);
                    hv.y = __half_as_ushort(hv1);
                    *(ushort2*)(Ch + base) = hv;
                    if (Cl && col < locols) {
                        ushort2 lv;
                        lv.x = h1(v0 - __half2float(hv0));
                        lv.y = h1(v1 - __half2float(hv1));
                        *(ushort2*)(Cl + (size_t)row * ldlo + col) = lv;
                    }
                }
            }
        }
    }
}

// ---------------- HMMA GEMM (hi-only): D = A * Wh^T ----------------
// 128x128, BK=64, warp tile 64x32, 3-stage, 1 sync/stage, 2 CTAs/SM (110.6 KB).
#define RS2 144
#define ARR2 (128 * RS2)                  // 18432
#define STAGE2 (2 * ARR2)                 // 36864 (A, Bh)
#define SMEM_GEMM2 (3 * STAGE2)           // 110592

__device__ __forceinline__ void gemm2_load_stage(
    const unsigned short* __restrict__ A, const unsigned short* __restrict__ Bh,
    int K, int m0, int n0, int k0, uint32_t smbase, int buf, int tid) {
    uint32_t sb = smbase + buf * STAGE2;
    #pragma unroll
    for (int it = 0; it < 8; it++) {
        int e = tid + it * 256;
        int arr = e >> 10;
        int idx = e & 1023;
        int row = idx >> 3;
        int ch = idx & 7;
        const unsigned short* src = arr == 0 ? A : Bh;
        int r0 = (arr == 0) ? m0 : n0;
        const unsigned short* g = src + (size_t)(r0 + row) * K + k0 + ch * 8;
        CP_ASYNC16(sb + arr * ARR2 + row * RS2 + ch * 16, g);
    }
}

__global__ __launch_bounds__(256)
void tgemm_hi_kernel(const unsigned short* __restrict__ A, const unsigned short* __restrict__ Bh,
                     int K,
                     float* __restrict__ Cf, unsigned short* __restrict__ Ch,
                     const float* __restrict__ bias, int relu, int ldc) {
    extern __shared__ char smem[];
    uint32_t smbase = cvta_s(smem);
    int tid = threadIdx.x;
    int m0 = blockIdx.x * 128, n0 = blockIdx.y * 128;
    int warp = tid >> 5, lane = tid & 31;
    int wm = (warp >> 2) * 64;
    int wn = (warp & 3) * 32;
    int arow = lane & 15;
    uint32_t asel = (uint32_t)(lane >> 4) << 4;
    int bnoff = ((lane >> 4) & 1) * 8 + (lane & 7);
    uint32_t bkoff = (uint32_t)((lane >> 3) & 1) << 4;

    float acc[4][4][4];
    #pragma unroll
    for (int i = 0; i < 4; i++)
        #pragma unroll
        for (int j = 0; j < 4; j++)
            #pragma unroll
            for (int q = 0; q < 4; q++) acc[i][j][q] = 0.f;

    int NS = K >> 6;
    gemm2_load_stage(A, Bh, K, m0, n0, 0, smbase, 0, tid);
    CP_COMMIT();
    gemm2_load_stage(A, Bh, K, m0, n0, 64, smbase, 1, tid);
    CP_COMMIT();

    int buf = 0;
    for (int s = 0; s < NS; s++) {
        if (s + 1 < NS) { CP_WAIT(1); } else { CP_WAIT(0); }
        __syncthreads();
        if (s + 2 < NS) {
            int pb = buf + 2; if (pb >= 3) pb -= 3;
            gemm2_load_stage(A, Bh, K, m0, n0, (s + 2) << 6, smbase, pb, tid);
            CP_COMMIT();
        }
        uint32_t sb = smbase + (uint32_t)buf * STAGE2;
        uint32_t sA = sb, sB = sb + ARR2;
        #pragma unroll
        for (int kk = 0; kk < 4; kk++) {
            uint32_t kb = kk * 32;
            uint32_t af[4][4];
            #pragma unroll
            for (int i = 0; i < 4; i++) {
                uint32_t ra = sA + (uint32_t)(wm + i * 16 + arow) * RS2 + kb + asel;
                ldm_x4(af[i], ra);
            }
            #pragma unroll
            for (int j2 = 0; j2 < 2; j2++) {
                uint32_t bh4[4];
                uint32_t rb = sB + (uint32_t)(wn + j2 * 16 + bnoff) * RS2 + kb + bkoff;
                ldm_x4(bh4, rb);
                #pragma unroll
                for (int i = 0; i < 4; i++) {
                    mma_f16(acc[i][2 * j2],     af[i], bh4);
                    mma_f16(acc[i][2 * j2 + 1], af[i], bh4 + 2);
                }
            }
        }
        if (++buf == 3) buf = 0;
    }

    int qr = lane >> 2;
    int qc = (lane & 3) * 2;
    #pragma unroll
    for (int i = 0; i < 4; i++) {
        #pragma unroll
        for (int j = 0; j < 4; j++) {
            int col = n0 + wn + j * 8 + qc;
            #pragma unroll
            for (int half = 0; half < 2; half++) {
                int row = m0 + wm + i * 16 + qr + half * 8;
                float v0 = acc[i][j][half * 2 + 0];
                float v1 = acc[i][j][half * 2 + 1];
                if (bias) {
                    float2 bv = *(const float2*)(bias + col);
                    v0 += bv.x; v1 += bv.y;
                }
                if (relu) { v0 = fmaxf(v0, 0.f); v1 = fmaxf(v1, 0.f); }
                size_t base = (size_t)row * ldc + col;
                if (Cf) { float2 o = {v0, v1}; *(float2*)(Cf + base) = o; }
                if (Ch) {
                    ushort2 hv;
                    hv.x = h1(v0);
                    hv.y = h1(v1);
                    *(ushort2*)(Ch + base) = hv;
                }
            }
        }
    }
}

// ---------------- fused flash attention (64-row tiles, 128 thr) ----------------
#define FRS 144
#define FARR (64 * FRS)
#define FKV_STAGE (2 * FARR)
#define SMEM_FLASH (2 * FARR + 2 * FKV_STAGE)

__device__ __forceinline__ void flash_load_q(
    const unsigned short* __restrict__ qh, const unsigned short* __restrict__ ql,
    int rowbase, int colbase, uint32_t smbase, int tid) {
    #pragma unroll
    for (int it = 0; it < 8; it++) {
        int e = tid + it * 128;
        int arr = e >> 9;
        int idx = e & 511;
        int row = idx >> 3, ch = idx & 7;
        const unsigned short* g;
        if (arr == 0)
            g = qh + (size_t)(rowbase + row) * (3 * CDIM) + colbase + ch * 8;
        else
            g = ql + (size_t)(rowbase + row) * CDIM + colbase + ch * 8;
        CP_ASYNC16(smbase + arr * FARR + row * FRS + ch * 16, g);
    }
}
__device__ __forceinline__ void flash_load_kv(
    const unsigned short* __restrict__ qh,
    int rowbase, int kcol, int vcol, uint32_t sb, int tid) {
    #pragma unroll
    for (int it = 0; it < 8; it++) {
        int e = tid + it * 128;
        int arr = e >> 9;
        int idx = e & 511;
        int row = idx >> 3, ch = idx & 7;
        int col = (arr == 0) ? kcol : vcol;
        const unsigned short* g = qh + (size_t)(rowbase + row) * (3 * CDIM) + col + ch * 8;
        CP_ASYNC16(sb + arr * FARR + row * FRS + ch * 16, g);
    }
}

__global__ __launch_bounds__(128)
void flash_kernel(const unsigned short* __restrict__ qh, const unsigned short* __restrict__ ql,
                  unsigned short* __restrict__ ob) {
    extern __shared__ char smem[];
    uint32_t smbase = cvta_s(smem);
    int tid = threadIdx.x;
    int tt = (int)gridDim.x - 1 - (int)blockIdx.x;
    int bh = blockIdx.y;
    int b = bh >> 4, h = bh & 15;
    int t0 = tt * 64;
    int qrowbase = b * TLEN + t0;
    int qcol = h * HDIM;
    int kcol = CDIM + h * HDIM;
    int vcol = 2 * CDIM + h * HDIM;

    int warp = tid >> 5, lane = tid & 31;
    int wm = warp * 16;
    int arow = lane & 15;
    uint32_t asel = (uint32_t)(lane >> 4) << 4;
    int bnoff = ((lane >> 4) & 1) * 8 + (lane & 7);
    uint32_t bkoff = (uint32_t)((lane >> 3) & 1) << 4;
    int vrowoff = (lane & 7) + ((lane >> 3) & 1) * 8;
    int vcp = (lane >> 4) & 1;
    int qr = lane >> 2;
    int qc = (lane & 3) * 2;

    float O[8][4];
    #pragma unroll
    for (int j = 0; j < 8; j++)
        #pragma unroll
        for (int q = 0; q < 4; q++) O[j][q] = 0.f;
    float m0r = -1e30f, m1r = -1e30f, l0 = 0.f, l1 = 0.f;

    int NS = tt + 1;
    uint32_t kvbase = smbase + 2 * FARR;

    flash_load_q(qh, ql, qrowbase, qcol, smbase, tid);
    flash_load_kv(qh, b * TLEN, kcol, vcol, kvbase, tid);
    CP_COMMIT();
    if (NS > 1) {
        flash_load_kv(qh, b * TLEN + 64, kcol, vcol, kvbase + FKV_STAGE, tid);
        CP_COMMIT();
    }

    for (int st = 0; st < NS; st++) {
        if (st + 1 < NS) { CP_WAIT(1); } else { CP_WAIT(0); }
        __syncthreads();
        uint32_t sKV = kvbase + (st & 1) * FKV_STAGE;
        uint32_t sK = sKV, sV = sKV + FARR;

        float S[8][4];
        #pragma unroll
        for (int j = 0; j < 8; j++)
            #pragma unroll
            for (int q = 0; q < 4; q++) S[j][q] = 0.f;
        #pragma unroll
        for (int d = 0; d < 4; d++) {
            uint32_t kb = d * 32;
            uint32_t ah[4], al[4];
            uint32_t ra = smbase + (uint32_t)(wm + arow) * FRS + kb + asel;
            ldm_x4(ah, ra);
            ldm_x4(al, ra + FARR);
            #pragma unroll
            for (int j2 = 0; j2 < 4; j2++) {
                uint32_t bf4[4];
                uint32_t rb = sK + (uint32_t)(j2 * 16 + bnoff) * FRS + kb + bkoff;
                ldm_x4(bf4, rb);
                mma_f16(S[2 * j2],     ah, bf4);
                mma_f16(S[2 * j2],     al, bf4);
                mma_f16(S[2 * j2 + 1], ah, bf4 + 2);
                mma_f16(S[2 * j2 + 1], al, bf4 + 2);
            }
        }
        if (st == tt) {
            int r0 = wm + qr, r1 = wm + qr + 8;
            #pragma unroll
            for (int j = 0; j < 8; j++) {
                int c0 = j * 8 + qc;
                S[j][0] = (c0     > r0) ? -1e30f : S[j][0] * 0.125f;
                S[j][1] = (c0 + 1 > r0) ? -1e30f : S[j][1] * 0.125f;
                S[j][2] = (c0     > r1) ? -1e30f : S[j][2] * 0.125f;
                S[j][3] = (c0 + 1 > r1) ? -1e30f : S[j][3] * 0.125f;
            }
        } else {
            #pragma unroll
            for (int j = 0; j < 8; j++)
                #pragma unroll
                for (int q = 0; q < 4; q++) S[j][q] *= 0.125f;
        }
        float mx0 = -1e30f, mx1 = -1e30f;
        #pragma unroll
        for (int j = 0; j < 8; j++) {
            mx0 = fmaxf(mx0, fmaxf(S[j][0], S[j][1]));
            mx1 = fmaxf(mx1, fmaxf(S[j][2], S[j][3]));
        }
        mx0 = fmaxf(mx0, __shfl_xor_sync(0xffffffffu, mx0, 1));
        mx0 = fmaxf(mx0, __shfl_xor_sync(0xffffffffu, mx0, 2));
        mx1 = fmaxf(mx1, __shfl_xor_sync(0xffffffffu, mx1, 1));
        mx1 = fmaxf(mx1, __shfl_xor_sync(0xffffffffu, mx1, 2));
        float mn0 = fmaxf(m0r, mx0), mn1 = fmaxf(m1r, mx1);
        float c0 = __expf(m0r - mn0), c1 = __expf(m1r - mn1);
        float rs0 = 0.f, rs1 = 0.f;
        #pragma unroll
        for (int j = 0; j < 8; j++) {
            S[j][0] = __expf(S[j][0] - mn0);
            S[j][1] = __expf(S[j][1] - mn0);
            S[j][2] = __expf(S[j][2] - mn1);
            S[j][3] = __expf(S[j][3] - mn1);
            rs0 += S[j][0] + S[j][1];
            rs1 += S[j][2] + S[j][3];
        }
        rs0 += __shfl_xor_sync(0xffffffffu, rs0, 1);
        rs0 += __shfl_xor_sync(0xffffffffu, rs0, 2);
        rs1 += __shfl_xor_sync(0xffffffffu, rs1, 1);
        rs1 += __shfl_xor_sync(0xffffffffu, rs1, 2);
        l0 = l0 * c0 + rs0;
        l1 = l1 * c1 + rs1;
        m0r = mn0; m1r = mn1;
        #pragma unroll
        for (int j = 0; j < 8; j++) {
            O[j][0] *= c0; O[j][1] *= c0;
            O[j][2] *= c1; O[j][3] *= c1;
        }
        #pragma unroll
        for (int kk = 0; kk < 4; kk++) {
            int j0 = 2 * kk, j1 = 2 * kk + 1;
            uint32_t pah[4], pal[4];
            pack2h(S[j0][0], S[j0][1], pah[0], pal[0]);
            pack2h(S[j0][2], S[j0][3], pah[1], pal[1]);
            pack2h(S[j1][0], S[j1][1], pah[2], pal[2]);
            pack2h(S[j1][2], S[j1][3], pah[3], pal[3]);
            uint32_t vrow = (uint32_t)(kk * 16 + vrowoff);
            #pragma unroll
            for (int jd2 = 0; jd2 < 4; jd2++) {
                uint32_t vf4[4];
                uint32_t rv = sV + vrow * FRS + (uint32_t)(jd2 * 2 + vcp) * 16;
                ldm_x4t(vf4, rv);
                mma_f16(O[2 * jd2],     pah, vf4);
                mma_f16(O[2 * jd2],     pal, vf4);
                mma_f16(O[2 * jd2 + 1], pah, vf4 + 2);
                mma_f16(O[2 * jd2 + 1], pal, vf4 + 2);
            }
        }
        __syncthreads();
        if (st + 2 < NS) {
            flash_load_kv(qh, b * TLEN + (st + 2) * 64, kcol, vcol,
                          kvbase + (st & 1) * FKV_STAGE, tid);
            CP_COMMIT();
        }
    }

    float inv0 = 1.f / l0, inv1 = 1.f / l1;
    int row0 = b * TLEN + t0 + wm + qr;
    #pragma unroll
    for (int jd = 0; jd < 8; jd++) {
        int col = qcol + jd * 8 + qc;
        ushort2 hv;
        hv.x = h1(O[jd][0] * inv0);
        hv.y = h1(O[jd][1] * inv0);
        *(ushort2*)(ob + (size_t)row0 * CDIM + col) = hv;
        hv.x = h1(O[jd][2] * inv1);
        hv.y = h1(O[jd][3] * inv1);
        *(ushort2*)(ob + (size_t)(row0 + 8) * CDIM + col) = hv;
    }
}

// ---------------- host ----------------
extern "C" void kernel_launch(void* const* d_in, const int* in_sizes, int n_in,
                              void* d_out, int out_size) {
    const int* idx = (const int*)d_in[0];
    const float* tok = (const float*)d_in[1];
    const float* pos = (const float*)d_in[2];
    const float* wq = (const float*)d_in[3];
    const float* wk = (const float*)d_in[4];
    const float* wv = (const float*)d_in[5];
    const float* wproj = (const float*)d_in[6];
    const float* bproj = (const float*)d_in[7];
    const float* ln1g = (const float*)d_in[8];
    const float* ln1b = (const float*)d_in[9];
    const float* ln2g = (const float*)d_in[10];
    const float* ln2b = (const float*)d_in[11];
    const float* w1 = (const float*)d_in[12];
    const float* b1 = (const float*)d_in[13];
    const float* w2 = (const float*)d_in[14];
    const float* b2 = (const float*)d_in[15];
    const float* lnfg = (const float*)d_in[16];
    const float* lnfb = (const float*)d_in[17];
    const float* wlm = (const float*)d_in[18];
    const float* blm = (const float*)d_in[19];
    float* out = (float*)d_out;

    float* px;
    unsigned short *pqkvb_h, *pqkvb_l, *phb, *pob, *pffb;
    unsigned short *pwqkv_h, *pwqkv_l, *pwproj_h, *pwproj_l;
    unsigned short *pw1_h, *pw2_h, *pw2_l, *pwlm_h;
    cudaGetSymbolAddress((void**)&px, g_x);
    cudaGetSymbolAddress((void**)&pqkvb_h, g_qkvb_h);
    cudaGetSymbolAddress((void**)&pqkvb_l, g_qkvb_l);
    cudaGetSymbolAddress((void**)&phb, g_hb);
    cudaGetSymbolAddress((void**)&pob, g_ob);
    cudaGetSymbolAddress((void**)&pffb, g_ffb);
    cudaGetSymbolAddress((void**)&pwqkv_h, g_wqkv_h);
    cudaGetSymbolAddress((void**)&pwqkv_l, g_wqkv_l);
    cudaGetSymbolAddress((void**)&pwproj_h, g_wproj_h);
    cudaGetSymbolAddress((void**)&pwproj_l, g_wproj_l);
    cudaGetSymbolAddress((void**)&pw1_h, g_w1_h);
    cudaGetSymbolAddress((void**)&pw2_h, g_w2_h);
    cudaGetSymbolAddress((void**)&pw2_l, g_w2_l);
    cudaGetSymbolAddress((void**)&pwlm_h, g_wlm_h);

    cudaFuncSetAttribute(tgemm_kernel, cudaFuncAttributeMaxDynamicSharedMemorySize, SMEM_GEMM);
    cudaFuncSetAttribute(tgemm_hi_kernel, cudaFuncAttributeMaxDynamicSharedMemorySize, SMEM_GEMM2);
    cudaFuncSetAttribute(flash_kernel, cudaFuncAttributeMaxDynamicSharedMemorySize, SMEM_FLASH);

    dim3 tb(32, 8);
    tsplit_qkv_kernel<<<dim3(96, 32, 8), tb>>>(wq, wk, wv, pwqkv_h, pwqkv_l);
    tsplit_mat_kernel<<<dim3(32, 32, 8), tb>>>(wproj, pwproj_h, pwproj_l, CDIM, CDIM);
    tsplit_mat_kernel<<<dim3(128, 32, 8), tb>>>(w1, pw1_h, nullptr, CDIM, FF);
    tsplit_mat_kernel<<<dim3(32, 128, 8), tb>>>(w2, pw2_h, pw2_l, FF, CDIM);
    tsplit_mat_kernel<<<dim3(1000, 32, 1), tb>>>(wlm, pwlm_h, nullptr, CDIM, VOCAB);

    embed_kernel<<<NTOK, 256>>>(idx, tok, pos, px);

    for (int l = 0; l < NLAYER; l++) {
        ln_kernel<<<NTOK / 8, 256>>>(px, ln1g + (size_t)l * CDIM, ln1b + (size_t)l * CDIM, phb);
        // Q part: hi/lo GEMM (N=1024), lo stored at ld=CDIM
        tgemm_kernel<<<dim3(32, 8), 256, SMEM_GEMM>>>(
            phb, pwqkv_h + (size_t)l * 3072 * 1024, pwqkv_l + (size_t)l * 3072 * 1024,
            CDIM, CDIM, nullptr, pqkvb_h, pqkvb_l, CDIM, CDIM, nullptr, nullptr, 0, 3 * CDIM);
        // K/V part: hi-only GEMM (N=2048), BK=64 single-sync
        tgemm_hi_kernel<<<dim3(32, 16), 256, SMEM_GEMM2>>>(
            phb, pwqkv_h + (size_t)l * 3072 * 1024 + (size_t)1024 * 1024, CDIM,
            nullptr, pqkvb_h + CDIM, nullptr, 0, 3 * CDIM);
        flash_kernel<<<dim3(16, BATCH * NHEAD), 128, SMEM_FLASH>>>(pqkvb_h, pqkvb_l, pob);
        tgemm_kernel<<<dim3(32, 8), 256, SMEM_GEMM>>>(
            pob, pwproj_h + (size_t)l * CDIM * CDIM, pwproj_l + (size_t)l * CDIM * CDIM,
            CDIM, CDIM, px, nullptr, nullptr, 0, 0, bproj + (size_t)l * CDIM, px, 0, CDIM);
        ln_kernel<<<NTOK / 8, 256>>>(px, ln2g + (size_t)l * CDIM, ln2b + (size_t)l * CDIM, phb);
        tgemm_hi_kernel<<<dim3(32, 32), 256, SMEM_GEMM2>>>(
            phb, pw1_h + (size_t)l * FF * CDIM, CDIM,
            nullptr, pffb, b1 + (size_t)l * FF, 1, FF);
        tgemm_kernel<<<dim3(32, 8), 256, SMEM_GEMM>>>(
            pffb, pw2_h + (size_t)l * CDIM * FF, pw2_l + (size_t)l * CDIM * FF,
            FF, CDIM, px, nullptr, nullptr, 0, 0, b2 + (size_t)l * CDIM, px, 0, CDIM);
    }
    ln_kernel<<<NTOK / 8, 256>>>(px, lnfg, lnfb, phb);
    tgemm_hi_kernel<<<dim3(32, 250), 256, SMEM_GEMM2>>>(
        phb, pwlm_h, CDIM, out, nullptr, blm, 0, VOCAB);
}

// round 17
// speedup vs baseline: 1.6866x; 1.1511x over previous
#include <cuda_runtime.h>
#include <cuda_fp16.h>
#include <cstdint>
#include <math.h>

#define BATCH 4
#define TLEN 1024
#define CDIM 1024
#define NHEAD 16
#define HDIM 64
#define NLAYER 8
#define VOCAB 32000
#define NTOK (BATCH * TLEN)
#define FF (4 * CDIM)

// ---------------- device scratch ----------------
__device__ float g_x[NTOK * CDIM];
__device__ unsigned short g_qkvb_h[NTOK * 3 * CDIM], g_qkvb_l[NTOK * CDIM];  // lo only for Q
__device__ unsigned short g_hb[NTOK * CDIM];
__device__ unsigned short g_ob[NTOK * CDIM];
__device__ unsigned short g_ffb[(size_t)NTOK * FF];
__device__ unsigned short g_wqkv_h[(size_t)NLAYER * 3 * CDIM * CDIM], g_wqkv_l[(size_t)NLAYER * 3 * CDIM * CDIM];
__device__ unsigned short g_wproj_h[(size_t)NLAYER * CDIM * CDIM], g_wproj_l[(size_t)NLAYER * CDIM * CDIM];
__device__ unsigned short g_w1_h[(size_t)NLAYER * FF * CDIM];
__device__ unsigned short g_w2_h[(size_t)NLAYER * CDIM * FF];
__device__ unsigned short g_wlm_h[(size_t)VOCAB * CDIM];

// ---------------- helpers ----------------
__device__ __forceinline__ uint32_t cvta_s(const void* p) {
    uint32_t a;
    asm("{ .reg .u64 t; cvta.to.shared.u64 t, %1; cvt.u32.u64 %0, t; }" : "=r"(a) : "l"(p));
    return a;
}
#define CP_ASYNC16(dst, src) \
    asm volatile("cp.async.cg.shared.global [%0], [%1], 16;" :: "r"(dst), "l"(src))
#define CP_COMMIT() asm volatile("cp.async.commit_group;" ::: "memory")
#define CP_WAIT(n)  asm volatile("cp.async.wait_group %0;" :: "n"(n) : "memory")

__device__ __forceinline__ void ldm_x4(uint32_t* r, uint32_t addr) {
    asm volatile("ldmatrix.sync.aligned.m8n8.x4.shared.b16 {%0,%1,%2,%3}, [%4];"
                 : "=r"(r[0]), "=r"(r[1]), "=r"(r[2]), "=r"(r[3]) : "r"(addr));
}
__device__ __forceinline__ void ldm_x4t(uint32_t* r, uint32_t addr) {
    asm volatile("ldmatrix.sync.aligned.m8n8.x4.trans.shared.b16 {%0,%1,%2,%3}, [%4];"
                 : "=r"(r[0]), "=r"(r[1]), "=r"(r[2]), "=r"(r[3]) : "r"(addr));
}
__device__ __forceinline__ void mma_f16(float* d, const uint32_t* a, const uint32_t* b) {
    asm volatile(
        "mma.sync.aligned.m16n8k16.row.col.f32.f16.f16.f32 "
        "{%0,%1,%2,%3}, {%4,%5,%6,%7}, {%8,%9}, {%0,%1,%2,%3};"
        : "+f"(d[0]), "+f"(d[1]), "+f"(d[2]), "+f"(d[3])
        : "r"(a[0]), "r"(a[1]), "r"(a[2]), "r"(a[3]), "r"(b[0]), "r"(b[1]));
}
__device__ __forceinline__ void hsplit(float v, unsigned short& h, unsigned short& l) {
    __half hb = __float2half_rn(v);
    __half lb = __float2half_rn(v - __half2float(hb));
    h = __half_as_ushort(hb);
    l = __half_as_ushort(lb);
}
__device__ __forceinline__ unsigned short h1(float v) {
    return __half_as_ushort(__float2half_rn(v));
}
__device__ __forceinline__ void pack2h(float a, float b, uint32_t& hi, uint32_t& lo) {
    unsigned short h0, l0, hh1, l1;
    hsplit(a, h0, l0);
    hsplit(b, hh1, l1);
    hi = (uint32_t)h0 | ((uint32_t)hh1 << 16);
    lo = (uint32_t)l0 | ((uint32_t)l1 << 16);
}

// ---------------- weight prep (transpose + fp16 hi/lo split) ----------------
__global__ void tsplit_qkv_kernel(const float* __restrict__ wq, const float* __restrict__ wk,
                                  const float* __restrict__ wv,
                                  unsigned short* __restrict__ dh, unsigned short* __restrict__ dl) {
    __shared__ float t[32][33];
    int n0 = blockIdx.x * 32, k0 = blockIdx.y * 32, l = blockIdx.z;
    int sel = n0 >> 10;
    const float* src = sel == 0 ? wq : (sel == 1 ? wk : wv);
    int within = n0 & 1023;
    int h = within >> 6, d0 = within & 63;
    const float* sp = src + ((size_t)(l * 16 + h) * 1024 + k0) * 64 + d0;
    int tx = threadIdx.x, ty = threadIdx.y;
    #pragma unroll
    for (int i = 0; i < 4; i++) t[ty + i * 8][tx] = sp[(size_t)(ty + i * 8) * 64 + tx];
    __syncthreads();
    size_t ob = (size_t)l * 3072 * 1024;
    #pragma unroll
    for (int i = 0; i < 4; i++) {
        int n = n0 + ty + i * 8, k = k0 + tx;
        unsigned short hh, ll;
        hsplit(t[tx][ty + i * 8], hh, ll);
        dh[ob + (size_t)n * 1024 + k] = hh;
        dl[ob + (size_t)n * 1024 + k] = ll;
    }
}
__global__ void tsplit_mat_kernel(const float* __restrict__ src,
                                  unsigned short* __restrict__ dh, unsigned short* __restrict__ dl,
                                  int K, int N) {
    __shared__ float t[32][33];
    int n0 = blockIdx.x * 32, k0 = blockIdx.y * 32;
    size_t l = blockIdx.z;
    const float* sp = src + l * (size_t)K * N;
    int tx = threadIdx.x, ty = threadIdx.y;
    #pragma unroll
    for (int i = 0; i < 4; i++) t[ty + i * 8][tx] = sp[(size_t)(k0 + ty + i * 8) * N + n0 + tx];
    __syncthreads();
    size_t ob = l * (size_t)K * N;
    #pragma unroll
    for (int i = 0; i < 4; i++) {
        int n = n0 + ty + i * 8, k = k0 + tx;
        unsigned short hh, ll;
        hsplit(t[tx][ty + i * 8], hh, ll);
        dh[ob + (size_t)n * K + k] = hh;
        if (dl) dl[ob + (size_t)n * K + k] = ll;
    }
}

// ---------------- embed ----------------
__global__ void embed_kernel(const int* __restrict__ idx, const float* __restrict__ tok,
                             const float* __restrict__ pos, float* __restrict__ x) {
    int row = blockIdx.x;
    int t = row & (TLEN - 1);
    int token = idx[row];
    const float4* te = (const float4*)(tok + (size_t)token * CDIM);
    const float4* pe = (const float4*)(pos + (size_t)t * CDIM);
    float4* xo = (float4*)(x + (size_t)row * CDIM);
    int i = threadIdx.x;
    float4 a = te[i], b = pe[i];
    a.x += b.x; a.y += b.y; a.z += b.z; a.w += b.w;
    xo[i] = a;
}

// ---------------- LayerNorm -> single fp16 (warp-per-row) ----------------
__global__ void ln_kernel(const float* __restrict__ x, const float* __restrict__ g,
                          const float* __restrict__ b, unsigned short* __restrict__ oh) {
    int warp = threadIdx.x >> 5, lane = threadIdx.x & 31;
    int row = blockIdx.x * 8 + warp;
    const float4* xr = (const float4*)(x + (size_t)row * CDIM);
    float4 v[8];
    float s = 0.f, ss = 0.f;
    #pragma unroll
    for (int i = 0; i < 8; i++) {
        v[i] = xr[lane + i * 32];
        s += v[i].x + v[i].y + v[i].z + v[i].w;
        ss += v[i].x * v[i].x + v[i].y * v[i].y + v[i].z * v[i].z + v[i].w * v[i].w;
    }
    #pragma unroll
    for (int o = 16; o > 0; o >>= 1) {
        s += __shfl_xor_sync(0xffffffffu, s, o);
        ss += __shfl_xor_sync(0xffffffffu, ss, o);
    }
    float mean = s * (1.0f / CDIM);
    float var = ss * (1.0f / CDIM) - mean * mean;
    float rstd = rsqrtf(var + 1e-5f);
    const float4* gp = (const float4*)g;
    const float4* bp = (const float4*)b;
    ushort4* op = (ushort4*)(oh + (size_t)row * CDIM);
    #pragma unroll
    for (int i = 0; i < 8; i++) {
        float4 gv = gp[lane + i * 32];
        float4 bv = bp[lane + i * 32];
        ushort4 hv;
        hv.x = h1((v[i].x - mean) * rstd * gv.x + bv.x);
        hv.y = h1((v[i].y - mean) * rstd * gv.y + bv.y);
        hv.z = h1((v[i].z - mean) * rstd * gv.z + bv.z);
        hv.w = h1((v[i].w - mean) * rstd * gv.w + bv.w);
        op[lane + i * 32] = hv;
    }
}

// ---------------- HMMA GEMM (hi/lo): D = A * (Wh[+Wl])^T ----------------
// 128x128, BK=32, warp tile 64x32, 3-stage, 1 sync/stage, 2 CTAs/SM.
#define RS 80
#define ARR_BYTES (128 * RS)
#define STAGE_BYTES (3 * ARR_BYTES)       // 30720 (A, Bh, Bl)
#define SMEM_GEMM (3 * STAGE_BYTES)       // 92160

__device__ __forceinline__ void gemm_load_stage(
    const unsigned short* __restrict__ A,
    const unsigned short* __restrict__ Bh, const unsigned short* __restrict__ Bl,
    int K, int m0, int n0, int k0, uint32_t smbase, int buf, int tid) {
    uint32_t sb = smbase + buf * STAGE_BYTES;
    #pragma unroll
    for (int it = 0; it < 6; it++) {
        int e = tid + it * 256;
        int arr = e >> 9;
        int idx = e & 511;
        int row = idx >> 2;
        int ch = idx & 3;
        const unsigned short* src = arr == 0 ? A : arr == 1 ? Bh : Bl;
        int r0 = (arr == 0) ? m0 : n0;
        const unsigned short* g = src + (size_t)(r0 + row) * K + k0 + ch * 8;
        CP_ASYNC16(sb + arr * ARR_BYTES + row * RS + ch * 16, g);
    }
}

__global__ __launch_bounds__(256)
void tgemm_kernel(const unsigned short* __restrict__ A,
                  const unsigned short* __restrict__ Bh, const unsigned short* __restrict__ Bl,
                  int K,
                  float* __restrict__ Cf, unsigned short* __restrict__ Ch,
                  unsigned short* __restrict__ Cl, int locols, int ldlo,
                  const float* __restrict__ bias, const float* __restrict__ res,
                  int relu, int ldc) {
    extern __shared__ char smem[];
    uint32_t smbase = cvta_s(smem);
    int tid = threadIdx.x;
    int m0 = blockIdx.x * 128, n0 = blockIdx.y * 128;
    int warp = tid >> 5, lane = tid & 31;
    int wm = (warp >> 2) * 64;
    int wn = (warp & 3) * 32;
    int arow = lane & 15;
    uint32_t asel = (uint32_t)(lane >> 4) << 4;
    int bnoff = ((lane >> 4) & 1) * 8 + (lane & 7);
    uint32_t bkoff = (uint32_t)((lane >> 3) & 1) << 4;

    float acc[4][4][4];
    #pragma unroll
    for (int i = 0; i < 4; i++)
        #pragma unroll
        for (int j = 0; j < 4; j++)
            #pragma unroll
            for (int q = 0; q < 4; q++) acc[i][j][q] = 0.f;

    int NS = K >> 5;
    gemm_load_stage(A, Bh, Bl, K, m0, n0, 0, smbase, 0, tid);
    CP_COMMIT();
    gemm_load_stage(A, Bh, Bl, K, m0, n0, 32, smbase, 1, tid);
    CP_COMMIT();

    int buf = 0;
    for (int s = 0; s < NS; s++) {
        if (s + 1 < NS) { CP_WAIT(1); } else { CP_WAIT(0); }
        __syncthreads();
        if (s + 2 < NS) {
            int pb = buf + 2; if (pb >= 3) pb -= 3;
            gemm_load_stage(A, Bh, Bl, K, m0, n0, (s + 2) << 5, smbase, pb, tid);
            CP_COMMIT();
        }
        uint32_t sb = smbase + (uint32_t)buf * STAGE_BYTES;
        uint32_t sA = sb, sBh = sb + ARR_BYTES;
        #pragma unroll
        for (int kk = 0; kk < 2; kk++) {
            uint32_t kb = kk * 32;
            uint32_t af[4][4];
            #pragma unroll
            for (int i = 0; i < 4; i++) {
                uint32_t ra = sA + (uint32_t)(wm + i * 16 + arow) * RS + kb + asel;
                ldm_x4(af[i], ra);
            }
            #pragma unroll
            for (int j2 = 0; j2 < 2; j2++) {
                uint32_t bh4[4], bl4[4];
                uint32_t rb = sBh + (uint32_t)(wn + j2 * 16 + bnoff) * RS + kb + bkoff;
                ldm_x4(bh4, rb);
                ldm_x4(bl4, rb + ARR_BYTES);
                #pragma unroll
                for (int i = 0; i < 4; i++) {
                    mma_f16(acc[i][2 * j2],     af[i], bh4);
                    mma_f16(acc[i][2 * j2 + 1], af[i], bh4 + 2);
                    mma_f16(acc[i][2 * j2],     af[i], bl4);
                    mma_f16(acc[i][2 * j2 + 1], af[i], bl4 + 2);
                }
            }
        }
        if (++buf == 3) buf = 0;
    }

    int qr = lane >> 2;
    int qc = (lane & 3) * 2;
    #pragma unroll
    for (int i = 0; i < 4; i++) {
        #pragma unroll
        for (int j = 0; j < 4; j++) {
            int col = n0 + wn + j * 8 + qc;
            #pragma unroll
            for (int half = 0; half < 2; half++) {
                int row = m0 + wm + i * 16 + qr + half * 8;
                float v0 = acc[i][j][half * 2 + 0];
                float v1 = acc[i][j][half * 2 + 1];
                if (bias) {
                    float2 bv = *(const float2*)(bias + col);
                    v0 += bv.x; v1 += bv.y;
                }
                size_t base = (size_t)row * ldc + col;
                if (res) {
                    float2 e = *(const float2*)(res + base);
                    v0 += e.x; v1 += e.y;
                }
                if (relu) { v0 = fmaxf(v0, 0.f); v1 = fmaxf(v1, 0.f); }
                if (Cf) { float2 o = {v0, v1}; *(float2*)(Cf + base) = o; }
                if (Ch) {
                    __half hv0 = __float2half_rn(v0);
                    __half hv1 = __float2half_rn(v1);
                    ushort2 hv;
                    hv.x = __half_as_ushort(hv0);
                    hv.y = __half_as_ushort(hv1);
                    *(ushort2*)(Ch + base) = hv;
                    if (Cl && col < locols) {
                        ushort2 lv;
                        lv.x = h1(v0 - __half2float(hv0));
                        lv.y = h1(v1 - __half2float(hv1));
                        *(ushort2*)(Cl + (size_t)row * ldlo + col) = lv;
                    }
                }
            }
        }
    }
}

// ---------------- HMMA GEMM (hi-only): D = A * Wh^T (+bias)(+res)(relu) ------
// 128x128, BK=64, warp tile 64x32, 3-stage, 1 sync/stage, 2 CTAs/SM (110.6 KB).
#define RS2 144
#define ARR2 (128 * RS2)                  // 18432
#define STAGE2 (2 * ARR2)                 // 36864 (A, Bh)
#define SMEM_GEMM2 (3 * STAGE2)           // 110592

__device__ __forceinline__ void gemm2_load_stage(
    const unsigned short* __restrict__ A, const unsigned short* __restrict__ Bh,
    int K, int m0, int n0, int k0, uint32_t smbase, int buf, int tid) {
    uint32_t sb = smbase + buf * STAGE2;
    #pragma unroll
    for (int it = 0; it < 8; it++) {
        int e = tid + it * 256;
        int arr = e >> 10;
        int idx = e & 1023;
        int row = idx >> 3;
        int ch = idx & 7;
        const unsigned short* src = arr == 0 ? A : Bh;
        int r0 = (arr == 0) ? m0 : n0;
        const unsigned short* g = src + (size_t)(r0 + row) * K + k0 + ch * 8;
        CP_ASYNC16(sb + arr * ARR2 + row * RS2 + ch * 16, g);
    }
}

__global__ __launch_bounds__(256)
void tgemm_hi_kernel(const unsigned short* __restrict__ A, const unsigned short* __restrict__ Bh,
                     int K,
                     float* __restrict__ Cf, unsigned short* __restrict__ Ch,
                     const float* __restrict__ bias, const float* __restrict__ res,
                     int relu, int ldc) {
    extern __shared__ char smem[];
    uint32_t smbase = cvta_s(smem);
    int tid = threadIdx.x;
    int m0 = blockIdx.x * 128, n0 = blockIdx.y * 128;
    int warp = tid >> 5, lane = tid & 31;
    int wm = (warp >> 2) * 64;
    int wn = (warp & 3) * 32;
    int arow = lane & 15;
    uint32_t asel = (uint32_t)(lane >> 4) << 4;
    int bnoff = ((lane >> 4) & 1) * 8 + (lane & 7);
    uint32_t bkoff = (uint32_t)((lane >> 3) & 1) << 4;

    float acc[4][4][4];
    #pragma unroll
    for (int i = 0; i < 4; i++)
        #pragma unroll
        for (int j = 0; j < 4; j++)
            #pragma unroll
            for (int q = 0; q < 4; q++) acc[i][j][q] = 0.f;

    int NS = K >> 6;
    gemm2_load_stage(A, Bh, K, m0, n0, 0, smbase, 0, tid);
    CP_COMMIT();
    gemm2_load_stage(A, Bh, K, m0, n0, 64, smbase, 1, tid);
    CP_COMMIT();

    int buf = 0;
    for (int s = 0; s < NS; s++) {
        if (s + 1 < NS) { CP_WAIT(1); } else { CP_WAIT(0); }
        __syncthreads();
        if (s + 2 < NS) {
            int pb = buf + 2; if (pb >= 3) pb -= 3;
            gemm2_load_stage(A, Bh, K, m0, n0, (s + 2) << 6, smbase, pb, tid);
            CP_COMMIT();
        }
        uint32_t sb = smbase + (uint32_t)buf * STAGE2;
        uint32_t sA = sb, sB = sb + ARR2;
        #pragma unroll
        for (int kk = 0; kk < 4; kk++) {
            uint32_t kb = kk * 32;
            uint32_t af[4][4];
            #pragma unroll
            for (int i = 0; i < 4; i++) {
                uint32_t ra = sA + (uint32_t)(wm + i * 16 + arow) * RS2 + kb + asel;
                ldm_x4(af[i], ra);
            }
            #pragma unroll
            for (int j2 = 0; j2 < 2; j2++) {
                uint32_t bh4[4];
                uint32_t rb = sB + (uint32_t)(wn + j2 * 16 + bnoff) * RS2 + kb + bkoff;
                ldm_x4(bh4, rb);
                #pragma unroll
                for (int i = 0; i < 4; i++) {
                    mma_f16(acc[i][2 * j2],     af[i], bh4);
                    mma_f16(acc[i][2 * j2 + 1], af[i], bh4 + 2);
                }
            }
        }
        if (++buf == 3) buf = 0;
    }

    int qr = lane >> 2;
    int qc = (lane & 3) * 2;
    #pragma unroll
    for (int i = 0; i < 4; i++) {
        #pragma unroll
        for (int j = 0; j < 4; j++) {
            int col = n0 + wn + j * 8 + qc;
            #pragma unroll
            for (int half = 0; half < 2; half++) {
                int row = m0 + wm + i * 16 + qr + half * 8;
                float v0 = acc[i][j][half * 2 + 0];
                float v1 = acc[i][j][half * 2 + 1];
                if (bias) {
                    float2 bv = *(const float2*)(bias + col);
                    v0 += bv.x; v1 += bv.y;
                }
                size_t base = (size_t)row * ldc + col;
                if (res) {
                    float2 e = *(const float2*)(res + base);
                    v0 += e.x; v1 += e.y;
                }
                if (relu) { v0 = fmaxf(v0, 0.f); v1 = fmaxf(v1, 0.f); }
                if (Cf) { float2 o = {v0, v1}; *(float2*)(Cf + base) = o; }
                if (Ch) {
                    ushort2 hv;
                    hv.x = h1(v0);
                    hv.y = h1(v1);
                    *(ushort2*)(Ch + base) = hv;
                }
            }
        }
    }
}

// ---------------- fused flash attention (64-row tiles, 128 thr) ----------------
// 3-buffer KV ring with post-sync prefetch (GEMM pattern).
#define FRS 144
#define FARR (64 * FRS)
#define FKV_STAGE (2 * FARR)
#define SMEM_FLASH (2 * FARR + 3 * FKV_STAGE)   // 73728

__device__ __forceinline__ void flash_load_q(
    const unsigned short* __restrict__ qh, const unsigned short* __restrict__ ql,
    int rowbase, int colbase, uint32_t smbase, int tid) {
    #pragma unroll
    for (int it = 0; it < 8; it++) {
        int e = tid + it * 128;
        int arr = e >> 9;
        int idx = e & 511;
        int row = idx >> 3, ch = idx & 7;
        const unsigned short* g;
        if (arr == 0)
            g = qh + (size_t)(rowbase + row) * (3 * CDIM) + colbase + ch * 8;
        else
            g = ql + (size_t)(rowbase + row) * CDIM + colbase + ch * 8;
        CP_ASYNC16(smbase + arr * FARR + row * FRS + ch * 16, g);
    }
}
__device__ __forceinline__ void flash_load_kv(
    const unsigned short* __restrict__ qh,
    int rowbase, int kcol, int vcol, uint32_t sb, int tid) {
    #pragma unroll
    for (int it = 0; it < 8; it++) {
        int e = tid + it * 128;
        int arr = e >> 9;
        int idx = e & 511;
        int row = idx >> 3, ch = idx & 7;
        int col = (arr == 0) ? kcol : vcol;
        const unsigned short* g = qh + (size_t)(rowbase + row) * (3 * CDIM) + col + ch * 8;
        CP_ASYNC16(sb + arr * FARR + row * FRS + ch * 16, g);
    }
}

__global__ __launch_bounds__(128)
void flash_kernel(const unsigned short* __restrict__ qh, const unsigned short* __restrict__ ql,
                  unsigned short* __restrict__ ob) {
    extern __shared__ char smem[];
    uint32_t smbase = cvta_s(smem);
    int tid = threadIdx.x;
    int tt = (int)gridDim.x - 1 - (int)blockIdx.x;
    int bh = blockIdx.y;
    int b = bh >> 4, h = bh & 15;
    int t0 = tt * 64;
    int qrowbase = b * TLEN + t0;
    int qcol = h * HDIM;
    int kcol = CDIM + h * HDIM;
    int vcol = 2 * CDIM + h * HDIM;

    int warp = tid >> 5, lane = tid & 31;
    int wm = warp * 16;
    int arow = lane & 15;
    uint32_t asel = (uint32_t)(lane >> 4) << 4;
    int bnoff = ((lane >> 4) & 1) * 8 + (lane & 7);
    uint32_t bkoff = (uint32_t)((lane >> 3) & 1) << 4;
    int vrowoff = (lane & 7) + ((lane >> 3) & 1) * 8;
    int vcp = (lane >> 4) & 1;
    int qr = lane >> 2;
    int qc = (lane & 3) * 2;

    float O[8][4];
    #pragma unroll
    for (int j = 0; j < 8; j++)
        #pragma unroll
        for (int q = 0; q < 4; q++) O[j][q] = 0.f;
    float m0r = -1e30f, m1r = -1e30f, l0 = 0.f, l1 = 0.f;

    int NS = tt + 1;
    uint32_t kvbase = smbase + 2 * FARR;

    flash_load_q(qh, ql, qrowbase, qcol, smbase, tid);
    flash_load_kv(qh, b * TLEN, kcol, vcol, kvbase, tid);
    CP_COMMIT();
    if (NS > 1) {
        flash_load_kv(qh, b * TLEN + 64, kcol, vcol, kvbase + FKV_STAGE, tid);
        CP_COMMIT();
    }

    int buf = 0;
    for (int st = 0; st < NS; st++) {
        if (st + 1 < NS) { CP_WAIT(1); } else { CP_WAIT(0); }
        __syncthreads();
        if (st + 2 < NS) {
            int pb = buf + 2; if (pb >= 3) pb -= 3;
            flash_load_kv(qh, b * TLEN + (st + 2) * 64, kcol, vcol,
                          kvbase + (uint32_t)pb * FKV_STAGE, tid);
            CP_COMMIT();
        }
        uint32_t sKV = kvbase + (uint32_t)buf * FKV_STAGE;
        uint32_t sK = sKV, sV = sKV + FARR;

        float S[8][4];
        #pragma unroll
        for (int j = 0; j < 8; j++)
            #pragma unroll
            for (int q = 0; q < 4; q++) S[j][q] = 0.f;
        #pragma unroll
        for (int d = 0; d < 4; d++) {
            uint32_t kb = d * 32;
            uint32_t ah[4], al[4];
            uint32_t ra = smbase + (uint32_t)(wm + arow) * FRS + kb + asel;
            ldm_x4(ah, ra);
            ldm_x4(al, ra + FARR);
            #pragma unroll
            for (int j2 = 0; j2 < 4; j2++) {
                uint32_t bf4[4];
                uint32_t rb = sK + (uint32_t)(j2 * 16 + bnoff) * FRS + kb + bkoff;
                ldm_x4(bf4, rb);
                mma_f16(S[2 * j2],     ah, bf4);
                mma_f16(S[2 * j2],     al, bf4);
                mma_f16(S[2 * j2 + 1], ah, bf4 + 2);
                mma_f16(S[2 * j2 + 1], al, bf4 + 2);
            }
        }
        if (st == tt) {
            int r0 = wm + qr, r1 = wm + qr + 8;
            #pragma unroll
            for (int j = 0; j < 8; j++) {
                int c0 = j * 8 + qc;
                S[j][0] = (c0     > r0) ? -1e30f : S[j][0] * 0.125f;
                S[j][1] = (c0 + 1 > r0) ? -1e30f : S[j][1] * 0.125f;
                S[j][2] = (c0     > r1) ? -1e30f : S[j][2] * 0.125f;
                S[j][3] = (c0 + 1 > r1) ? -1e30f : S[j][3] * 0.125f;
            }
        } else {
            #pragma unroll
            for (int j = 0; j < 8; j++)
                #pragma unroll
                for (int q = 0; q < 4; q++) S[j][q] *= 0.125f;
        }
        float mx0 = -1e30f, mx1 = -1e30f;
        #pragma unroll
        for (int j = 0; j < 8; j++) {
            mx0 = fmaxf(mx0, fmaxf(S[j][0], S[j][1]));
            mx1 = fmaxf(mx1, fmaxf(S[j][2], S[j][3]));
        }
        mx0 = fmaxf(mx0, __shfl_xor_sync(0xffffffffu, mx0, 1));
        mx0 = fmaxf(mx0, __shfl_xor_sync(0xffffffffu, mx0, 2));
        mx1 = fmaxf(mx1, __shfl_xor_sync(0xffffffffu, mx1, 1));
        mx1 = fmaxf(mx1, __shfl_xor_sync(0xffffffffu, mx1, 2));
        float mn0 = fmaxf(m0r, mx0), mn1 = fmaxf(m1r, mx1);
        float c0 = __expf(m0r - mn0), c1 = __expf(m1r - mn1);
        float rs0 = 0.f, rs1 = 0.f;
        #pragma unroll
        for (int j = 0; j < 8; j++) {
            S[j][0] = __expf(S[j][0] - mn0);
            S[j][1] = __expf(S[j][1] - mn0);
            S[j][2] = __expf(S[j][2] - mn1);
            S[j][3] = __expf(S[j][3] - mn1);
            rs0 += S[j][0] + S[j][1];
            rs1 += S[j][2] + S[j][3];
        }
        rs0 += __shfl_xor_sync(0xffffffffu, rs0, 1);
        rs0 += __shfl_xor_sync(0xffffffffu, rs0, 2);
        rs1 += __shfl_xor_sync(0xffffffffu, rs1, 1);
        rs1 += __shfl_xor_sync(0xffffffffu, rs1, 2);
        l0 = l0 * c0 + rs0;
        l1 = l1 * c1 + rs1;
        m0r = mn0; m1r = mn1;
        #pragma unroll
        for (int j = 0; j < 8; j++) {
            O[j][0] *= c0; O[j][1] *= c0;
            O[j][2] *= c1; O[j][3] *= c1;
        }
        #pragma unroll
        for (int kk = 0; kk < 4; kk++) {
            int j0 = 2 * kk, j1 = 2 * kk + 1;
            uint32_t pah[4], pal[4];
            pack2h(S[j0][0], S[j0][1], pah[0], pal[0]);
            pack2h(S[j0][2], S[j0][3], pah[1], pal[1]);
            pack2h(S[j1][0], S[j1][1], pah[2], pal[2]);
            pack2h(S[j1][2], S[j1][3], pah[3], pal[3]);
            uint32_t vrow = (uint32_t)(kk * 16 + vrowoff);
            #pragma unroll
            for (int jd2 = 0; jd2 < 4; jd2++) {
                uint32_t vf4[4];
                uint32_t rv = sV + vrow * FRS + (uint32_t)(jd2 * 2 + vcp) * 16;
                ldm_x4t(vf4, rv);
                mma_f16(O[2 * jd2],     pah, vf4);
                mma_f16(O[2 * jd2],     pal, vf4);
                mma_f16(O[2 * jd2 + 1], pah, vf4 + 2);
                mma_f16(O[2 * jd2 + 1], pal, vf4 + 2);
            }
        }
        if (++buf == 3) buf = 0;
    }

    float inv0 = 1.f / l0, inv1 = 1.f / l1;
    int row0 = b * TLEN + t0 + wm + qr;
    #pragma unroll
    for (int jd = 0; jd < 8; jd++) {
        int col = qcol + jd * 8 + qc;
        ushort2 hv;
        hv.x = h1(O[jd][0] * inv0);
        hv.y = h1(O[jd][1] * inv0);
        *(ushort2*)(ob + (size_t)row0 * CDIM + col) = hv;
        hv.x = h1(O[jd][2] * inv1);
        hv.y = h1(O[jd][3] * inv1);
        *(ushort2*)(ob + (size_t)(row0 + 8) * CDIM + col) = hv;
    }
}

// ---------------- host ----------------
extern "C" void kernel_launch(void* const* d_in, const int* in_sizes, int n_in,
                              void* d_out, int out_size) {
    const int* idx = (const int*)d_in[0];
    const float* tok = (const float*)d_in[1];
    const float* pos = (const float*)d_in[2];
    const float* wq = (const float*)d_in[3];
    const float* wk = (const float*)d_in[4];
    const float* wv = (const float*)d_in[5];
    const float* wproj = (const float*)d_in[6];
    const float* bproj = (const float*)d_in[7];
    const float* ln1g = (const float*)d_in[8];
    const float* ln1b = (const float*)d_in[9];
    const float* ln2g = (const float*)d_in[10];
    const float* ln2b = (const float*)d_in[11];
    const float* w1 = (const float*)d_in[12];
    const float* b1 = (const float*)d_in[13];
    const float* w2 = (const float*)d_in[14];
    const float* b2 = (const float*)d_in[15];
    const float* lnfg = (const float*)d_in[16];
    const float* lnfb = (const float*)d_in[17];
    const float* wlm = (const float*)d_in[18];
    const float* blm = (const float*)d_in[19];
    float* out = (float*)d_out;

    float* px;
    unsigned short *pqkvb_h, *pqkvb_l, *phb, *pob, *pffb;
    unsigned short *pwqkv_h, *pwqkv_l, *pwproj_h, *pwproj_l;
    unsigned short *pw1_h, *pw2_h, *pwlm_h;
    cudaGetSymbolAddress((void**)&px, g_x);
    cudaGetSymbolAddress((void**)&pqkvb_h, g_qkvb_h);
    cudaGetSymbolAddress((void**)&pqkvb_l, g_qkvb_l);
    cudaGetSymbolAddress((void**)&phb, g_hb);
    cudaGetSymbolAddress((void**)&pob, g_ob);
    cudaGetSymbolAddress((void**)&pffb, g_ffb);
    cudaGetSymbolAddress((void**)&pwqkv_h, g_wqkv_h);
    cudaGetSymbolAddress((void**)&pwqkv_l, g_wqkv_l);
    cudaGetSymbolAddress((void**)&pwproj_h, g_wproj_h);
    cudaGetSymbolAddress((void**)&pwproj_l, g_wproj_l);
    cudaGetSymbolAddress((void**)&pw1_h, g_w1_h);
    cudaGetSymbolAddress((void**)&pw2_h, g_w2_h);
    cudaGetSymbolAddress((void**)&pwlm_h, g_wlm_h);

    cudaFuncSetAttribute(tgemm_kernel, cudaFuncAttributeMaxDynamicSharedMemorySize, SMEM_GEMM);
    cudaFuncSetAttribute(tgemm_hi_kernel, cudaFuncAttributeMaxDynamicSharedMemorySize, SMEM_GEMM2);
    cudaFuncSetAttribute(flash_kernel, cudaFuncAttributeMaxDynamicSharedMemorySize, SMEM_FLASH);

    dim3 tb(32, 8);
    tsplit_qkv_kernel<<<dim3(96, 32, 8), tb>>>(wq, wk, wv, pwqkv_h, pwqkv_l);
    tsplit_mat_kernel<<<dim3(32, 32, 8), tb>>>(wproj, pwproj_h, pwproj_l, CDIM, CDIM);
    tsplit_mat_kernel<<<dim3(128, 32, 8), tb>>>(w1, pw1_h, nullptr, CDIM, FF);
    tsplit_mat_kernel<<<dim3(32, 128, 8), tb>>>(w2, pw2_h, nullptr, FF, CDIM);
    tsplit_mat_kernel<<<dim3(1000, 32, 1), tb>>>(wlm, pwlm_h, nullptr, CDIM, VOCAB);

    embed_kernel<<<NTOK, 256>>>(idx, tok, pos, px);

    for (int l = 0; l < NLAYER; l++) {
        ln_kernel<<<NTOK / 8, 256>>>(px, ln1g + (size_t)l * CDIM, ln1b + (size_t)l * CDIM, phb);
        // Q part: hi/lo GEMM (N=1024), lo stored at ld=CDIM
        tgemm_kernel<<<dim3(32, 8), 256, SMEM_GEMM>>>(
            phb, pwqkv_h + (size_t)l * 3072 * 1024, pwqkv_l + (size_t)l * 3072 * 1024,
            CDIM, nullptr, pqkvb_h, pqkvb_l, CDIM, CDIM, nullptr, nullptr, 0, 3 * CDIM);
        // K/V part: hi-only GEMM (N=2048), BK=64 single-sync
        tgemm_hi_kernel<<<dim3(32, 16), 256, SMEM_GEMM2>>>(
            phb, pwqkv_h + (size_t)l * 3072 * 1024 + (size_t)1024 * 1024, CDIM,
            nullptr, pqkvb_h + CDIM, nullptr, nullptr, 0, 3 * CDIM);
        flash_kernel<<<dim3(16, BATCH * NHEAD), 128, SMEM_FLASH>>>(pqkvb_h, pqkvb_l, pob);
        tgemm_kernel<<<dim3(32, 8), 256, SMEM_GEMM>>>(
            pob, pwproj_h + (size_t)l * CDIM * CDIM, pwproj_l + (size_t)l * CDIM * CDIM,
            CDIM, px, nullptr, nullptr, 0, 0, bproj + (size_t)l * CDIM, px, 0, CDIM);
        ln_kernel<<<NTOK / 8, 256>>>(px, ln2g + (size_t)l * CDIM, ln2b + (size_t)l * CDIM, phb);
        tgemm_hi_kernel<<<dim3(32, 32), 256, SMEM_GEMM2>>>(
            phb, pw1_h + (size_t)l * FF * CDIM, CDIM,
            nullptr, pffb, b1 + (size_t)l * FF, nullptr, 1, FF);
        // MLP down: hi-only GEMM (K=4096 -> 32 stages instead of 128) + residual
        tgemm_hi_kernel<<<dim3(32, 8), 256, SMEM_GEMM2>>>(
            pffb, pw2_h + (size_t)l * CDIM * FF, FF,
            px, nullptr, b2 + (size_t)l * CDIM, px, 0, CDIM);
    }
    ln_kernel<<<NTOK / 8, 256>>>(px, lnfg, lnfb, phb);
    tgemm_hi_kernel<<<dim3(32, 250), 256, SMEM_GEMM2>>>(
        phb, pwlm_h, CDIM, out, nullptr, blm, nullptr, 0, VOCAB);
}